// round 11
// baseline (speedup 1.0000x reference)
#include <cuda_runtime.h>
#include <cuda_bf16.h>
#include <cuda_fp16.h>
#include <math.h>
#include <stdint.h>

#define Nn    20000
#define Ee    120000
#define INF_  3000
#define HIDF  512
#define OUTF  30
#define NH    3
#define NDOMc 4
#define MHc   64
#define NLABc 20
#define EPSBN 1e-5f
#define KPAD  3008                 // 3000 padded to multiple of 32

// ---------------- scratch (static device memory; no allocations) ----------------
__device__ float    g_x[(size_t)Nn * INF_];
__device__ float    g_H[(size_t)Nn * NH * HIDF];
__device__ float    g_acc1[(size_t)Nn * NH * HIDF];
__device__ float    g_h1[(size_t)Nn * HIDF];
__device__ float    g_H2[(size_t)Nn * NH * OUTF];
__device__ float    g_acc2[(size_t)Nn * NH * OUTF];
__device__ float    g_als1[Nn * NH], g_ald1[Nn * NH];
__device__ float    g_als2[Nn * NH], g_ald2[Nn * NH];
__device__ float    g_e1[(size_t)Ee * NH];
__device__ float    g_e2[(size_t)Ee * NH];
__device__ unsigned g_mkey1[Nn * NH], g_mkey2[Nn * NH];
__device__ float    g_den1[Nn * NH], g_den2[Nn * NH];
__device__ float    g_bnsum[INF_], g_bnsum2[INF_];
__device__ float    g_dsum[NDOMc * INF_], g_dsum2[NDOMc * INF_];
__device__ float    g_cnt[NDOMc];
__device__ __align__(256) __half g_Ahi[(size_t)Nn * KPAD];
__device__ __align__(256) __half g_Alo[(size_t)Nn * KPAD];
__device__ __align__(256) __half g_Wq[(size_t)INF_ * KPAD];   // transposed weights [N, KPAD]

// ---------------- helpers ----------------
__device__ __forceinline__ unsigned f2o(float f) {
    unsigned u = __float_as_uint(f);
    return (u & 0x80000000u) ? ~u : (u | 0x80000000u);
}
__device__ __forceinline__ float o2f(unsigned k) {
    return (k & 0x80000000u) ? __uint_as_float(k ^ 0x80000000u) : __uint_as_float(~k);
}
__device__ __forceinline__ float eluf(float v) { return v > 0.f ? v : (expf(v) - 1.f); }

__device__ __forceinline__ uint32_t smem_u32(const void* p) {
    uint32_t a;
    asm("{ .reg .u64 t; cvta.to.shared.u64 t, %1; cvt.u32.u64 %0, t; }" : "=r"(a) : "l"(p));
    return a;
}

__device__ __forceinline__ void cp16(uint32_t dst, const void* src, int ok) {
    asm volatile("cp.async.cg.shared.global [%0], [%1], 16, %2;"
                 :: "r"(dst), "l"(src), "r"(ok ? 16 : 0) : "memory");
}
#define CP_COMMIT() asm volatile("cp.async.commit_group;" ::: "memory")
#define CP_WAIT2()  asm volatile("cp.async.wait_group 2;" ::: "memory")

__device__ __forceinline__ void mma16816(float* c, const uint32_t* a, const uint32_t* b) {
    asm volatile(
        "mma.sync.aligned.m16n8k16.row.col.f32.f16.f16.f32 "
        "{%0,%1,%2,%3},{%4,%5,%6,%7},{%8,%9},{%0,%1,%2,%3};"
        : "+f"(c[0]), "+f"(c[1]), "+f"(c[2]), "+f"(c[3])
        : "r"(a[0]), "r"(a[1]), "r"(a[2]), "r"(a[3]), "r"(b[0]), "r"(b[1]));
}
__device__ __forceinline__ void ldsm_x4(uint32_t* r, uint32_t addr) {
    asm volatile("ldmatrix.sync.aligned.m8n8.x4.shared.b16 {%0,%1,%2,%3}, [%4];"
                 : "=r"(r[0]), "=r"(r[1]), "=r"(r[2]), "=r"(r[3]) : "r"(addr));
}

// ---------------- split helpers (fp16 hi/lo) ----------------
__device__ __forceinline__ void split_store4(__half* hi, __half* lo, size_t o,
                                             float v0, float v1, float v2, float v3) {
    __half h0 = __float2half_rn(v0), h1 = __float2half_rn(v1);
    __half h2 = __float2half_rn(v2), h3 = __float2half_rn(v3);
    __half2 hp0 = __halves2half2(h0, h1), hp1 = __halves2half2(h2, h3);
    __half2 lp0 = __halves2half2(__float2half_rn(v0 - __half2float(h0)),
                                 __float2half_rn(v1 - __half2float(h1)));
    __half2 lp1 = __halves2half2(__float2half_rn(v2 - __half2float(h2)),
                                 __float2half_rn(v3 - __half2float(h3)));
    uint2 hv, lv;
    hv.x = *(uint32_t*)&hp0; hv.y = *(uint32_t*)&hp1;
    lv.x = *(uint32_t*)&lp0; lv.y = *(uint32_t*)&lp1;
    *reinterpret_cast<uint2*>(hi + o) = hv;
    *reinterpret_cast<uint2*>(lo + o) = lv;
}

__global__ void k_splitA4(const float* __restrict__ X, __half* __restrict__ hi,
                          __half* __restrict__ lo, int M, int K) {
    size_t i4 = (size_t)blockIdx.x * blockDim.x + threadIdx.x;
    const int kq = KPAD / 4;
    if (i4 >= (size_t)M * kq) return;
    int m = (int)(i4 / kq), k4 = (int)(i4 % kq) * 4;
    const float* row = X + (size_t)m * K;
    float v0, v1, v2, v3;
    if (k4 + 3 < K) {
        float4 f = *reinterpret_cast<const float4*>(row + k4);
        v0 = f.x; v1 = f.y; v2 = f.z; v3 = f.w;
    } else {
        v0 = (k4 + 0 < K) ? row[k4 + 0] : 0.f;
        v1 = (k4 + 1 < K) ? row[k4 + 1] : 0.f;
        v2 = (k4 + 2 < K) ? row[k4 + 2] : 0.f;
        v3 = (k4 + 3 < K) ? row[k4 + 3] : 0.f;
    }
    split_store4(hi, lo, (size_t)m * KPAD + k4, v0, v1, v2, v3);
}

// Fused: BN apply + ELU + fp16 split
__global__ void k_bn_elu_split(const float* __restrict__ X,
                               const float* __restrict__ g, const float* __restrict__ b,
                               __half* __restrict__ hi, __half* __restrict__ lo) {
    size_t i4 = (size_t)blockIdx.x * blockDim.x + threadIdx.x;
    const int kq = KPAD / 4;
    if (i4 >= (size_t)Nn * kq) return;
    int m = (int)(i4 / kq), k4 = (int)(i4 % kq) * 4;
    float v[4];
    if (k4 + 3 < INF_) {
        float4 f = *reinterpret_cast<const float4*>(X + (size_t)m * INF_ + k4);
        v[0] = f.x; v[1] = f.y; v[2] = f.z; v[3] = f.w;
#pragma unroll
        for (int q = 0; q < 4; q++) {
            int j = k4 + q;
            float mu  = g_bnsum[j] * (1.f / Nn);
            float var = fmaxf(g_bnsum2[j] * (1.f / Nn) - mu * mu, 0.f);
            v[q] = eluf((v[q] - mu) * rsqrtf(var + EPSBN) * g[j] + b[j]);
        }
    } else {
#pragma unroll
        for (int q = 0; q < 4; q++) {
            int j = k4 + q;
            if (j < INF_) {
                float x = X[(size_t)m * INF_ + j];
                float mu  = g_bnsum[j] * (1.f / Nn);
                float var = fmaxf(g_bnsum2[j] * (1.f / Nn) - mu * mu, 0.f);
                v[q] = eluf((x - mu) * rsqrtf(var + EPSBN) * g[j] + b[j]);
            } else v[q] = 0.f;
        }
    }
    split_store4(hi, lo, (size_t)m * KPAD + k4, v[0], v[1], v[2], v[3]);
}

// Fused: DSBN apply + ELU + fp16 split
__global__ void k_dsbn_elu_split(const float* __restrict__ X, const int* __restrict__ y,
                                 const float* __restrict__ gmm, const float* __restrict__ bta,
                                 __half* __restrict__ hi, __half* __restrict__ lo) {
    size_t i4 = (size_t)blockIdx.x * blockDim.x + threadIdx.x;
    const int kq = KPAD / 4;
    if (i4 >= (size_t)Nn * kq) return;
    int m = (int)(i4 / kq), k4 = (int)(i4 % kq) * 4;
    int d = y[m];
    float c = g_cnt[d];
    bool norm = (c > 1.f);
    float inv = norm ? (1.f / c) : 0.f;
    float v[4];
#pragma unroll
    for (int q = 0; q < 4; q++) {
        int j = k4 + q;
        if (j < INF_) {
            float x = X[(size_t)m * INF_ + j];
            float o = x;
            if (norm) {
                float mu  = g_dsum[d * INF_ + j] * inv;
                float var = fmaxf(g_dsum2[d * INF_ + j] * inv - mu * mu, 0.f);
                o = (x - mu) * rsqrtf(var + EPSBN) * gmm[d * INF_ + j] + bta[d * INF_ + j];
            }
            v[q] = eluf(o);
        } else v[q] = 0.f;
    }
    split_store4(hi, lo, (size_t)m * KPAD + k4, v[0], v[1], v[2], v[3]);
}

// W[K, N] f32 -> WT fp16 [N, KPAD] (zero pad beyond K)
__global__ void k_splitWT(const float* __restrict__ W, __half* __restrict__ hi,
                          int K, int Nmat) {
    __shared__ float t[32][33];
    int kb = blockIdx.x * 32, nb = blockIdx.y * 32;
    int rk = kb + threadIdx.y, rn = nb + threadIdx.x;
    t[threadIdx.y][threadIdx.x] = (rk < K && rn < Nmat) ? W[(size_t)rk * Nmat + rn] : 0.f;
    __syncthreads();
    int wn = nb + threadIdx.y, wk = kb + threadIdx.x;
    if (wn < Nmat && wk < KPAD)
        hi[(size_t)wn * KPAD + wk] = __float2half_rn(t[threadIdx.x][threadIdx.y]);
}

// ------ mma.sync fp16 2-term GEMM: 256 thr, ldmatrix, 3-stage, 2 CTAs/SM ------
#define ROWB      80
#define TILE_PAD  (128 * ROWB)           // 10240 B
#define STAGE_B   (3 * TILE_PAD)         // 30720 B  (Ahi, Alo, B)
#define GSMEM     (3 * STAGE_B)          // 92160 B  -> 2 CTAs/SM (184320 <= 228KB)

__device__ __forceinline__ void ld_stage(
    uint32_t sb,
    const __half* __restrict__ Ahi, const __half* __restrict__ Alo,
    const __half* __restrict__ Bq,
    int m0, int n0, int M, int Nmat, int kb, int tid)
{
    int row = tid >> 1;
    int cb = (tid & 1) * 32;
    int ce = cb >> 1;

    int gA = m0 + row;
    int okA = gA < M;
    const __half* a  = Ahi + (size_t)(okA ? gA : 0) * KPAD + kb + ce;
    const __half* al = Alo + (size_t)(okA ? gA : 0) * KPAD + kb + ce;
    uint32_t soA = sb + (uint32_t)row * ROWB + (uint32_t)cb;
    cp16(soA,      a,      okA);
    cp16(soA + 16, a + 8,  okA);
    cp16(soA + TILE_PAD,      al,     okA);
    cp16(soA + TILE_PAD + 16, al + 8, okA);

    int gB = n0 + row;
    int okB = gB < Nmat;
    const __half* b = Bq + (size_t)(okB ? gB : 0) * KPAD + kb + ce;
    uint32_t soB = sb + 2 * TILE_PAD + (uint32_t)row * ROWB + (uint32_t)cb;
    cp16(soB,      b,     okB);
    cp16(soB + 16, b + 8, okB);
}

__global__ void __launch_bounds__(256, 2) gemm_mma3(
    const __half* __restrict__ Ahi, const __half* __restrict__ Alo,
    const __half* __restrict__ Bq,
    const float* __restrict__ bias, float* __restrict__ C,
    int M, int Nmat, int nNt)
{
    extern __shared__ char smem[];
    uint32_t sbase = smem_u32(smem);
    int tid = threadIdx.x, lane = tid & 31, wid = tid >> 5;
    int wm = wid >> 2, wn = wid & 3;          // warp grid 2x4; warp tile 64x32
    int gID = lane >> 2, tg = lane & 3;
    int bid = blockIdx.x;
    int nt = bid % nNt, mt = bid / nNt;
    int m0 = mt * 128, n0 = nt * 128;
    const int nK = KPAD / 32;

    float acc[4][4][4];
#pragma unroll
    for (int i = 0; i < 4; i++)
#pragma unroll
        for (int j = 0; j < 4; j++)
#pragma unroll
            for (int q = 0; q < 4; q++) acc[i][j][q] = 0.f;

    // prologue: stages 0, 1 in flight
    ld_stage(sbase, Ahi, Alo, Bq, m0, n0, M, Nmat, 0, tid);
    CP_COMMIT();
    ld_stage(sbase + STAGE_B, Ahi, Alo, Bq, m0, n0, M, Nmat, 32, tid);
    CP_COMMIT();

    uint32_t aOff[4], bOff[2];
#pragma unroll
    for (int mi = 0; mi < 4; mi++)
        aOff[mi] = (uint32_t)(wm * 64 + mi * 16 + (lane & 15)) * ROWB + (uint32_t)(lane >> 4) * 16;
#pragma unroll
    for (int pp = 0; pp < 2; pp++)
        bOff[pp] = (uint32_t)(wn * 32 + pp * 16 + ((lane >> 4) << 3) + (lane & 7)) * ROWB
                 + (uint32_t)(((lane >> 3) & 1) << 4);

    for (int kt = 0; kt < nK; kt++) {
        // prefetch stage kt+2 (its buffer was last read in iter kt-1; trailing sync protects it)
        if (kt + 2 < nK) {
            int s2 = (kt + 2) % 3;
            ld_stage(sbase + (uint32_t)s2 * STAGE_B,
                     Ahi, Alo, Bq, m0, n0, M, Nmat, (kt + 2) * 32, tid);
        }
        CP_COMMIT();
        CP_WAIT2();                // stage kt's group complete (<=2 pending)
        __syncthreads();

        uint32_t sb = sbase + (uint32_t)(kt % 3) * STAGE_B;
#pragma unroll
        for (int ks = 0; ks < 2; ks++) {
            uint32_t kb2 = (uint32_t)ks * 32;
            uint32_t bh[2][4];
#pragma unroll
            for (int pp = 0; pp < 2; pp++)
                ldsm_x4(bh[pp], sb + 2 * TILE_PAD + bOff[pp] + kb2);
#pragma unroll
            for (int mi = 0; mi < 4; mi++) {
                uint32_t ah[4], al[4];
                ldsm_x4(ah, sb + aOff[mi] + kb2);
                ldsm_x4(al, sb + TILE_PAD + aOff[mi] + kb2);
#pragma unroll
                for (int ni = 0; ni < 4; ni++) {
                    uint32_t* Bh = &bh[ni >> 1][(ni & 1) * 2];
                    mma16816(acc[mi][ni], ah, Bh);
                    mma16816(acc[mi][ni], al, Bh);
                }
            }
        }
        __syncthreads();
    }

#pragma unroll
    for (int mi = 0; mi < 4; mi++) {
        int r0 = m0 + wm * 64 + mi * 16 + gID;
        int r1 = r0 + 8;
#pragma unroll
        for (int ni = 0; ni < 4; ni++) {
            int cbase = n0 + wn * 32 + ni * 8 + tg * 2;
            if (cbase >= Nmat) continue;
            bool two = (cbase + 1 < Nmat);
            float bx = bias ? bias[cbase] : 0.f;
            float by = (bias && two) ? bias[cbase + 1] : 0.f;
            if (r0 < M) {
                float* p = C + (size_t)r0 * Nmat + cbase;
                if (two) { p[0] = acc[mi][ni][0] + bx; p[1] = acc[mi][ni][1] + by; }
                else p[0] = acc[mi][ni][0] + bx;
            }
            if (r1 < M) {
                float* p = C + (size_t)r1 * Nmat + cbase;
                if (two) { p[0] = acc[mi][ni][2] + bx; p[1] = acc[mi][ni][3] + by; }
                else p[0] = acc[mi][ni][2] + bx;
            }
        }
    }
}

// ---------------- zero scratch ----------------
__global__ void k_zero() {
    size_t i = (size_t)blockIdx.x * blockDim.x + threadIdx.x;
    if (i < (size_t)Nn * NH * HIDF) g_acc1[i] = 0.f;
    if (i < (size_t)Nn * NH * OUTF) g_acc2[i] = 0.f;
    if (i < Nn * NH) {
        g_mkey1[i] = 0u; g_den1[i] = 0.f;
        g_mkey2[i] = 0u; g_den2[i] = 0.f;
    }
    if (i < INF_) { g_bnsum[i] = 0.f; g_bnsum2[i] = 0.f; }
    if (i < NDOMc * INF_) { g_dsum[i] = 0.f; g_dsum2[i] = 0.f; }
    if (i < NDOMc) g_cnt[i] = 0.f;
}

// ---------------- tiled SGEMM (GAT2 small GEMM) ----------------
#define BM 128
#define BN 128
#define BK 8
#define TM 8
#define TN 8
__global__ __launch_bounds__(256) void sgemm_k(
    const float* __restrict__ A, const float* __restrict__ B,
    const float* __restrict__ bias, float* __restrict__ C,
    int M, int Nc, int K)
{
    __shared__ float As[BK][BM];
    __shared__ float Bs[BK][BN];
    int tid = threadIdx.x;
    int m0 = blockIdx.y * BM;
    int n0 = blockIdx.x * BN;
    int tx = tid & 15, ty = tid >> 4;

    float acc[TM][TN];
    #pragma unroll
    for (int i = 0; i < TM; i++)
        #pragma unroll
        for (int j = 0; j < TN; j++) acc[i][j] = 0.f;

    int aRow = tid >> 1;
    int aCol = (tid & 1) * 4;
    int bRow = tid >> 5;
    int bCol = (tid & 31) * 4;

    int nK = K / BK;
    for (int kt = 0; kt < nK; kt++) {
        int kb = kt * BK;
        float4 av = make_float4(0.f, 0.f, 0.f, 0.f);
        if (m0 + aRow < M)
            av = *reinterpret_cast<const float4*>(A + (size_t)(m0 + aRow) * K + kb + aCol);
        As[aCol + 0][aRow] = av.x; As[aCol + 1][aRow] = av.y;
        As[aCol + 2][aRow] = av.z; As[aCol + 3][aRow] = av.w;

        const float* Bp = B + (size_t)(kb + bRow) * Nc + n0 + bCol;
        float4 bv;
        if (n0 + bCol + 3 < Nc && ((((size_t)Bp) & 15) == 0)) {
            bv = *reinterpret_cast<const float4*>(Bp);
        } else {
            bv.x = (n0 + bCol + 0 < Nc) ? Bp[0] : 0.f;
            bv.y = (n0 + bCol + 1 < Nc) ? Bp[1] : 0.f;
            bv.z = (n0 + bCol + 2 < Nc) ? Bp[2] : 0.f;
            bv.w = (n0 + bCol + 3 < Nc) ? Bp[3] : 0.f;
        }
        Bs[bRow][bCol + 0] = bv.x; Bs[bRow][bCol + 1] = bv.y;
        Bs[bRow][bCol + 2] = bv.z; Bs[bRow][bCol + 3] = bv.w;
        __syncthreads();

        #pragma unroll
        for (int k = 0; k < BK; k++) {
            float ar[TM], br[TN];
            #pragma unroll
            for (int i = 0; i < TM; i++) ar[i] = As[k][ty * TM + i];
            #pragma unroll
            for (int j = 0; j < TN; j++) br[j] = Bs[k][tx * TN + j];
            #pragma unroll
            for (int i = 0; i < TM; i++)
                #pragma unroll
                for (int j = 0; j < TN; j++) acc[i][j] += ar[i] * br[j];
        }
        __syncthreads();
    }

    #pragma unroll
    for (int i = 0; i < TM; i++) {
        int m = m0 + ty * TM + i;
        if (m >= M) continue;
        #pragma unroll
        for (int j = 0; j < TN; j++) {
            int n = n0 + tx * TN + j;
            if (n >= Nc) continue;
            float v = acc[i][j];
            if (bias) v += bias[n];
            C[(size_t)m * Nc + n] = v;
        }
    }
}

// ---------------- batch-norm column sums ----------------
__global__ void k_colsum(const float* __restrict__ X) {
    int j = blockIdx.x * blockDim.x + threadIdx.x;
    if (j >= INF_) return;
    int chunk = (Nn + gridDim.y - 1) / gridDim.y;
    int n0 = blockIdx.y * chunk;
    int n1 = min(n0 + chunk, Nn);
    float a = 0.f, b = 0.f;
    for (int n = n0; n < n1; n++) {
        float v = X[(size_t)n * INF_ + j];
        a += v; b += v * v;
    }
    atomicAdd(&g_bnsum[j], a);
    atomicAdd(&g_bnsum2[j], b);
}

// ---------------- attention logits: warp per (n, h) ----------------
__global__ void k_attn_logits(const float* __restrict__ Hh, const float* __restrict__ asrc,
                              const float* __restrict__ adst, float* als, float* ald, int F) {
    int w = (int)(((size_t)blockIdx.x * blockDim.x + threadIdx.x) >> 5);
    int lane = threadIdx.x & 31;
    if (w >= Nn * NH) return;
    int h = w % NH;
    const float* hp = Hh + (size_t)w * F;
    float s = 0.f, d = 0.f;
    for (int t = lane; t < F; t += 32) {
        float hv = hp[t];
        s += hv * asrc[h * F + t];
        d += hv * adst[h * F + t];
    }
    #pragma unroll
    for (int o = 16; o; o >>= 1) {
        s += __shfl_down_sync(0xffffffffu, s, o);
        d += __shfl_down_sync(0xffffffffu, d, o);
    }
    if (lane == 0) { als[w] = s; ald[w] = d; }
}

// ---------------- edge softmax ----------------
__global__ void k_edge_max(const int* __restrict__ src, const int* __restrict__ dst,
                           const float* __restrict__ als, const float* __restrict__ ald,
                           float* e, unsigned* mkey) {
    int i = blockIdx.x * blockDim.x + threadIdx.x;
    if (i >= Ee * NH) return;
    int ed = i / NH, h = i % NH;
    float v = als[src[ed] * NH + h] + ald[dst[ed] * NH + h];
    v = v > 0.f ? v : 0.2f * v;
    e[i] = v;
    atomicMax(&mkey[dst[ed] * NH + h], f2o(v));
}

__global__ void k_edge_exp(const int* __restrict__ dst, float* e,
                           const unsigned* __restrict__ mkey, float* den) {
    int i = blockIdx.x * blockDim.x + threadIdx.x;
    if (i >= Ee * NH) return;
    int ed = i / NH, h = i % NH;
    float m = o2f(mkey[dst[ed] * NH + h]);
    float ex = expf(e[i] - m);
    e[i] = ex;
    atomicAdd(&den[dst[ed] * NH + h], ex);
}

// ---------------- weighted message scatter ----------------
__global__ void k_scatter4(const int* __restrict__ src, const int* __restrict__ dst,
                           const float* __restrict__ Hh, const float* __restrict__ e,
                           const float* __restrict__ den, float* out, int F) {
    int ed = blockIdx.x;
    int s = src[ed], d = dst[ed];
    __shared__ float alpha[NH];
    if (threadIdx.x < NH)
        alpha[threadIdx.x] = e[ed * NH + threadIdx.x] / (den[d * NH + threadIdx.x] + 1e-16f);
    __syncthreads();
    int tot4 = NH * F / 4;
    int fq = F / 4;
    const float4* Hs = reinterpret_cast<const float4*>(Hh + (size_t)s * NH * F);
    float* od = out + (size_t)d * NH * F;
    for (int i4 = threadIdx.x; i4 < tot4; i4 += blockDim.x) {
        int h = i4 / fq;
        float a = alpha[h];
        float4 v = Hs[i4];
        int base = i4 * 4;
        atomicAdd(&od[base + 0], v.x * a);
        atomicAdd(&od[base + 1], v.y * a);
        atomicAdd(&od[base + 2], v.z * a);
        atomicAdd(&od[base + 3], v.w * a);
    }
}

__global__ void k_scatter(const int* __restrict__ src, const int* __restrict__ dst,
                          const float* __restrict__ Hh, const float* __restrict__ e,
                          const float* __restrict__ den, float* out, int F) {
    int ed = blockIdx.x;
    int s = src[ed], d = dst[ed];
    __shared__ float alpha[NH];
    if (threadIdx.x < NH)
        alpha[threadIdx.x] = e[ed * NH + threadIdx.x] / (den[d * NH + threadIdx.x] + 1e-16f);
    __syncthreads();
    int tot = NH * F;
    for (int idx = threadIdx.x; idx < tot; idx += blockDim.x) {
        int h = idx / F;
        atomicAdd(&out[(size_t)d * tot + idx], Hh[(size_t)s * tot + idx] * alpha[h]);
    }
}

// ---------------- head mean (+ optional ELU) ----------------
__global__ void k_mean(const float* __restrict__ acc, float* out, int F, int doElu) {
    size_t i = (size_t)blockIdx.x * blockDim.x + threadIdx.x;
    if (i >= (size_t)Nn * F) return;
    int n = (int)(i / F), d2 = (int)(i % F);
    const float* p = acc + (size_t)n * NH * F + d2;
    float v = (p[0] + p[F] + p[2 * F]) * (1.f / NH);
    if (doElu) v = eluf(v);
    out[i] = v;
}

// ---------------- MLP head ----------------
__global__ void k_mlp(const float* __restrict__ z, const float* __restrict__ w1,
                      const float* __restrict__ b1, const float* __restrict__ w2,
                      const float* __restrict__ b2, const int* __restrict__ flag,
                      float* yp) {
    int n = blockIdx.x;
    int t = threadIdx.x;
    __shared__ float zs[OUTF];
    __shared__ float hid[MHc];
    if (t < OUTF) zs[t] = z[(size_t)n * OUTF + t];
    __syncthreads();
    if (*flag == 0) {
        if (t < NLABc) yp[(size_t)n * NLABc + t] = 0.f;
        return;
    }
    float a = b1[t];
    #pragma unroll
    for (int k = 0; k < OUTF; k++) a += zs[k] * w1[k * MHc + t];
    hid[t] = fmaxf(a, 0.f);
    __syncthreads();
    if (t < NLABc) {
        float o = b2[t];
        #pragma unroll
        for (int k2 = 0; k2 < MHc; k2++) o += hid[k2] * w2[k2 * NLABc + t];
        yp[(size_t)n * NLABc + t] = o;
    }
}

// ---------------- fc2 (K=30, write-bound) — float4 over j ----------------
__global__ void k_fc2v(const float* __restrict__ z, const float* __restrict__ W,
                       const float* __restrict__ b, float* __restrict__ out) {
    size_t i4 = (size_t)blockIdx.x * blockDim.x + threadIdx.x;
    const int jq = INF_ / 4;   // 750
    if (i4 >= (size_t)Nn * jq) return;
    int n = (int)(i4 / jq), j4 = (int)(i4 % jq) * 4;
    float4 acc = *reinterpret_cast<const float4*>(b + j4);
    const float* zr = z + (size_t)n * OUTF;
    #pragma unroll
    for (int k = 0; k < OUTF; k++) {
        float zk = zr[k];
        float4 w = *reinterpret_cast<const float4*>(W + (size_t)k * INF_ + j4);
        acc.x += zk * w.x; acc.y += zk * w.y; acc.z += zk * w.z; acc.w += zk * w.w;
    }
    *reinterpret_cast<float4*>(out + (size_t)n * INF_ + j4) = acc;
}

// ---------------- DSBN ----------------
__global__ void k_cnt(const int* __restrict__ y) {
    int n = blockIdx.x * blockDim.x + threadIdx.x;
    if (n < Nn) atomicAdd(&g_cnt[y[n]], 1.f);
}

__global__ void k_dsbn_sum(const float* __restrict__ X, const int* __restrict__ y) {
    int j = blockIdx.x * blockDim.x + threadIdx.x;
    if (j >= INF_) return;
    int chunk = (Nn + gridDim.y - 1) / gridDim.y;
    int n0 = blockIdx.y * chunk;
    int n1 = min(n0 + chunk, Nn);
    float a[NDOMc], b[NDOMc];
    #pragma unroll
    for (int k = 0; k < NDOMc; k++) { a[k] = 0.f; b[k] = 0.f; }
    for (int n = n0; n < n1; n++) {
        int d = y[n];
        float v = X[(size_t)n * INF_ + j];
        #pragma unroll
        for (int k = 0; k < NDOMc; k++) {
            float m = (d == k) ? 1.f : 0.f;
            a[k] += m * v;
            b[k] += m * v * v;
        }
    }
    #pragma unroll
    for (int k = 0; k < NDOMc; k++) {
        atomicAdd(&g_dsum[k * INF_ + j], a[k]);
        atomicAdd(&g_dsum2[k * INF_ + j], b[k]);
    }
}

// ======================================================================
extern "C" void kernel_launch(void* const* d_in, const int* in_sizes, int n_in,
                              void* d_out, int out_size) {
    const float* features = (const float*)d_in[0];
    const int*   ei       = (const int*)d_in[1];
    const int*   y        = (const int*)d_in[2];
    const int*   flag     = (const int*)d_in[3];
    const float* fc1_w    = (const float*)d_in[4];
    const float* fc1_b    = (const float*)d_in[5];
    const float* bn_g     = (const float*)d_in[6];
    const float* bn_b     = (const float*)d_in[7];
    const float* W1       = (const float*)d_in[8];
    const float* a1_src   = (const float*)d_in[9];
    const float* a1_dst   = (const float*)d_in[10];
    const float* W2       = (const float*)d_in[11];
    const float* a2_src   = (const float*)d_in[12];
    const float* a2_dst   = (const float*)d_in[13];
    const float* mlp_w1   = (const float*)d_in[14];
    const float* mlp_b1   = (const float*)d_in[15];
    const float* mlp_w2   = (const float*)d_in[16];
    const float* mlp_b2   = (const float*)d_in[17];
    const float* fc2_w    = (const float*)d_in[18];
    const float* fc2_b    = (const float*)d_in[19];
    const float* dsbn_g   = (const float*)d_in[20];
    const float* dsbn_b   = (const float*)d_in[21];
    const float* fc3_w    = (const float*)d_in[22];
    const float* fc3_b    = (const float*)d_in[23];

    float* out    = (float*)d_out;
    float* z_out  = out;
    float* h3_out = out + (size_t)Nn * OUTF;
    float* yp_out = h3_out + (size_t)Nn * INF_;
    const int* srcp = ei;
    const int* dstp = ei + Ee;

    void* p;
    cudaGetSymbolAddress(&p, g_x);     float* px    = (float*)p;
    cudaGetSymbolAddress(&p, g_H);     float* pH    = (float*)p;
    cudaGetSymbolAddress(&p, g_acc1);  float* pacc1 = (float*)p;
    cudaGetSymbolAddress(&p, g_h1);    float* ph1   = (float*)p;
    cudaGetSymbolAddress(&p, g_H2);    float* pH2   = (float*)p;
    cudaGetSymbolAddress(&p, g_acc2);  float* pacc2 = (float*)p;
    cudaGetSymbolAddress(&p, g_als1);  float* pals1 = (float*)p;
    cudaGetSymbolAddress(&p, g_ald1);  float* pald1 = (float*)p;
    cudaGetSymbolAddress(&p, g_als2);  float* pals2 = (float*)p;
    cudaGetSymbolAddress(&p, g_ald2);  float* pald2 = (float*)p;
    cudaGetSymbolAddress(&p, g_e1);    float* pe1   = (float*)p;
    cudaGetSymbolAddress(&p, g_e2);    float* pe2   = (float*)p;
    cudaGetSymbolAddress(&p, g_mkey1); unsigned* pmk1 = (unsigned*)p;
    cudaGetSymbolAddress(&p, g_mkey2); unsigned* pmk2 = (unsigned*)p;
    cudaGetSymbolAddress(&p, g_den1);  float* pden1 = (float*)p;
    cudaGetSymbolAddress(&p, g_den2);  float* pden2 = (float*)p;
    cudaGetSymbolAddress(&p, g_Ahi);   __half* pAhi = (__half*)p;
    cudaGetSymbolAddress(&p, g_Alo);   __half* pAlo = (__half*)p;
    cudaGetSymbolAddress(&p, g_Wq);    __half* pWq  = (__half*)p;

    static int smem_set = 0;
    if (!smem_set) {
        cudaFuncSetAttribute(gemm_mma3, cudaFuncAttributeMaxDynamicSharedMemorySize, GSMEM);
        smem_set = 1;
    }

    const int nMt = (Nn + 127) / 128;
    const size_t splitGrid4 = ((size_t)Nn * (KPAD / 4) + 255) / 256;

    // 0) zero scratch
    {
        size_t tot = (size_t)Nn * NH * HIDF;
        k_zero<<<(unsigned)((tot + 255) / 256), 256>>>();
    }

    // 1) fc1
    {
        dim3 tg((KPAD + 31) / 32, (INF_ + 31) / 32);
        k_splitWT<<<tg, dim3(32, 32)>>>(fc1_w, pWq, INF_, INF_);
        k_splitA4<<<(unsigned)splitGrid4, 256>>>(features, pAhi, pAlo, Nn, INF_);
        int nNt = (INF_ + 127) / 128;
        gemm_mma3<<<nMt * nNt, 256, GSMEM>>>(pAhi, pAlo, pWq, fc1_b, px, Nn, INF_, nNt);
    }

    // 2) batchnorm stats + fused apply/ELU/split
    {
        dim3 grid((INF_ + 255) / 256, 128);
        k_colsum<<<grid, 256>>>(px);
        k_bn_elu_split<<<(unsigned)splitGrid4, 256>>>(px, bn_g, bn_b, pAhi, pAlo);
    }

    // 3) GAT layer 1
    {
        dim3 tg((KPAD + 31) / 32, (NH * HIDF + 31) / 32);
        k_splitWT<<<tg, dim3(32, 32)>>>(W1, pWq, INF_, NH * HIDF);
        int nNt = (NH * HIDF + 127) / 128;
        gemm_mma3<<<nMt * nNt, 256, GSMEM>>>(pAhi, pAlo, pWq, nullptr, pH, Nn, NH * HIDF, nNt);

        int warps = Nn * NH;
        k_attn_logits<<<(warps * 32 + 127) / 128, 128>>>(pH, a1_src, a1_dst, pals1, pald1, HIDF);

        int et = Ee * NH;
        k_edge_max<<<(et + 255) / 256, 256>>>(srcp, dstp, pals1, pald1, pe1, pmk1);
        k_edge_exp<<<(et + 255) / 256, 256>>>(dstp, pe1, pmk1, pden1);
        k_scatter4<<<Ee, 256>>>(srcp, dstp, pH, pe1, pden1, pacc1, HIDF);

        size_t tot = (size_t)Nn * HIDF;
        k_mean<<<(unsigned)((tot + 255) / 256), 256>>>(pacc1, ph1, HIDF, 1);
    }

    // 4) GAT layer 2 -> z
    {
        dim3 grid((NH * OUTF + BN - 1) / BN, (Nn + BM - 1) / BM);
        sgemm_k<<<grid, 256>>>(ph1, W2, nullptr, pH2, Nn, NH * OUTF, HIDF);

        int warps = Nn * NH;
        k_attn_logits<<<(warps * 32 + 127) / 128, 128>>>(pH2, a2_src, a2_dst, pals2, pald2, OUTF);

        int et = Ee * NH;
        k_edge_max<<<(et + 255) / 256, 256>>>(srcp, dstp, pals2, pald2, pe2, pmk2);
        k_edge_exp<<<(et + 255) / 256, 256>>>(dstp, pe2, pmk2, pden2);
        k_scatter<<<Ee, 128>>>(srcp, dstp, pH2, pe2, pden2, pacc2, OUTF);

        size_t tot = (size_t)Nn * OUTF;
        k_mean<<<(unsigned)((tot + 255) / 256), 256>>>(pacc2, z_out, OUTF, 0);
    }

    // 5) MLP head
    k_mlp<<<Nn, MHc>>>(z_out, mlp_w1, mlp_b1, mlp_w2, mlp_b2, flag, yp_out);

    // 6) fc2 -> DSBN stats -> fused apply/ELU/split
    {
        size_t tot4 = (size_t)Nn * (INF_ / 4);
        k_fc2v<<<(unsigned)((tot4 + 255) / 256), 256>>>(z_out, fc2_w, fc2_b, px);
        k_cnt<<<(Nn + 255) / 256, 256>>>(y);
        dim3 grid((INF_ + 255) / 256, 128);
        k_dsbn_sum<<<grid, 256>>>(px, y);
        k_dsbn_elu_split<<<(unsigned)splitGrid4, 256>>>(px, y, dsbn_g, dsbn_b, pAhi, pAlo);
    }

    // 7) fc3 -> h3
    {
        dim3 tg((KPAD + 31) / 32, (INF_ + 31) / 32);
        k_splitWT<<<tg, dim3(32, 32)>>>(fc3_w, pWq, INF_, INF_);
        int nNt = (INF_ + 127) / 128;
        gemm_mma3<<<nMt * nNt, 256, GSMEM>>>(pAhi, pAlo, pWq, fc3_b, h3_out, Nn, INF_, nNt);
    }
}

// round 12
// speedup vs baseline: 1.0401x; 1.0401x over previous
#include <cuda_runtime.h>
#include <cuda_bf16.h>
#include <cuda_fp16.h>
#include <math.h>
#include <stdint.h>

#define Nn    20000
#define Ee    120000
#define INF_  3000
#define HIDF  512
#define OUTF  30
#define NH    3
#define NDOMc 4
#define MHc   64
#define NLABc 20
#define EPSBN 1e-5f
#define KPAD  3008                 // 3000 padded to multiple of 32

// ---------------- scratch (static device memory; no allocations) ----------------
__device__ float    g_x[(size_t)Nn * INF_];
__device__ float    g_H[(size_t)Nn * NH * HIDF];
__device__ float    g_acc1[(size_t)Nn * NH * HIDF];
__device__ float    g_h1[(size_t)Nn * HIDF];
__device__ float    g_H2[(size_t)Nn * NH * OUTF];
__device__ float    g_acc2[(size_t)Nn * NH * OUTF];
__device__ float    g_als1[Nn * NH], g_ald1[Nn * NH];
__device__ float    g_als2[Nn * NH], g_ald2[Nn * NH];
__device__ float    g_e1[(size_t)Ee * NH];
__device__ float    g_e2[(size_t)Ee * NH];
__device__ unsigned g_mkey1[Nn * NH], g_mkey2[Nn * NH];
__device__ float    g_den1[Nn * NH], g_den2[Nn * NH];
__device__ float    g_bnsum[INF_], g_bnsum2[INF_];
__device__ float    g_dsum[NDOMc * INF_], g_dsum2[NDOMc * INF_];
__device__ float    g_cnt[NDOMc];
__device__ __align__(256) __half g_Ahi[(size_t)Nn * KPAD];
__device__ __align__(256) __half g_Alo[(size_t)Nn * KPAD];
__device__ __align__(256) __half g_Wq[(size_t)INF_ * KPAD];   // transposed weights [N, KPAD]

// ---------------- helpers ----------------
__device__ __forceinline__ unsigned f2o(float f) {
    unsigned u = __float_as_uint(f);
    return (u & 0x80000000u) ? ~u : (u | 0x80000000u);
}
__device__ __forceinline__ float o2f(unsigned k) {
    return (k & 0x80000000u) ? __uint_as_float(k ^ 0x80000000u) : __uint_as_float(~k);
}
__device__ __forceinline__ float eluf(float v) { return v > 0.f ? v : (expf(v) - 1.f); }

__device__ __forceinline__ uint32_t smem_u32(const void* p) {
    uint32_t a;
    asm("{ .reg .u64 t; cvta.to.shared.u64 t, %1; cvt.u32.u64 %0, t; }" : "=r"(a) : "l"(p));
    return a;
}

__device__ __forceinline__ void cp16(uint32_t dst, const void* src, int ok) {
    asm volatile("cp.async.cg.shared.global [%0], [%1], 16, %2;"
                 :: "r"(dst), "l"(src), "r"(ok ? 16 : 0) : "memory");
}
#define CP_COMMIT() asm volatile("cp.async.commit_group;" ::: "memory")
#define CP_WAIT1()  asm volatile("cp.async.wait_group 1;" ::: "memory")

__device__ __forceinline__ void mma16816(float* c, const uint32_t* a, const uint32_t* b) {
    asm volatile(
        "mma.sync.aligned.m16n8k16.row.col.f32.f16.f16.f32 "
        "{%0,%1,%2,%3},{%4,%5,%6,%7},{%8,%9},{%0,%1,%2,%3};"
        : "+f"(c[0]), "+f"(c[1]), "+f"(c[2]), "+f"(c[3])
        : "r"(a[0]), "r"(a[1]), "r"(a[2]), "r"(a[3]), "r"(b[0]), "r"(b[1]));
}
__device__ __forceinline__ void ldsm_x4(uint32_t* r, uint32_t addr) {
    asm volatile("ldmatrix.sync.aligned.m8n8.x4.shared.b16 {%0,%1,%2,%3}, [%4];"
                 : "=r"(r[0]), "=r"(r[1]), "=r"(r[2]), "=r"(r[3]) : "r"(addr));
}

// ---------------- split helpers (fp16 hi/lo) ----------------
__device__ __forceinline__ void split_store4(__half* hi, __half* lo, size_t o,
                                             float v0, float v1, float v2, float v3) {
    __half h0 = __float2half_rn(v0), h1 = __float2half_rn(v1);
    __half h2 = __float2half_rn(v2), h3 = __float2half_rn(v3);
    __half2 hp0 = __halves2half2(h0, h1), hp1 = __halves2half2(h2, h3);
    __half2 lp0 = __halves2half2(__float2half_rn(v0 - __half2float(h0)),
                                 __float2half_rn(v1 - __half2float(h1)));
    __half2 lp1 = __halves2half2(__float2half_rn(v2 - __half2float(h2)),
                                 __float2half_rn(v3 - __half2float(h3)));
    uint2 hv, lv;
    hv.x = *(uint32_t*)&hp0; hv.y = *(uint32_t*)&hp1;
    lv.x = *(uint32_t*)&lp0; lv.y = *(uint32_t*)&lp1;
    *reinterpret_cast<uint2*>(hi + o) = hv;
    *reinterpret_cast<uint2*>(lo + o) = lv;
}

__global__ void k_splitA4(const float* __restrict__ X, __half* __restrict__ hi,
                          __half* __restrict__ lo, int M, int K) {
    size_t i4 = (size_t)blockIdx.x * blockDim.x + threadIdx.x;
    const int kq = KPAD / 4;
    if (i4 >= (size_t)M * kq) return;
    int m = (int)(i4 / kq), k4 = (int)(i4 % kq) * 4;
    const float* row = X + (size_t)m * K;
    float v0, v1, v2, v3;
    if (k4 + 3 < K) {
        float4 f = *reinterpret_cast<const float4*>(row + k4);
        v0 = f.x; v1 = f.y; v2 = f.z; v3 = f.w;
    } else {
        v0 = (k4 + 0 < K) ? row[k4 + 0] : 0.f;
        v1 = (k4 + 1 < K) ? row[k4 + 1] : 0.f;
        v2 = (k4 + 2 < K) ? row[k4 + 2] : 0.f;
        v3 = (k4 + 3 < K) ? row[k4 + 3] : 0.f;
    }
    split_store4(hi, lo, (size_t)m * KPAD + k4, v0, v1, v2, v3);
}

// Fused: BN apply + ELU + fp16 split
__global__ void k_bn_elu_split(const float* __restrict__ X,
                               const float* __restrict__ g, const float* __restrict__ b,
                               __half* __restrict__ hi, __half* __restrict__ lo) {
    size_t i4 = (size_t)blockIdx.x * blockDim.x + threadIdx.x;
    const int kq = KPAD / 4;
    if (i4 >= (size_t)Nn * kq) return;
    int m = (int)(i4 / kq), k4 = (int)(i4 % kq) * 4;
    float v[4];
    if (k4 + 3 < INF_) {
        float4 f = *reinterpret_cast<const float4*>(X + (size_t)m * INF_ + k4);
        v[0] = f.x; v[1] = f.y; v[2] = f.z; v[3] = f.w;
#pragma unroll
        for (int q = 0; q < 4; q++) {
            int j = k4 + q;
            float mu  = g_bnsum[j] * (1.f / Nn);
            float var = fmaxf(g_bnsum2[j] * (1.f / Nn) - mu * mu, 0.f);
            v[q] = eluf((v[q] - mu) * rsqrtf(var + EPSBN) * g[j] + b[j]);
        }
    } else {
#pragma unroll
        for (int q = 0; q < 4; q++) {
            int j = k4 + q;
            if (j < INF_) {
                float x = X[(size_t)m * INF_ + j];
                float mu  = g_bnsum[j] * (1.f / Nn);
                float var = fmaxf(g_bnsum2[j] * (1.f / Nn) - mu * mu, 0.f);
                v[q] = eluf((x - mu) * rsqrtf(var + EPSBN) * g[j] + b[j]);
            } else v[q] = 0.f;
        }
    }
    split_store4(hi, lo, (size_t)m * KPAD + k4, v[0], v[1], v[2], v[3]);
}

// Fused: DSBN apply + ELU + fp16 split
__global__ void k_dsbn_elu_split(const float* __restrict__ X, const int* __restrict__ y,
                                 const float* __restrict__ gmm, const float* __restrict__ bta,
                                 __half* __restrict__ hi, __half* __restrict__ lo) {
    size_t i4 = (size_t)blockIdx.x * blockDim.x + threadIdx.x;
    const int kq = KPAD / 4;
    if (i4 >= (size_t)Nn * kq) return;
    int m = (int)(i4 / kq), k4 = (int)(i4 % kq) * 4;
    int d = y[m];
    float c = g_cnt[d];
    bool norm = (c > 1.f);
    float inv = norm ? (1.f / c) : 0.f;
    float v[4];
#pragma unroll
    for (int q = 0; q < 4; q++) {
        int j = k4 + q;
        if (j < INF_) {
            float x = X[(size_t)m * INF_ + j];
            float o = x;
            if (norm) {
                float mu  = g_dsum[d * INF_ + j] * inv;
                float var = fmaxf(g_dsum2[d * INF_ + j] * inv - mu * mu, 0.f);
                o = (x - mu) * rsqrtf(var + EPSBN) * gmm[d * INF_ + j] + bta[d * INF_ + j];
            }
            v[q] = eluf(o);
        } else v[q] = 0.f;
    }
    split_store4(hi, lo, (size_t)m * KPAD + k4, v[0], v[1], v[2], v[3]);
}

// W[K, N] f32 -> WT fp16 [N, KPAD] (zero pad beyond K)
__global__ void k_splitWT(const float* __restrict__ W, __half* __restrict__ hi,
                          int K, int Nmat) {
    __shared__ float t[32][33];
    int kb = blockIdx.x * 32, nb = blockIdx.y * 32;
    int rk = kb + threadIdx.y, rn = nb + threadIdx.x;
    t[threadIdx.y][threadIdx.x] = (rk < K && rn < Nmat) ? W[(size_t)rk * Nmat + rn] : 0.f;
    __syncthreads();
    int wn = nb + threadIdx.y, wk = kb + threadIdx.x;
    if (wn < Nmat && wk < KPAD)
        hi[(size_t)wn * KPAD + wk] = __float2half_rn(t[threadIdx.x][threadIdx.y]);
}

// ------ mma.sync fp16 2-term GEMM: 256 thr, ldmatrix, 2-stage, 2 CTAs/SM (round-10 best) ------
#define ROWB      80
#define TILE_PAD  (128 * ROWB)           // 10240 B
#define STAGE_B   (3 * TILE_PAD)         // 30720 B  (Ahi, Alo, B)
#define GSMEM     (2 * STAGE_B)          // 61440 B

__device__ __forceinline__ void ld_stage(
    uint32_t sb,
    const __half* __restrict__ Ahi, const __half* __restrict__ Alo,
    const __half* __restrict__ Bq,
    int m0, int n0, int M, int Nmat, int kb, int tid)
{
    int row = tid >> 1;
    int cb = (tid & 1) * 32;
    int ce = cb >> 1;

    int gA = m0 + row;
    int okA = gA < M;
    const __half* a  = Ahi + (size_t)(okA ? gA : 0) * KPAD + kb + ce;
    const __half* al = Alo + (size_t)(okA ? gA : 0) * KPAD + kb + ce;
    uint32_t soA = sb + (uint32_t)row * ROWB + (uint32_t)cb;
    cp16(soA,      a,      okA);
    cp16(soA + 16, a + 8,  okA);
    cp16(soA + TILE_PAD,      al,     okA);
    cp16(soA + TILE_PAD + 16, al + 8, okA);

    int gB = n0 + row;
    int okB = gB < Nmat;
    const __half* b = Bq + (size_t)(okB ? gB : 0) * KPAD + kb + ce;
    uint32_t soB = sb + 2 * TILE_PAD + (uint32_t)row * ROWB + (uint32_t)cb;
    cp16(soB,      b,     okB);
    cp16(soB + 16, b + 8, okB);
}

__global__ void __launch_bounds__(256, 2) gemm_mma3(
    const __half* __restrict__ Ahi, const __half* __restrict__ Alo,
    const __half* __restrict__ Bq,
    const float* __restrict__ bias, float* __restrict__ C,
    int M, int Nmat, int nNt)
{
    extern __shared__ char smem[];
    uint32_t sbase = smem_u32(smem);
    int tid = threadIdx.x, lane = tid & 31, wid = tid >> 5;
    int wm = wid >> 2, wn = wid & 3;          // warp grid 2x4; warp tile 64x32
    int gID = lane >> 2, tg = lane & 3;
    int bid = blockIdx.x;
    int nt = bid % nNt, mt = bid / nNt;
    int m0 = mt * 128, n0 = nt * 128;
    const int nK = KPAD / 32;

    float acc[4][4][4];
#pragma unroll
    for (int i = 0; i < 4; i++)
#pragma unroll
        for (int j = 0; j < 4; j++)
#pragma unroll
            for (int q = 0; q < 4; q++) acc[i][j][q] = 0.f;

    ld_stage(sbase, Ahi, Alo, Bq, m0, n0, M, Nmat, 0, tid);
    CP_COMMIT();

    uint32_t aOff[4], bOff[2];
#pragma unroll
    for (int mi = 0; mi < 4; mi++)
        aOff[mi] = (uint32_t)(wm * 64 + mi * 16 + (lane & 15)) * ROWB + (uint32_t)(lane >> 4) * 16;
#pragma unroll
    for (int pp = 0; pp < 2; pp++)
        bOff[pp] = (uint32_t)(wn * 32 + pp * 16 + ((lane >> 4) << 3) + (lane & 7)) * ROWB
                 + (uint32_t)(((lane >> 3) & 1) << 4);

    for (int kt = 0; kt < nK; kt++) {
        if (kt + 1 < nK)
            ld_stage(sbase + (uint32_t)((kt + 1) & 1) * STAGE_B,
                     Ahi, Alo, Bq, m0, n0, M, Nmat, (kt + 1) * 32, tid);
        CP_COMMIT();
        CP_WAIT1();
        __syncthreads();

        uint32_t sb = sbase + (uint32_t)(kt & 1) * STAGE_B;
#pragma unroll
        for (int ks = 0; ks < 2; ks++) {
            uint32_t kb2 = (uint32_t)ks * 32;
            uint32_t bh[2][4];
#pragma unroll
            for (int pp = 0; pp < 2; pp++)
                ldsm_x4(bh[pp], sb + 2 * TILE_PAD + bOff[pp] + kb2);
#pragma unroll
            for (int mi = 0; mi < 4; mi++) {
                uint32_t ah[4], al[4];
                ldsm_x4(ah, sb + aOff[mi] + kb2);
                ldsm_x4(al, sb + TILE_PAD + aOff[mi] + kb2);
#pragma unroll
                for (int ni = 0; ni < 4; ni++) {
                    uint32_t* Bh = &bh[ni >> 1][(ni & 1) * 2];
                    mma16816(acc[mi][ni], ah, Bh);
                    mma16816(acc[mi][ni], al, Bh);
                }
            }
        }
        __syncthreads();
    }

#pragma unroll
    for (int mi = 0; mi < 4; mi++) {
        int r0 = m0 + wm * 64 + mi * 16 + gID;
        int r1 = r0 + 8;
#pragma unroll
        for (int ni = 0; ni < 4; ni++) {
            int cbase = n0 + wn * 32 + ni * 8 + tg * 2;
            if (cbase >= Nmat) continue;
            bool two = (cbase + 1 < Nmat);
            float bx = bias ? bias[cbase] : 0.f;
            float by = (bias && two) ? bias[cbase + 1] : 0.f;
            if (r0 < M) {
                float* p = C + (size_t)r0 * Nmat + cbase;
                if (two) { p[0] = acc[mi][ni][0] + bx; p[1] = acc[mi][ni][1] + by; }
                else p[0] = acc[mi][ni][0] + bx;
            }
            if (r1 < M) {
                float* p = C + (size_t)r1 * Nmat + cbase;
                if (two) { p[0] = acc[mi][ni][2] + bx; p[1] = acc[mi][ni][3] + by; }
                else p[0] = acc[mi][ni][2] + bx;
            }
        }
    }
}

// ---------------- zero scratch ----------------
__global__ void k_zero() {
    size_t i = (size_t)blockIdx.x * blockDim.x + threadIdx.x;
    if (i < (size_t)Nn * NH * HIDF) g_acc1[i] = 0.f;
    if (i < (size_t)Nn * NH * OUTF) g_acc2[i] = 0.f;
    if (i < Nn * NH) {
        g_mkey1[i] = 0u; g_den1[i] = 0.f;
        g_mkey2[i] = 0u; g_den2[i] = 0.f;
    }
    if (i < INF_) { g_bnsum[i] = 0.f; g_bnsum2[i] = 0.f; }
    if (i < NDOMc * INF_) { g_dsum[i] = 0.f; g_dsum2[i] = 0.f; }
    if (i < NDOMc) g_cnt[i] = 0.f;
}

// ---------------- tiled SGEMM (GAT2 small GEMM) ----------------
#define BM 128
#define BN 128
#define BK 8
#define TM 8
#define TN 8
__global__ __launch_bounds__(256) void sgemm_k(
    const float* __restrict__ A, const float* __restrict__ B,
    const float* __restrict__ bias, float* __restrict__ C,
    int M, int Nc, int K)
{
    __shared__ float As[BK][BM];
    __shared__ float Bs[BK][BN];
    int tid = threadIdx.x;
    int m0 = blockIdx.y * BM;
    int n0 = blockIdx.x * BN;
    int tx = tid & 15, ty = tid >> 4;

    float acc[TM][TN];
    #pragma unroll
    for (int i = 0; i < TM; i++)
        #pragma unroll
        for (int j = 0; j < TN; j++) acc[i][j] = 0.f;

    int aRow = tid >> 1;
    int aCol = (tid & 1) * 4;
    int bRow = tid >> 5;
    int bCol = (tid & 31) * 4;

    int nK = K / BK;
    for (int kt = 0; kt < nK; kt++) {
        int kb = kt * BK;
        float4 av = make_float4(0.f, 0.f, 0.f, 0.f);
        if (m0 + aRow < M)
            av = *reinterpret_cast<const float4*>(A + (size_t)(m0 + aRow) * K + kb + aCol);
        As[aCol + 0][aRow] = av.x; As[aCol + 1][aRow] = av.y;
        As[aCol + 2][aRow] = av.z; As[aCol + 3][aRow] = av.w;

        const float* Bp = B + (size_t)(kb + bRow) * Nc + n0 + bCol;
        float4 bv;
        if (n0 + bCol + 3 < Nc && ((((size_t)Bp) & 15) == 0)) {
            bv = *reinterpret_cast<const float4*>(Bp);
        } else {
            bv.x = (n0 + bCol + 0 < Nc) ? Bp[0] : 0.f;
            bv.y = (n0 + bCol + 1 < Nc) ? Bp[1] : 0.f;
            bv.z = (n0 + bCol + 2 < Nc) ? Bp[2] : 0.f;
            bv.w = (n0 + bCol + 3 < Nc) ? Bp[3] : 0.f;
        }
        Bs[bRow][bCol + 0] = bv.x; Bs[bRow][bCol + 1] = bv.y;
        Bs[bRow][bCol + 2] = bv.z; Bs[bRow][bCol + 3] = bv.w;
        __syncthreads();

        #pragma unroll
        for (int k = 0; k < BK; k++) {
            float ar[TM], br[TN];
            #pragma unroll
            for (int i = 0; i < TM; i++) ar[i] = As[k][ty * TM + i];
            #pragma unroll
            for (int j = 0; j < TN; j++) br[j] = Bs[k][tx * TN + j];
            #pragma unroll
            for (int i = 0; i < TM; i++)
                #pragma unroll
                for (int j = 0; j < TN; j++) acc[i][j] += ar[i] * br[j];
        }
        __syncthreads();
    }

    #pragma unroll
    for (int i = 0; i < TM; i++) {
        int m = m0 + ty * TM + i;
        if (m >= M) continue;
        #pragma unroll
        for (int j = 0; j < TN; j++) {
            int n = n0 + tx * TN + j;
            if (n >= Nc) continue;
            float v = acc[i][j];
            if (bias) v += bias[n];
            C[(size_t)m * Nc + n] = v;
        }
    }
}

// ---------------- batch-norm column sums ----------------
__global__ void k_colsum(const float* __restrict__ X) {
    int j = blockIdx.x * blockDim.x + threadIdx.x;
    if (j >= INF_) return;
    int chunk = (Nn + gridDim.y - 1) / gridDim.y;
    int n0 = blockIdx.y * chunk;
    int n1 = min(n0 + chunk, Nn);
    float a = 0.f, b = 0.f;
    for (int n = n0; n < n1; n++) {
        float v = X[(size_t)n * INF_ + j];
        a += v; b += v * v;
    }
    atomicAdd(&g_bnsum[j], a);
    atomicAdd(&g_bnsum2[j], b);
}

// ---------------- attention logits: warp per (n, h) ----------------
__global__ void k_attn_logits(const float* __restrict__ Hh, const float* __restrict__ asrc,
                              const float* __restrict__ adst, float* als, float* ald, int F) {
    int w = (int)(((size_t)blockIdx.x * blockDim.x + threadIdx.x) >> 5);
    int lane = threadIdx.x & 31;
    if (w >= Nn * NH) return;
    int h = w % NH;
    const float* hp = Hh + (size_t)w * F;
    float s = 0.f, d = 0.f;
    for (int t = lane; t < F; t += 32) {
        float hv = hp[t];
        s += hv * asrc[h * F + t];
        d += hv * adst[h * F + t];
    }
    #pragma unroll
    for (int o = 16; o; o >>= 1) {
        s += __shfl_down_sync(0xffffffffu, s, o);
        d += __shfl_down_sync(0xffffffffu, d, o);
    }
    if (lane == 0) { als[w] = s; ald[w] = d; }
}

// ---------------- edge softmax ----------------
__global__ void k_edge_max(const int* __restrict__ src, const int* __restrict__ dst,
                           const float* __restrict__ als, const float* __restrict__ ald,
                           float* e, unsigned* mkey) {
    int i = blockIdx.x * blockDim.x + threadIdx.x;
    if (i >= Ee * NH) return;
    int ed = i / NH, h = i % NH;
    float v = als[src[ed] * NH + h] + ald[dst[ed] * NH + h];
    v = v > 0.f ? v : 0.2f * v;
    e[i] = v;
    atomicMax(&mkey[dst[ed] * NH + h], f2o(v));
}

__global__ void k_edge_exp(const int* __restrict__ dst, float* e,
                           const unsigned* __restrict__ mkey, float* den) {
    int i = blockIdx.x * blockDim.x + threadIdx.x;
    if (i >= Ee * NH) return;
    int ed = i / NH, h = i % NH;
    float m = o2f(mkey[dst[ed] * NH + h]);
    float ex = expf(e[i] - m);
    e[i] = ex;
    atomicAdd(&den[dst[ed] * NH + h], ex);
}

// ---------------- weighted message scatter: warp per (edge, head) ----------------
__global__ void k_scatter_w(const int* __restrict__ src, const int* __restrict__ dst,
                            const float* __restrict__ Hh, const float* __restrict__ e,
                            const float* __restrict__ den, float* __restrict__ out) {
    int w = (int)(((size_t)blockIdx.x * blockDim.x + threadIdx.x) >> 5);
    int lane = threadIdx.x & 31;
    if (w >= Ee * NH) return;
    int ed = w / NH, h = w % NH;
    int s = src[ed], d = dst[ed];
    float a = e[ed * NH + h] / (den[d * NH + h] + 1e-16f);
    const float4* Hs = reinterpret_cast<const float4*>(Hh + ((size_t)s * NH + h) * HIDF);
    float* od = out + ((size_t)d * NH + h) * HIDF;
    const int f4 = HIDF / 4;   // 128
#pragma unroll
    for (int i = lane; i < f4; i += 32) {
        float4 v = Hs[i];
        int base = i * 4;
        atomicAdd(&od[base + 0], v.x * a);
        atomicAdd(&od[base + 1], v.y * a);
        atomicAdd(&od[base + 2], v.z * a);
        atomicAdd(&od[base + 3], v.w * a);
    }
}

// warp per (edge, head), F=30 scalar
__global__ void k_scatter_w30(const int* __restrict__ src, const int* __restrict__ dst,
                              const float* __restrict__ Hh, const float* __restrict__ e,
                              const float* __restrict__ den, float* __restrict__ out) {
    int w = (int)(((size_t)blockIdx.x * blockDim.x + threadIdx.x) >> 5);
    int lane = threadIdx.x & 31;
    if (w >= Ee * NH) return;
    int ed = w / NH, h = w % NH;
    int s = src[ed], d = dst[ed];
    float a = e[ed * NH + h] / (den[d * NH + h] + 1e-16f);
    const float* Hs = Hh + ((size_t)s * NH + h) * OUTF;
    float* od = out + ((size_t)d * NH + h) * OUTF;
    if (lane < OUTF)
        atomicAdd(&od[lane], Hs[lane] * a);
}

// ---------------- head mean (+ optional ELU) ----------------
__global__ void k_mean(const float* __restrict__ acc, float* out, int F, int doElu) {
    size_t i = (size_t)blockIdx.x * blockDim.x + threadIdx.x;
    if (i >= (size_t)Nn * F) return;
    int n = (int)(i / F), d2 = (int)(i % F);
    const float* p = acc + (size_t)n * NH * F + d2;
    float v = (p[0] + p[F] + p[2 * F]) * (1.f / NH);
    if (doElu) v = eluf(v);
    out[i] = v;
}

// ---------------- MLP head ----------------
__global__ void k_mlp(const float* __restrict__ z, const float* __restrict__ w1,
                      const float* __restrict__ b1, const float* __restrict__ w2,
                      const float* __restrict__ b2, const int* __restrict__ flag,
                      float* yp) {
    int n = blockIdx.x;
    int t = threadIdx.x;
    __shared__ float zs[OUTF];
    __shared__ float hid[MHc];
    if (t < OUTF) zs[t] = z[(size_t)n * OUTF + t];
    __syncthreads();
    if (*flag == 0) {
        if (t < NLABc) yp[(size_t)n * NLABc + t] = 0.f;
        return;
    }
    float a = b1[t];
    #pragma unroll
    for (int k = 0; k < OUTF; k++) a += zs[k] * w1[k * MHc + t];
    hid[t] = fmaxf(a, 0.f);
    __syncthreads();
    if (t < NLABc) {
        float o = b2[t];
        #pragma unroll
        for (int k2 = 0; k2 < MHc; k2++) o += hid[k2] * w2[k2 * NLABc + t];
        yp[(size_t)n * NLABc + t] = o;
    }
}

// ---------------- fc2 (K=30, write-bound) — float4 over j ----------------
__global__ void k_fc2v(const float* __restrict__ z, const float* __restrict__ W,
                       const float* __restrict__ b, float* __restrict__ out) {
    size_t i4 = (size_t)blockIdx.x * blockDim.x + threadIdx.x;
    const int jq = INF_ / 4;   // 750
    if (i4 >= (size_t)Nn * jq) return;
    int n = (int)(i4 / jq), j4 = (int)(i4 % jq) * 4;
    float4 acc = *reinterpret_cast<const float4*>(b + j4);
    const float* zr = z + (size_t)n * OUTF;
    #pragma unroll
    for (int k = 0; k < OUTF; k++) {
        float zk = zr[k];
        float4 w = *reinterpret_cast<const float4*>(W + (size_t)k * INF_ + j4);
        acc.x += zk * w.x; acc.y += zk * w.y; acc.z += zk * w.z; acc.w += zk * w.w;
    }
    *reinterpret_cast<float4*>(out + (size_t)n * INF_ + j4) = acc;
}

// ---------------- DSBN ----------------
__global__ void k_cnt(const int* __restrict__ y) {
    int n = blockIdx.x * blockDim.x + threadIdx.x;
    if (n < Nn) atomicAdd(&g_cnt[y[n]], 1.f);
}

__global__ void k_dsbn_sum(const float* __restrict__ X, const int* __restrict__ y) {
    int j = blockIdx.x * blockDim.x + threadIdx.x;
    if (j >= INF_) return;
    int chunk = (Nn + gridDim.y - 1) / gridDim.y;
    int n0 = blockIdx.y * chunk;
    int n1 = min(n0 + chunk, Nn);
    float a[NDOMc], b[NDOMc];
    #pragma unroll
    for (int k = 0; k < NDOMc; k++) { a[k] = 0.f; b[k] = 0.f; }
    for (int n = n0; n < n1; n++) {
        int d = y[n];
        float v = X[(size_t)n * INF_ + j];
        #pragma unroll
        for (int k = 0; k < NDOMc; k++) {
            float m = (d == k) ? 1.f : 0.f;
            a[k] += m * v;
            b[k] += m * v * v;
        }
    }
    #pragma unroll
    for (int k = 0; k < NDOMc; k++) {
        atomicAdd(&g_dsum[k * INF_ + j], a[k]);
        atomicAdd(&g_dsum2[k * INF_ + j], b[k]);
    }
}

// ======================================================================
extern "C" void kernel_launch(void* const* d_in, const int* in_sizes, int n_in,
                              void* d_out, int out_size) {
    const float* features = (const float*)d_in[0];
    const int*   ei       = (const int*)d_in[1];
    const int*   y        = (const int*)d_in[2];
    const int*   flag     = (const int*)d_in[3];
    const float* fc1_w    = (const float*)d_in[4];
    const float* fc1_b    = (const float*)d_in[5];
    const float* bn_g     = (const float*)d_in[6];
    const float* bn_b     = (const float*)d_in[7];
    const float* W1       = (const float*)d_in[8];
    const float* a1_src   = (const float*)d_in[9];
    const float* a1_dst   = (const float*)d_in[10];
    const float* W2       = (const float*)d_in[11];
    const float* a2_src   = (const float*)d_in[12];
    const float* a2_dst   = (const float*)d_in[13];
    const float* mlp_w1   = (const float*)d_in[14];
    const float* mlp_b1   = (const float*)d_in[15];
    const float* mlp_w2   = (const float*)d_in[16];
    const float* mlp_b2   = (const float*)d_in[17];
    const float* fc2_w    = (const float*)d_in[18];
    const float* fc2_b    = (const float*)d_in[19];
    const float* dsbn_g   = (const float*)d_in[20];
    const float* dsbn_b   = (const float*)d_in[21];
    const float* fc3_w    = (const float*)d_in[22];
    const float* fc3_b    = (const float*)d_in[23];

    float* out    = (float*)d_out;
    float* z_out  = out;
    float* h3_out = out + (size_t)Nn * OUTF;
    float* yp_out = h3_out + (size_t)Nn * INF_;
    const int* srcp = ei;
    const int* dstp = ei + Ee;

    void* p;
    cudaGetSymbolAddress(&p, g_x);     float* px    = (float*)p;
    cudaGetSymbolAddress(&p, g_H);     float* pH    = (float*)p;
    cudaGetSymbolAddress(&p, g_acc1);  float* pacc1 = (float*)p;
    cudaGetSymbolAddress(&p, g_h1);    float* ph1   = (float*)p;
    cudaGetSymbolAddress(&p, g_H2);    float* pH2   = (float*)p;
    cudaGetSymbolAddress(&p, g_acc2);  float* pacc2 = (float*)p;
    cudaGetSymbolAddress(&p, g_als1);  float* pals1 = (float*)p;
    cudaGetSymbolAddress(&p, g_ald1);  float* pald1 = (float*)p;
    cudaGetSymbolAddress(&p, g_als2);  float* pals2 = (float*)p;
    cudaGetSymbolAddress(&p, g_ald2);  float* pald2 = (float*)p;
    cudaGetSymbolAddress(&p, g_e1);    float* pe1   = (float*)p;
    cudaGetSymbolAddress(&p, g_e2);    float* pe2   = (float*)p;
    cudaGetSymbolAddress(&p, g_mkey1); unsigned* pmk1 = (unsigned*)p;
    cudaGetSymbolAddress(&p, g_mkey2); unsigned* pmk2 = (unsigned*)p;
    cudaGetSymbolAddress(&p, g_den1);  float* pden1 = (float*)p;
    cudaGetSymbolAddress(&p, g_den2);  float* pden2 = (float*)p;
    cudaGetSymbolAddress(&p, g_Ahi);   __half* pAhi = (__half*)p;
    cudaGetSymbolAddress(&p, g_Alo);   __half* pAlo = (__half*)p;
    cudaGetSymbolAddress(&p, g_Wq);    __half* pWq  = (__half*)p;

    static int smem_set = 0;
    if (!smem_set) {
        cudaFuncSetAttribute(gemm_mma3, cudaFuncAttributeMaxDynamicSharedMemorySize, GSMEM);
        smem_set = 1;
    }

    const int nMt = (Nn + 127) / 128;
    const size_t splitGrid4 = ((size_t)Nn * (KPAD / 4) + 255) / 256;
    const int scW = (Ee * NH * 32 + 255) / 256;   // warp-per-(edge,head) grid

    // 0) zero scratch
    {
        size_t tot = (size_t)Nn * NH * HIDF;
        k_zero<<<(unsigned)((tot + 255) / 256), 256>>>();
    }

    // 1) fc1
    {
        dim3 tg((KPAD + 31) / 32, (INF_ + 31) / 32);
        k_splitWT<<<tg, dim3(32, 32)>>>(fc1_w, pWq, INF_, INF_);
        k_splitA4<<<(unsigned)splitGrid4, 256>>>(features, pAhi, pAlo, Nn, INF_);
        int nNt = (INF_ + 127) / 128;
        gemm_mma3<<<nMt * nNt, 256, GSMEM>>>(pAhi, pAlo, pWq, fc1_b, px, Nn, INF_, nNt);
    }

    // 2) batchnorm stats + fused apply/ELU/split
    {
        dim3 grid((INF_ + 255) / 256, 128);
        k_colsum<<<grid, 256>>>(px);
        k_bn_elu_split<<<(unsigned)splitGrid4, 256>>>(px, bn_g, bn_b, pAhi, pAlo);
    }

    // 3) GAT layer 1
    {
        dim3 tg((KPAD + 31) / 32, (NH * HIDF + 31) / 32);
        k_splitWT<<<tg, dim3(32, 32)>>>(W1, pWq, INF_, NH * HIDF);
        int nNt = (NH * HIDF + 127) / 128;
        gemm_mma3<<<nMt * nNt, 256, GSMEM>>>(pAhi, pAlo, pWq, nullptr, pH, Nn, NH * HIDF, nNt);

        int warps = Nn * NH;
        k_attn_logits<<<(warps * 32 + 127) / 128, 128>>>(pH, a1_src, a1_dst, pals1, pald1, HIDF);

        int et = Ee * NH;
        k_edge_max<<<(et + 255) / 256, 256>>>(srcp, dstp, pals1, pald1, pe1, pmk1);
        k_edge_exp<<<(et + 255) / 256, 256>>>(dstp, pe1, pmk1, pden1);
        k_scatter_w<<<scW, 256>>>(srcp, dstp, pH, pe1, pden1, pacc1);

        size_t tot = (size_t)Nn * HIDF;
        k_mean<<<(unsigned)((tot + 255) / 256), 256>>>(pacc1, ph1, HIDF, 1);
    }

    // 4) GAT layer 2 -> z
    {
        dim3 grid((NH * OUTF + BN - 1) / BN, (Nn + BM - 1) / BM);
        sgemm_k<<<grid, 256>>>(ph1, W2, nullptr, pH2, Nn, NH * OUTF, HIDF);

        int warps = Nn * NH;
        k_attn_logits<<<(warps * 32 + 127) / 128, 128>>>(pH2, a2_src, a2_dst, pals2, pald2, OUTF);

        int et = Ee * NH;
        k_edge_max<<<(et + 255) / 256, 256>>>(srcp, dstp, pals2, pald2, pe2, pmk2);
        k_edge_exp<<<(et + 255) / 256, 256>>>(dstp, pe2, pmk2, pden2);
        k_scatter_w30<<<scW, 256>>>(srcp, dstp, pH2, pe2, pden2, pacc2);

        size_t tot = (size_t)Nn * OUTF;
        k_mean<<<(unsigned)((tot + 255) / 256), 256>>>(pacc2, z_out, OUTF, 0);
    }

    // 5) MLP head
    k_mlp<<<Nn, MHc>>>(z_out, mlp_w1, mlp_b1, mlp_w2, mlp_b2, flag, yp_out);

    // 6) fc2 -> DSBN stats -> fused apply/ELU/split
    {
        size_t tot4 = (size_t)Nn * (INF_ / 4);
        k_fc2v<<<(unsigned)((tot4 + 255) / 256), 256>>>(z_out, fc2_w, fc2_b, px);
        k_cnt<<<(Nn + 255) / 256, 256>>>(y);
        dim3 grid((INF_ + 255) / 256, 128);
        k_dsbn_sum<<<grid, 256>>>(px, y);
        k_dsbn_elu_split<<<(unsigned)splitGrid4, 256>>>(px, y, dsbn_g, dsbn_b, pAhi, pAlo);
    }

    // 7) fc3 -> h3
    {
        dim3 tg((KPAD + 31) / 32, (INF_ + 31) / 32);
        k_splitWT<<<tg, dim3(32, 32)>>>(fc3_w, pWq, INF_, INF_);
        int nNt = (INF_ + 127) / 128;
        gemm_mma3<<<nMt * nNt, 256, GSMEM>>>(pAhi, pAlo, pWq, fc3_b, h3_out, Nn, INF_, nNt);
    }
}

// round 13
// speedup vs baseline: 1.4734x; 1.4166x over previous
#include <cuda_runtime.h>
#include <cuda_bf16.h>
#include <cuda_fp16.h>
#include <math.h>
#include <stdint.h>

#define Nn    20000
#define Ee    120000
#define INF_  3000
#define HIDF  512
#define OUTF  30
#define NH    3
#define NDOMc 4
#define MHc   64
#define NLABc 20
#define EPSBN 1e-5f
#define KPAD  3008                 // 3000 padded to multiple of 32

// ---------------- scratch (static device memory; no allocations) ----------------
__device__ float    g_x[(size_t)Nn * INF_];
__device__ float    g_H[(size_t)Nn * NH * HIDF];
__device__ float    g_h1[(size_t)Nn * HIDF];
__device__ float    g_H2[(size_t)Nn * NH * OUTF];
__device__ float    g_als1[Nn * NH], g_ald1[Nn * NH];
__device__ float    g_als2[Nn * NH], g_ald2[Nn * NH];
__device__ float    g_e1[(size_t)Ee * NH];
__device__ float    g_e2[(size_t)Ee * NH];
__device__ unsigned g_mkey1[Nn * NH], g_mkey2[Nn * NH];
__device__ float    g_den1[Nn * NH], g_den2[Nn * NH];
__device__ float    g_bnsum[INF_], g_bnsum2[INF_];
__device__ float    g_dsum[NDOMc * INF_], g_dsum2[NDOMc * INF_];
__device__ float    g_cnt[NDOMc];
__device__ __align__(256) __half g_Aq[(size_t)Nn * KPAD];
__device__ __align__(256) __half g_Wq[(size_t)INF_ * KPAD];   // transposed weights [N, KPAD]

// ---------------- helpers ----------------
__device__ __forceinline__ unsigned f2o(float f) {
    unsigned u = __float_as_uint(f);
    return (u & 0x80000000u) ? ~u : (u | 0x80000000u);
}
__device__ __forceinline__ float o2f(unsigned k) {
    return (k & 0x80000000u) ? __uint_as_float(k ^ 0x80000000u) : __uint_as_float(~k);
}
__device__ __forceinline__ float eluf(float v) { return v > 0.f ? v : (expf(v) - 1.f); }

__device__ __forceinline__ uint32_t smem_u32(const void* p) {
    uint32_t a;
    asm("{ .reg .u64 t; cvta.to.shared.u64 t, %1; cvt.u32.u64 %0, t; }" : "=r"(a) : "l"(p));
    return a;
}

__device__ __forceinline__ void cp16(uint32_t dst, const void* src, int ok) {
    asm volatile("cp.async.cg.shared.global [%0], [%1], 16, %2;"
                 :: "r"(dst), "l"(src), "r"(ok ? 16 : 0) : "memory");
}
#define CP_COMMIT() asm volatile("cp.async.commit_group;" ::: "memory")
#define CP_WAIT1()  asm volatile("cp.async.wait_group 1;" ::: "memory")

__device__ __forceinline__ void mma16816(float* c, const uint32_t* a, const uint32_t* b) {
    asm volatile(
        "mma.sync.aligned.m16n8k16.row.col.f32.f16.f16.f32 "
        "{%0,%1,%2,%3},{%4,%5,%6,%7},{%8,%9},{%0,%1,%2,%3};"
        : "+f"(c[0]), "+f"(c[1]), "+f"(c[2]), "+f"(c[3])
        : "r"(a[0]), "r"(a[1]), "r"(a[2]), "r"(a[3]), "r"(b[0]), "r"(b[1]));
}
__device__ __forceinline__ void ldsm_x4(uint32_t* r, uint32_t addr) {
    asm volatile("ldmatrix.sync.aligned.m8n8.x4.shared.b16 {%0,%1,%2,%3}, [%4];"
                 : "=r"(r[0]), "=r"(r[1]), "=r"(r[2]), "=r"(r[3]) : "r"(addr));
}

// ---------------- fp16 convert helpers ----------------
__device__ __forceinline__ void cvt_store4(__half* dst, size_t o,
                                           float v0, float v1, float v2, float v3) {
    __half2 p0 = __halves2half2(__float2half_rn(v0), __float2half_rn(v1));
    __half2 p1 = __halves2half2(__float2half_rn(v2), __float2half_rn(v3));
    uint2 hv;
    hv.x = *(uint32_t*)&p0; hv.y = *(uint32_t*)&p1;
    *reinterpret_cast<uint2*>(dst + o) = hv;
}

__global__ void k_cvtA4(const float* __restrict__ X, __half* __restrict__ q, int M, int K) {
    size_t i4 = (size_t)blockIdx.x * blockDim.x + threadIdx.x;
    const int kq = KPAD / 4;
    if (i4 >= (size_t)M * kq) return;
    int m = (int)(i4 / kq), k4 = (int)(i4 % kq) * 4;
    const float* row = X + (size_t)m * K;
    float v0, v1, v2, v3;
    if (k4 + 3 < K) {
        float4 f = *reinterpret_cast<const float4*>(row + k4);
        v0 = f.x; v1 = f.y; v2 = f.z; v3 = f.w;
    } else {
        v0 = (k4 + 0 < K) ? row[k4 + 0] : 0.f;
        v1 = (k4 + 1 < K) ? row[k4 + 1] : 0.f;
        v2 = (k4 + 2 < K) ? row[k4 + 2] : 0.f;
        v3 = (k4 + 3 < K) ? row[k4 + 3] : 0.f;
    }
    cvt_store4(q, (size_t)m * KPAD + k4, v0, v1, v2, v3);
}

// Fused: BN apply + ELU + fp16 convert
__global__ void k_bn_elu_cvt(const float* __restrict__ X,
                             const float* __restrict__ g, const float* __restrict__ b,
                             __half* __restrict__ q) {
    size_t i4 = (size_t)blockIdx.x * blockDim.x + threadIdx.x;
    const int kq = KPAD / 4;
    if (i4 >= (size_t)Nn * kq) return;
    int m = (int)(i4 / kq), k4 = (int)(i4 % kq) * 4;
    float v[4];
    if (k4 + 3 < INF_) {
        float4 f = *reinterpret_cast<const float4*>(X + (size_t)m * INF_ + k4);
        v[0] = f.x; v[1] = f.y; v[2] = f.z; v[3] = f.w;
#pragma unroll
        for (int qq = 0; qq < 4; qq++) {
            int j = k4 + qq;
            float mu  = g_bnsum[j] * (1.f / Nn);
            float var = fmaxf(g_bnsum2[j] * (1.f / Nn) - mu * mu, 0.f);
            v[qq] = eluf((v[qq] - mu) * rsqrtf(var + EPSBN) * g[j] + b[j]);
        }
    } else {
#pragma unroll
        for (int qq = 0; qq < 4; qq++) {
            int j = k4 + qq;
            if (j < INF_) {
                float x = X[(size_t)m * INF_ + j];
                float mu  = g_bnsum[j] * (1.f / Nn);
                float var = fmaxf(g_bnsum2[j] * (1.f / Nn) - mu * mu, 0.f);
                v[qq] = eluf((x - mu) * rsqrtf(var + EPSBN) * g[j] + b[j]);
            } else v[qq] = 0.f;
        }
    }
    cvt_store4(q, (size_t)m * KPAD + k4, v[0], v[1], v[2], v[3]);
}

// Fused: DSBN apply + ELU + fp16 convert
__global__ void k_dsbn_elu_cvt(const float* __restrict__ X, const int* __restrict__ y,
                               const float* __restrict__ gmm, const float* __restrict__ bta,
                               __half* __restrict__ q) {
    size_t i4 = (size_t)blockIdx.x * blockDim.x + threadIdx.x;
    const int kq = KPAD / 4;
    if (i4 >= (size_t)Nn * kq) return;
    int m = (int)(i4 / kq), k4 = (int)(i4 % kq) * 4;
    int d = y[m];
    float c = g_cnt[d];
    bool norm = (c > 1.f);
    float inv = norm ? (1.f / c) : 0.f;
    float v[4];
#pragma unroll
    for (int qq = 0; qq < 4; qq++) {
        int j = k4 + qq;
        if (j < INF_) {
            float x = X[(size_t)m * INF_ + j];
            float o = x;
            if (norm) {
                float mu  = g_dsum[d * INF_ + j] * inv;
                float var = fmaxf(g_dsum2[d * INF_ + j] * inv - mu * mu, 0.f);
                o = (x - mu) * rsqrtf(var + EPSBN) * gmm[d * INF_ + j] + bta[d * INF_ + j];
            }
            v[qq] = eluf(o);
        } else v[qq] = 0.f;
    }
    cvt_store4(q, (size_t)m * KPAD + k4, v[0], v[1], v[2], v[3]);
}

// W[K, N] f32 -> WT fp16 [N, KPAD] (zero pad beyond K)
__global__ void k_splitWT(const float* __restrict__ W, __half* __restrict__ hi,
                          int K, int Nmat) {
    __shared__ float t[32][33];
    int kb = blockIdx.x * 32, nb = blockIdx.y * 32;
    int rk = kb + threadIdx.y, rn = nb + threadIdx.x;
    t[threadIdx.y][threadIdx.x] = (rk < K && rn < Nmat) ? W[(size_t)rk * Nmat + rn] : 0.f;
    __syncthreads();
    int wn = nb + threadIdx.y, wk = kb + threadIdx.x;
    if (wn < Nmat && wk < KPAD)
        hi[(size_t)wn * KPAD + wk] = __float2half_rn(t[threadIdx.x][threadIdx.y]);
}

// ------ mma.sync fp16 single-term GEMM: 256 thr, ldmatrix, 2-stage, 2 CTAs/SM ------
#define ROWB      80
#define TILE_PAD  (128 * ROWB)           // 10240 B
#define STAGE_B   (2 * TILE_PAD)         // 20480 B  (A, B)
#define GSMEM     (2 * STAGE_B)          // 40960 B

__device__ __forceinline__ void ld_stage(
    uint32_t sb,
    const __half* __restrict__ Aq, const __half* __restrict__ Bq,
    int m0, int n0, int M, int Nmat, int kb, int tid)
{
    int row = tid >> 1;
    int cb = (tid & 1) * 32;
    int ce = cb >> 1;

    int gA = m0 + row;
    int okA = gA < M;
    const __half* a = Aq + (size_t)(okA ? gA : 0) * KPAD + kb + ce;
    uint32_t soA = sb + (uint32_t)row * ROWB + (uint32_t)cb;
    cp16(soA,      a,     okA);
    cp16(soA + 16, a + 8, okA);

    int gB = n0 + row;
    int okB = gB < Nmat;
    const __half* b = Bq + (size_t)(okB ? gB : 0) * KPAD + kb + ce;
    uint32_t soB = sb + TILE_PAD + (uint32_t)row * ROWB + (uint32_t)cb;
    cp16(soB,      b,     okB);
    cp16(soB + 16, b + 8, okB);
}

__global__ void __launch_bounds__(256, 2) gemm_mma3(
    const __half* __restrict__ Aq, const __half* __restrict__ Bq,
    const float* __restrict__ bias, float* __restrict__ C,
    int M, int Nmat, int nNt)
{
    extern __shared__ char smem[];
    uint32_t sbase = smem_u32(smem);
    int tid = threadIdx.x, lane = tid & 31, wid = tid >> 5;
    int wm = wid >> 2, wn = wid & 3;          // warp grid 2x4; warp tile 64x32
    int gID = lane >> 2, tg = lane & 3;
    int bid = blockIdx.x;
    int nt = bid % nNt, mt = bid / nNt;
    int m0 = mt * 128, n0 = nt * 128;
    const int nK = KPAD / 32;

    float acc[4][4][4];
#pragma unroll
    for (int i = 0; i < 4; i++)
#pragma unroll
        for (int j = 0; j < 4; j++)
#pragma unroll
            for (int q = 0; q < 4; q++) acc[i][j][q] = 0.f;

    ld_stage(sbase, Aq, Bq, m0, n0, M, Nmat, 0, tid);
    CP_COMMIT();

    uint32_t aOff[4], bOff[2];
#pragma unroll
    for (int mi = 0; mi < 4; mi++)
        aOff[mi] = (uint32_t)(wm * 64 + mi * 16 + (lane & 15)) * ROWB + (uint32_t)(lane >> 4) * 16;
#pragma unroll
    for (int pp = 0; pp < 2; pp++)
        bOff[pp] = (uint32_t)(wn * 32 + pp * 16 + ((lane >> 4) << 3) + (lane & 7)) * ROWB
                 + (uint32_t)(((lane >> 3) & 1) << 4);

    for (int kt = 0; kt < nK; kt++) {
        if (kt + 1 < nK)
            ld_stage(sbase + (uint32_t)((kt + 1) & 1) * STAGE_B,
                     Aq, Bq, m0, n0, M, Nmat, (kt + 1) * 32, tid);
        CP_COMMIT();
        CP_WAIT1();
        __syncthreads();

        uint32_t sb = sbase + (uint32_t)(kt & 1) * STAGE_B;
#pragma unroll
        for (int ks = 0; ks < 2; ks++) {
            uint32_t kb2 = (uint32_t)ks * 32;
            uint32_t bh[2][4];
#pragma unroll
            for (int pp = 0; pp < 2; pp++)
                ldsm_x4(bh[pp], sb + TILE_PAD + bOff[pp] + kb2);
#pragma unroll
            for (int mi = 0; mi < 4; mi++) {
                uint32_t ah[4];
                ldsm_x4(ah, sb + aOff[mi] + kb2);
#pragma unroll
                for (int ni = 0; ni < 4; ni++)
                    mma16816(acc[mi][ni], ah, &bh[ni >> 1][(ni & 1) * 2]);
            }
        }
        __syncthreads();
    }

#pragma unroll
    for (int mi = 0; mi < 4; mi++) {
        int r0 = m0 + wm * 64 + mi * 16 + gID;
        int r1 = r0 + 8;
#pragma unroll
        for (int ni = 0; ni < 4; ni++) {
            int cbase = n0 + wn * 32 + ni * 8 + tg * 2;
            if (cbase >= Nmat) continue;
            bool two = (cbase + 1 < Nmat);
            float bx = bias ? bias[cbase] : 0.f;
            float by = (bias && two) ? bias[cbase + 1] : 0.f;
            if (r0 < M) {
                float* p = C + (size_t)r0 * Nmat + cbase;
                if (two) { p[0] = acc[mi][ni][0] + bx; p[1] = acc[mi][ni][1] + by; }
                else p[0] = acc[mi][ni][0] + bx;
            }
            if (r1 < M) {
                float* p = C + (size_t)r1 * Nmat + cbase;
                if (two) { p[0] = acc[mi][ni][2] + bx; p[1] = acc[mi][ni][3] + by; }
                else p[0] = acc[mi][ni][2] + bx;
            }
        }
    }
}

// ---------------- zero scratch ----------------
__global__ void k_zero() {
    size_t i = (size_t)blockIdx.x * blockDim.x + threadIdx.x;
    if (i < (size_t)Nn * HIDF) g_h1[i] = 0.f;
    if (i < Nn * NH) {
        g_mkey1[i] = 0u; g_den1[i] = 0.f;
        g_mkey2[i] = 0u; g_den2[i] = 0.f;
    }
    if (i < INF_) { g_bnsum[i] = 0.f; g_bnsum2[i] = 0.f; }
    if (i < NDOMc * INF_) { g_dsum[i] = 0.f; g_dsum2[i] = 0.f; }
    if (i < NDOMc) g_cnt[i] = 0.f;
}

__global__ void k_zerof(float* __restrict__ p, size_t n) {
    size_t i = (size_t)blockIdx.x * blockDim.x + threadIdx.x;
    if (i < n) p[i] = 0.f;
}

__global__ void k_elu1(float* __restrict__ p, size_t n) {
    size_t i = (size_t)blockIdx.x * blockDim.x + threadIdx.x;
    if (i < n) p[i] = eluf(p[i]);
}

// ---------------- tiled SGEMM (GAT2 small GEMM) ----------------
#define BM 128
#define BN 128
#define BK 8
#define TM 8
#define TN 8
__global__ __launch_bounds__(256) void sgemm_k(
    const float* __restrict__ A, const float* __restrict__ B,
    const float* __restrict__ bias, float* __restrict__ C,
    int M, int Nc, int K)
{
    __shared__ float As[BK][BM];
    __shared__ float Bs[BK][BN];
    int tid = threadIdx.x;
    int m0 = blockIdx.y * BM;
    int n0 = blockIdx.x * BN;
    int tx = tid & 15, ty = tid >> 4;

    float acc[TM][TN];
    #pragma unroll
    for (int i = 0; i < TM; i++)
        #pragma unroll
        for (int j = 0; j < TN; j++) acc[i][j] = 0.f;

    int aRow = tid >> 1;
    int aCol = (tid & 1) * 4;
    int bRow = tid >> 5;
    int bCol = (tid & 31) * 4;

    int nK = K / BK;
    for (int kt = 0; kt < nK; kt++) {
        int kb = kt * BK;
        float4 av = make_float4(0.f, 0.f, 0.f, 0.f);
        if (m0 + aRow < M)
            av = *reinterpret_cast<const float4*>(A + (size_t)(m0 + aRow) * K + kb + aCol);
        As[aCol + 0][aRow] = av.x; As[aCol + 1][aRow] = av.y;
        As[aCol + 2][aRow] = av.z; As[aCol + 3][aRow] = av.w;

        const float* Bp = B + (size_t)(kb + bRow) * Nc + n0 + bCol;
        float4 bv;
        if (n0 + bCol + 3 < Nc && ((((size_t)Bp) & 15) == 0)) {
            bv = *reinterpret_cast<const float4*>(Bp);
        } else {
            bv.x = (n0 + bCol + 0 < Nc) ? Bp[0] : 0.f;
            bv.y = (n0 + bCol + 1 < Nc) ? Bp[1] : 0.f;
            bv.z = (n0 + bCol + 2 < Nc) ? Bp[2] : 0.f;
            bv.w = (n0 + bCol + 3 < Nc) ? Bp[3] : 0.f;
        }
        Bs[bRow][bCol + 0] = bv.x; Bs[bRow][bCol + 1] = bv.y;
        Bs[bRow][bCol + 2] = bv.z; Bs[bRow][bCol + 3] = bv.w;
        __syncthreads();

        #pragma unroll
        for (int k = 0; k < BK; k++) {
            float ar[TM], br[TN];
            #pragma unroll
            for (int i = 0; i < TM; i++) ar[i] = As[k][ty * TM + i];
            #pragma unroll
            for (int j = 0; j < TN; j++) br[j] = Bs[k][tx * TN + j];
            #pragma unroll
            for (int i = 0; i < TM; i++)
                #pragma unroll
                for (int j = 0; j < TN; j++) acc[i][j] += ar[i] * br[j];
        }
        __syncthreads();
    }

    #pragma unroll
    for (int i = 0; i < TM; i++) {
        int m = m0 + ty * TM + i;
        if (m >= M) continue;
        #pragma unroll
        for (int j = 0; j < TN; j++) {
            int n = n0 + tx * TN + j;
            if (n >= Nc) continue;
            float v = acc[i][j];
            if (bias) v += bias[n];
            C[(size_t)m * Nc + n] = v;
        }
    }
}

// ---------------- batch-norm column sums ----------------
__global__ void k_colsum(const float* __restrict__ X) {
    int j = blockIdx.x * blockDim.x + threadIdx.x;
    if (j >= INF_) return;
    int chunk = (Nn + gridDim.y - 1) / gridDim.y;
    int n0 = blockIdx.y * chunk;
    int n1 = min(n0 + chunk, Nn);
    float a = 0.f, b = 0.f;
    for (int n = n0; n < n1; n++) {
        float v = X[(size_t)n * INF_ + j];
        a += v; b += v * v;
    }
    atomicAdd(&g_bnsum[j], a);
    atomicAdd(&g_bnsum2[j], b);
}

// ---------------- attention logits: warp per (n, h) ----------------
__global__ void k_attn_logits(const float* __restrict__ Hh, const float* __restrict__ asrc,
                              const float* __restrict__ adst, float* als, float* ald, int F) {
    int w = (int)(((size_t)blockIdx.x * blockDim.x + threadIdx.x) >> 5);
    int lane = threadIdx.x & 31;
    if (w >= Nn * NH) return;
    int h = w % NH;
    const float* hp = Hh + (size_t)w * F;
    float s = 0.f, d = 0.f;
    for (int t = lane; t < F; t += 32) {
        float hv = hp[t];
        s += hv * asrc[h * F + t];
        d += hv * adst[h * F + t];
    }
    #pragma unroll
    for (int o = 16; o; o >>= 1) {
        s += __shfl_down_sync(0xffffffffu, s, o);
        d += __shfl_down_sync(0xffffffffu, d, o);
    }
    if (lane == 0) { als[w] = s; ald[w] = d; }
}

// ---------------- edge softmax ----------------
__global__ void k_edge_max(const int* __restrict__ src, const int* __restrict__ dst,
                           const float* __restrict__ als, const float* __restrict__ ald,
                           float* e, unsigned* mkey) {
    int i = blockIdx.x * blockDim.x + threadIdx.x;
    if (i >= Ee * NH) return;
    int ed = i / NH, h = i % NH;
    float v = als[src[ed] * NH + h] + ald[dst[ed] * NH + h];
    v = v > 0.f ? v : 0.2f * v;
    e[i] = v;
    atomicMax(&mkey[dst[ed] * NH + h], f2o(v));
}

__global__ void k_edge_exp(const int* __restrict__ dst, float* e,
                           const unsigned* __restrict__ mkey, float* den) {
    int i = blockIdx.x * blockDim.x + threadIdx.x;
    if (i >= Ee * NH) return;
    int ed = i / NH, h = i % NH;
    float m = o2f(mkey[dst[ed] * NH + h]);
    float ex = expf(e[i] - m);
    e[i] = ex;
    atomicAdd(&den[dst[ed] * NH + h], ex);
}

// ---------------- scatter with fused head-mean: warp per (edge, head) ----------------
// accumulates (alpha/NH) * H[s,h,:] directly into out[d, :]  (out = [N, HIDF])
__global__ void k_scatter_w(const int* __restrict__ src, const int* __restrict__ dst,
                            const float* __restrict__ Hh, const float* __restrict__ e,
                            const float* __restrict__ den, float* __restrict__ out) {
    int w = (int)(((size_t)blockIdx.x * blockDim.x + threadIdx.x) >> 5);
    int lane = threadIdx.x & 31;
    if (w >= Ee * NH) return;
    int ed = w / NH, h = w % NH;
    int s = src[ed], d = dst[ed];
    float a = e[ed * NH + h] / (den[d * NH + h] + 1e-16f) * (1.f / NH);
    const float4* Hs = reinterpret_cast<const float4*>(Hh + ((size_t)s * NH + h) * HIDF);
    float* od = out + (size_t)d * HIDF;
    const int f4 = HIDF / 4;   // 128
#pragma unroll
    for (int i = lane; i < f4; i += 32) {
        float4 v = Hs[i];
        int base = i * 4;
        atomicAdd(&od[base + 0], v.x * a);
        atomicAdd(&od[base + 1], v.y * a);
        atomicAdd(&od[base + 2], v.z * a);
        atomicAdd(&od[base + 3], v.w * a);
    }
}

// same, F=30, out = [N, OUTF] (written straight to z_out)
__global__ void k_scatter_w30(const int* __restrict__ src, const int* __restrict__ dst,
                              const float* __restrict__ Hh, const float* __restrict__ e,
                              const float* __restrict__ den, float* __restrict__ out) {
    int w = (int)(((size_t)blockIdx.x * blockDim.x + threadIdx.x) >> 5);
    int lane = threadIdx.x & 31;
    if (w >= Ee * NH) return;
    int ed = w / NH, h = w % NH;
    int s = src[ed], d = dst[ed];
    float a = e[ed * NH + h] / (den[d * NH + h] + 1e-16f) * (1.f / NH);
    const float* Hs = Hh + ((size_t)s * NH + h) * OUTF;
    float* od = out + (size_t)d * OUTF;
    if (lane < OUTF)
        atomicAdd(&od[lane], Hs[lane] * a);
}

// ---------------- MLP head ----------------
__global__ void k_mlp(const float* __restrict__ z, const float* __restrict__ w1,
                      const float* __restrict__ b1, const float* __restrict__ w2,
                      const float* __restrict__ b2, const int* __restrict__ flag,
                      float* yp) {
    int n = blockIdx.x;
    int t = threadIdx.x;
    __shared__ float zs[OUTF];
    __shared__ float hid[MHc];
    if (t < OUTF) zs[t] = z[(size_t)n * OUTF + t];
    __syncthreads();
    if (*flag == 0) {
        if (t < NLABc) yp[(size_t)n * NLABc + t] = 0.f;
        return;
    }
    float a = b1[t];
    #pragma unroll
    for (int k = 0; k < OUTF; k++) a += zs[k] * w1[k * MHc + t];
    hid[t] = fmaxf(a, 0.f);
    __syncthreads();
    if (t < NLABc) {
        float o = b2[t];
        #pragma unroll
        for (int k2 = 0; k2 < MHc; k2++) o += hid[k2] * w2[k2 * NLABc + t];
        yp[(size_t)n * NLABc + t] = o;
    }
}

// ---------------- fc2 (K=30, write-bound) — float4 over j ----------------
__global__ void k_fc2v(const float* __restrict__ z, const float* __restrict__ W,
                       const float* __restrict__ b, float* __restrict__ out) {
    size_t i4 = (size_t)blockIdx.x * blockDim.x + threadIdx.x;
    const int jq = INF_ / 4;   // 750
    if (i4 >= (size_t)Nn * jq) return;
    int n = (int)(i4 / jq), j4 = (int)(i4 % jq) * 4;
    float4 acc = *reinterpret_cast<const float4*>(b + j4);
    const float* zr = z + (size_t)n * OUTF;
    #pragma unroll
    for (int k = 0; k < OUTF; k++) {
        float zk = zr[k];
        float4 w = *reinterpret_cast<const float4*>(W + (size_t)k * INF_ + j4);
        acc.x += zk * w.x; acc.y += zk * w.y; acc.z += zk * w.z; acc.w += zk * w.w;
    }
    *reinterpret_cast<float4*>(out + (size_t)n * INF_ + j4) = acc;
}

// ---------------- DSBN ----------------
__global__ void k_cnt(const int* __restrict__ y) {
    int n = blockIdx.x * blockDim.x + threadIdx.x;
    if (n < Nn) atomicAdd(&g_cnt[y[n]], 1.f);
}

__global__ void k_dsbn_sum(const float* __restrict__ X, const int* __restrict__ y) {
    int j = blockIdx.x * blockDim.x + threadIdx.x;
    if (j >= INF_) return;
    int chunk = (Nn + gridDim.y - 1) / gridDim.y;
    int n0 = blockIdx.y * chunk;
    int n1 = min(n0 + chunk, Nn);
    float a[NDOMc], b[NDOMc];
    #pragma unroll
    for (int k = 0; k < NDOMc; k++) { a[k] = 0.f; b[k] = 0.f; }
    for (int n = n0; n < n1; n++) {
        int d = y[n];
        float v = X[(size_t)n * INF_ + j];
        #pragma unroll
        for (int k = 0; k < NDOMc; k++) {
            float m = (d == k) ? 1.f : 0.f;
            a[k] += m * v;
            b[k] += m * v * v;
        }
    }
    #pragma unroll
    for (int k = 0; k < NDOMc; k++) {
        atomicAdd(&g_dsum[k * INF_ + j], a[k]);
        atomicAdd(&g_dsum2[k * INF_ + j], b[k]);
    }
}

// ======================================================================
extern "C" void kernel_launch(void* const* d_in, const int* in_sizes, int n_in,
                              void* d_out, int out_size) {
    const float* features = (const float*)d_in[0];
    const int*   ei       = (const int*)d_in[1];
    const int*   y        = (const int*)d_in[2];
    const int*   flag     = (const int*)d_in[3];
    const float* fc1_w    = (const float*)d_in[4];
    const float* fc1_b    = (const float*)d_in[5];
    const float* bn_g     = (const float*)d_in[6];
    const float* bn_b     = (const float*)d_in[7];
    const float* W1       = (const float*)d_in[8];
    const float* a1_src   = (const float*)d_in[9];
    const float* a1_dst   = (const float*)d_in[10];
    const float* W2       = (const float*)d_in[11];
    const float* a2_src   = (const float*)d_in[12];
    const float* a2_dst   = (const float*)d_in[13];
    const float* mlp_w1   = (const float*)d_in[14];
    const float* mlp_b1   = (const float*)d_in[15];
    const float* mlp_w2   = (const float*)d_in[16];
    const float* mlp_b2   = (const float*)d_in[17];
    const float* fc2_w    = (const float*)d_in[18];
    const float* fc2_b    = (const float*)d_in[19];
    const float* dsbn_g   = (const float*)d_in[20];
    const float* dsbn_b   = (const float*)d_in[21];
    const float* fc3_w    = (const float*)d_in[22];
    const float* fc3_b    = (const float*)d_in[23];

    float* out    = (float*)d_out;
    float* z_out  = out;
    float* h3_out = out + (size_t)Nn * OUTF;
    float* yp_out = h3_out + (size_t)Nn * INF_;
    const int* srcp = ei;
    const int* dstp = ei + Ee;

    void* p;
    cudaGetSymbolAddress(&p, g_x);     float* px    = (float*)p;
    cudaGetSymbolAddress(&p, g_H);     float* pH    = (float*)p;
    cudaGetSymbolAddress(&p, g_h1);    float* ph1   = (float*)p;
    cudaGetSymbolAddress(&p, g_H2);    float* pH2   = (float*)p;
    cudaGetSymbolAddress(&p, g_als1);  float* pals1 = (float*)p;
    cudaGetSymbolAddress(&p, g_ald1);  float* pald1 = (float*)p;
    cudaGetSymbolAddress(&p, g_als2);  float* pals2 = (float*)p;
    cudaGetSymbolAddress(&p, g_ald2);  float* pald2 = (float*)p;
    cudaGetSymbolAddress(&p, g_e1);    float* pe1   = (float*)p;
    cudaGetSymbolAddress(&p, g_e2);    float* pe2   = (float*)p;
    cudaGetSymbolAddress(&p, g_mkey1); unsigned* pmk1 = (unsigned*)p;
    cudaGetSymbolAddress(&p, g_mkey2); unsigned* pmk2 = (unsigned*)p;
    cudaGetSymbolAddress(&p, g_den1);  float* pden1 = (float*)p;
    cudaGetSymbolAddress(&p, g_den2);  float* pden2 = (float*)p;
    cudaGetSymbolAddress(&p, g_Aq);    __half* pAq = (__half*)p;
    cudaGetSymbolAddress(&p, g_Wq);    __half* pWq = (__half*)p;

    static int smem_set = 0;
    if (!smem_set) {
        cudaFuncSetAttribute(gemm_mma3, cudaFuncAttributeMaxDynamicSharedMemorySize, GSMEM);
        smem_set = 1;
    }

    const int nMt = (Nn + 127) / 128;
    const size_t cvtGrid4 = ((size_t)Nn * (KPAD / 4) + 255) / 256;
    const int scW = (Ee * NH * 32 + 255) / 256;   // warp-per-(edge,head) grid

    // 0) zero scratch + z_out region
    {
        size_t tot = (size_t)Nn * HIDF;
        k_zero<<<(unsigned)((tot + 255) / 256), 256>>>();
        k_zerof<<<(Nn * OUTF + 255) / 256, 256>>>(z_out, (size_t)Nn * OUTF);
    }

    // 1) fc1
    {
        dim3 tg((KPAD + 31) / 32, (INF_ + 31) / 32);
        k_splitWT<<<tg, dim3(32, 32)>>>(fc1_w, pWq, INF_, INF_);
        k_cvtA4<<<(unsigned)cvtGrid4, 256>>>(features, pAq, Nn, INF_);
        int nNt = (INF_ + 127) / 128;
        gemm_mma3<<<nMt * nNt, 256, GSMEM>>>(pAq, pWq, fc1_b, px, Nn, INF_, nNt);
    }

    // 2) batchnorm stats + fused apply/ELU/convert
    {
        dim3 grid((INF_ + 255) / 256, 128);
        k_colsum<<<grid, 256>>>(px);
        k_bn_elu_cvt<<<(unsigned)cvtGrid4, 256>>>(px, bn_g, bn_b, pAq);
    }

    // 3) GAT layer 1
    {
        dim3 tg((KPAD + 31) / 32, (NH * HIDF + 31) / 32);
        k_splitWT<<<tg, dim3(32, 32)>>>(W1, pWq, INF_, NH * HIDF);
        int nNt = (NH * HIDF + 127) / 128;
        gemm_mma3<<<nMt * nNt, 256, GSMEM>>>(pAq, pWq, nullptr, pH, Nn, NH * HIDF, nNt);

        int warps = Nn * NH;
        k_attn_logits<<<(warps * 32 + 127) / 128, 128>>>(pH, a1_src, a1_dst, pals1, pald1, HIDF);

        int et = Ee * NH;
        k_edge_max<<<(et + 255) / 256, 256>>>(srcp, dstp, pals1, pald1, pe1, pmk1);
        k_edge_exp<<<(et + 255) / 256, 256>>>(dstp, pe1, pmk1, pden1);
        k_scatter_w<<<scW, 256>>>(srcp, dstp, pH, pe1, pden1, ph1);

        size_t tot = (size_t)Nn * HIDF;
        k_elu1<<<(unsigned)((tot + 255) / 256), 256>>>(ph1, tot);
    }

    // 4) GAT layer 2 -> z (scatter writes straight to z_out with fused mean)
    {
        dim3 grid((NH * OUTF + BN - 1) / BN, (Nn + BM - 1) / BM);
        sgemm_k<<<grid, 256>>>(ph1, W2, nullptr, pH2, Nn, NH * OUTF, HIDF);

        int warps = Nn * NH;
        k_attn_logits<<<(warps * 32 + 127) / 128, 128>>>(pH2, a2_src, a2_dst, pals2, pald2, OUTF);

        int et = Ee * NH;
        k_edge_max<<<(et + 255) / 256, 256>>>(srcp, dstp, pals2, pald2, pe2, pmk2);
        k_edge_exp<<<(et + 255) / 256, 256>>>(dstp, pe2, pmk2, pden2);
        k_scatter_w30<<<scW, 256>>>(srcp, dstp, pH2, pe2, pden2, z_out);
    }

    // 5) MLP head
    k_mlp<<<Nn, MHc>>>(z_out, mlp_w1, mlp_b1, mlp_w2, mlp_b2, flag, yp_out);

    // 6) fc2 -> DSBN stats -> fused apply/ELU/convert
    {
        size_t tot4 = (size_t)Nn * (INF_ / 4);
        k_fc2v<<<(unsigned)((tot4 + 255) / 256), 256>>>(z_out, fc2_w, fc2_b, px);
        k_cnt<<<(Nn + 255) / 256, 256>>>(y);
        dim3 grid((INF_ + 255) / 256, 128);
        k_dsbn_sum<<<grid, 256>>>(px, y);
        k_dsbn_elu_cvt<<<(unsigned)cvtGrid4, 256>>>(px, y, dsbn_g, dsbn_b, pAq);
    }

    // 7) fc3 -> h3
    {
        dim3 tg((KPAD + 31) / 32, (INF_ + 31) / 32);
        k_splitWT<<<tg, dim3(32, 32)>>>(fc3_w, pWq, INF_, INF_);
        int nNt = (INF_ + 127) / 128;
        gemm_mma3<<<nMt * nNt, 256, GSMEM>>>(pAq, pWq, fc3_b, h3_out, Nn, INF_, nNt);
    }
}

// round 14
// speedup vs baseline: 1.5760x; 1.0697x over previous
#include <cuda_runtime.h>
#include <cuda_bf16.h>
#include <cuda_fp16.h>
#include <math.h>
#include <stdint.h>

#define Nn    20000
#define Ee    120000
#define INF_  3000
#define HIDF  512
#define OUTF  30
#define NH    3
#define NDOMc 4
#define MHc   64
#define NLABc 20
#define EPSBN 1e-5f
#define KPAD  3008                 // 3000 padded to multiple of 32

// ---------------- scratch (static device memory; no allocations) ----------------
__device__ float    g_x[(size_t)Nn * INF_];
__device__ float    g_H[(size_t)Nn * NH * HIDF];
__device__ float    g_h1[(size_t)Nn * HIDF];
__device__ float    g_H2[(size_t)Nn * NH * OUTF];
__device__ float    g_als1[Nn * NH], g_ald1[Nn * NH];
__device__ float    g_als2[Nn * NH], g_ald2[Nn * NH];
__device__ float    g_e1[(size_t)Ee * NH];
__device__ float    g_e2[(size_t)Ee * NH];
__device__ unsigned g_mkey1[Nn * NH], g_mkey2[Nn * NH];
__device__ float    g_den1[Nn * NH], g_den2[Nn * NH];
__device__ float    g_bnsum[INF_], g_bnsum2[INF_];
__device__ float    g_dsum[NDOMc * INF_], g_dsum2[NDOMc * INF_];
__device__ float    g_cnt[NDOMc];
__device__ __align__(256) __half g_Aq[(size_t)Nn * KPAD];
__device__ __align__(256) __half g_Wq[(size_t)INF_ * KPAD];   // transposed weights [N, KPAD]

// ---------------- helpers ----------------
__device__ __forceinline__ unsigned f2o(float f) {
    unsigned u = __float_as_uint(f);
    return (u & 0x80000000u) ? ~u : (u | 0x80000000u);
}
__device__ __forceinline__ float o2f(unsigned k) {
    return (k & 0x80000000u) ? __uint_as_float(k ^ 0x80000000u) : __uint_as_float(~k);
}
__device__ __forceinline__ float eluf(float v) { return v > 0.f ? v : (expf(v) - 1.f); }

__device__ __forceinline__ uint32_t smem_u32(const void* p) {
    uint32_t a;
    asm("{ .reg .u64 t; cvta.to.shared.u64 t, %1; cvt.u32.u64 %0, t; }" : "=r"(a) : "l"(p));
    return a;
}

__device__ __forceinline__ void cp16(uint32_t dst, const void* src, int ok) {
    asm volatile("cp.async.cg.shared.global [%0], [%1], 16, %2;"
                 :: "r"(dst), "l"(src), "r"(ok ? 16 : 0) : "memory");
}
#define CP_COMMIT() asm volatile("cp.async.commit_group;" ::: "memory")
#define CP_WAIT1()  asm volatile("cp.async.wait_group 1;" ::: "memory")

__device__ __forceinline__ void mma16816(float* c, const uint32_t* a, const uint32_t* b) {
    asm volatile(
        "mma.sync.aligned.m16n8k16.row.col.f32.f16.f16.f32 "
        "{%0,%1,%2,%3},{%4,%5,%6,%7},{%8,%9},{%0,%1,%2,%3};"
        : "+f"(c[0]), "+f"(c[1]), "+f"(c[2]), "+f"(c[3])
        : "r"(a[0]), "r"(a[1]), "r"(a[2]), "r"(a[3]), "r"(b[0]), "r"(b[1]));
}
__device__ __forceinline__ void ldsm_x4(uint32_t* r, uint32_t addr) {
    asm volatile("ldmatrix.sync.aligned.m8n8.x4.shared.b16 {%0,%1,%2,%3}, [%4];"
                 : "=r"(r[0]), "=r"(r[1]), "=r"(r[2]), "=r"(r[3]) : "r"(addr));
}

// ---------------- fp16 convert helpers ----------------
__device__ __forceinline__ void cvt_store4(__half* dst, size_t o,
                                           float v0, float v1, float v2, float v3) {
    __half2 p0 = __halves2half2(__float2half_rn(v0), __float2half_rn(v1));
    __half2 p1 = __halves2half2(__float2half_rn(v2), __float2half_rn(v3));
    uint2 hv;
    hv.x = *(uint32_t*)&p0; hv.y = *(uint32_t*)&p1;
    *reinterpret_cast<uint2*>(dst + o) = hv;
}

__global__ void k_cvtA4(const float* __restrict__ X, __half* __restrict__ q, int M, int K) {
    size_t i4 = (size_t)blockIdx.x * blockDim.x + threadIdx.x;
    const int kq = KPAD / 4;
    if (i4 >= (size_t)M * kq) return;
    int m = (int)(i4 / kq), k4 = (int)(i4 % kq) * 4;
    const float* row = X + (size_t)m * K;
    float v0, v1, v2, v3;
    if (k4 + 3 < K) {
        float4 f = *reinterpret_cast<const float4*>(row + k4);
        v0 = f.x; v1 = f.y; v2 = f.z; v3 = f.w;
    } else {
        v0 = (k4 + 0 < K) ? row[k4 + 0] : 0.f;
        v1 = (k4 + 1 < K) ? row[k4 + 1] : 0.f;
        v2 = (k4 + 2 < K) ? row[k4 + 2] : 0.f;
        v3 = (k4 + 3 < K) ? row[k4 + 3] : 0.f;
    }
    cvt_store4(q, (size_t)m * KPAD + k4, v0, v1, v2, v3);
}

// Fused: BN apply + ELU + fp16 convert
__global__ void k_bn_elu_cvt(const float* __restrict__ X,
                             const float* __restrict__ g, const float* __restrict__ b,
                             __half* __restrict__ q) {
    size_t i4 = (size_t)blockIdx.x * blockDim.x + threadIdx.x;
    const int kq = KPAD / 4;
    if (i4 >= (size_t)Nn * kq) return;
    int m = (int)(i4 / kq), k4 = (int)(i4 % kq) * 4;
    float v[4];
    if (k4 + 3 < INF_) {
        float4 f = *reinterpret_cast<const float4*>(X + (size_t)m * INF_ + k4);
        v[0] = f.x; v[1] = f.y; v[2] = f.z; v[3] = f.w;
#pragma unroll
        for (int qq = 0; qq < 4; qq++) {
            int j = k4 + qq;
            float mu  = g_bnsum[j] * (1.f / Nn);
            float var = fmaxf(g_bnsum2[j] * (1.f / Nn) - mu * mu, 0.f);
            v[qq] = eluf((v[qq] - mu) * rsqrtf(var + EPSBN) * g[j] + b[j]);
        }
    } else {
#pragma unroll
        for (int qq = 0; qq < 4; qq++) {
            int j = k4 + qq;
            if (j < INF_) {
                float x = X[(size_t)m * INF_ + j];
                float mu  = g_bnsum[j] * (1.f / Nn);
                float var = fmaxf(g_bnsum2[j] * (1.f / Nn) - mu * mu, 0.f);
                v[qq] = eluf((x - mu) * rsqrtf(var + EPSBN) * g[j] + b[j]);
            } else v[qq] = 0.f;
        }
    }
    cvt_store4(q, (size_t)m * KPAD + k4, v[0], v[1], v[2], v[3]);
}

// Fused: DSBN apply + ELU + fp16 convert
__global__ void k_dsbn_elu_cvt(const float* __restrict__ X, const int* __restrict__ y,
                               const float* __restrict__ gmm, const float* __restrict__ bta,
                               __half* __restrict__ q) {
    size_t i4 = (size_t)blockIdx.x * blockDim.x + threadIdx.x;
    const int kq = KPAD / 4;
    if (i4 >= (size_t)Nn * kq) return;
    int m = (int)(i4 / kq), k4 = (int)(i4 % kq) * 4;
    int d = y[m];
    float c = g_cnt[d];
    bool norm = (c > 1.f);
    float inv = norm ? (1.f / c) : 0.f;
    float v[4];
#pragma unroll
    for (int qq = 0; qq < 4; qq++) {
        int j = k4 + qq;
        if (j < INF_) {
            float x = X[(size_t)m * INF_ + j];
            float o = x;
            if (norm) {
                float mu  = g_dsum[d * INF_ + j] * inv;
                float var = fmaxf(g_dsum2[d * INF_ + j] * inv - mu * mu, 0.f);
                o = (x - mu) * rsqrtf(var + EPSBN) * gmm[d * INF_ + j] + bta[d * INF_ + j];
            }
            v[qq] = eluf(o);
        } else v[qq] = 0.f;
    }
    cvt_store4(q, (size_t)m * KPAD + k4, v[0], v[1], v[2], v[3]);
}

// W[K, N] f32 -> WT fp16 [N, KPAD] (zero pad beyond K)
__global__ void k_splitWT(const float* __restrict__ W, __half* __restrict__ hi,
                          int K, int Nmat) {
    __shared__ float t[32][33];
    int kb = blockIdx.x * 32, nb = blockIdx.y * 32;
    int rk = kb + threadIdx.y, rn = nb + threadIdx.x;
    t[threadIdx.y][threadIdx.x] = (rk < K && rn < Nmat) ? W[(size_t)rk * Nmat + rn] : 0.f;
    __syncthreads();
    int wn = nb + threadIdx.y, wk = kb + threadIdx.x;
    if (wn < Nmat && wk < KPAD)
        hi[(size_t)wn * KPAD + wk] = __float2half_rn(t[threadIdx.x][threadIdx.y]);
}

// ------ mma.sync fp16 single-term GEMM: 256 thr, ldmatrix, 2-stage, 2 CTAs/SM ------
#define ROWB      80
#define TILE_PAD  (128 * ROWB)           // 10240 B
#define STAGE_B   (2 * TILE_PAD)         // 20480 B  (A, B)
#define GSMEM     (2 * STAGE_B)          // 40960 B

__device__ __forceinline__ void ld_stage(
    uint32_t sb,
    const __half* __restrict__ Aq, const __half* __restrict__ Bq,
    int m0, int n0, int M, int Nmat, int kb, int tid)
{
    int row = tid >> 1;
    int cb = (tid & 1) * 32;
    int ce = cb >> 1;

    int gA = m0 + row;
    int okA = gA < M;
    const __half* a = Aq + (size_t)(okA ? gA : 0) * KPAD + kb + ce;
    uint32_t soA = sb + (uint32_t)row * ROWB + (uint32_t)cb;
    cp16(soA,      a,     okA);
    cp16(soA + 16, a + 8, okA);

    int gB = n0 + row;
    int okB = gB < Nmat;
    const __half* b = Bq + (size_t)(okB ? gB : 0) * KPAD + kb + ce;
    uint32_t soB = sb + TILE_PAD + (uint32_t)row * ROWB + (uint32_t)cb;
    cp16(soB,      b,     okB);
    cp16(soB + 16, b + 8, okB);
}

__global__ void __launch_bounds__(256, 2) gemm_mma3(
    const __half* __restrict__ Aq, const __half* __restrict__ Bq,
    const float* __restrict__ bias, float* __restrict__ C,
    int M, int Nmat, int nNt)
{
    extern __shared__ char smem[];
    uint32_t sbase = smem_u32(smem);
    int tid = threadIdx.x, lane = tid & 31, wid = tid >> 5;
    int wm = wid >> 2, wn = wid & 3;          // warp grid 2x4; warp tile 64x32
    int gID = lane >> 2, tg = lane & 3;
    int bid = blockIdx.x;
    int nt = bid % nNt, mt = bid / nNt;
    int m0 = mt * 128, n0 = nt * 128;
    const int nK = KPAD / 32;

    float acc[4][4][4];
#pragma unroll
    for (int i = 0; i < 4; i++)
#pragma unroll
        for (int j = 0; j < 4; j++)
#pragma unroll
            for (int q = 0; q < 4; q++) acc[i][j][q] = 0.f;

    ld_stage(sbase, Aq, Bq, m0, n0, M, Nmat, 0, tid);
    CP_COMMIT();

    uint32_t aOff[4], bOff[2];
#pragma unroll
    for (int mi = 0; mi < 4; mi++)
        aOff[mi] = (uint32_t)(wm * 64 + mi * 16 + (lane & 15)) * ROWB + (uint32_t)(lane >> 4) * 16;
#pragma unroll
    for (int pp = 0; pp < 2; pp++)
        bOff[pp] = (uint32_t)(wn * 32 + pp * 16 + ((lane >> 4) << 3) + (lane & 7)) * ROWB
                 + (uint32_t)(((lane >> 3) & 1) << 4);

    for (int kt = 0; kt < nK; kt++) {
        if (kt + 1 < nK)
            ld_stage(sbase + (uint32_t)((kt + 1) & 1) * STAGE_B,
                     Aq, Bq, m0, n0, M, Nmat, (kt + 1) * 32, tid);
        CP_COMMIT();
        CP_WAIT1();
        __syncthreads();

        uint32_t sb = sbase + (uint32_t)(kt & 1) * STAGE_B;
#pragma unroll
        for (int ks = 0; ks < 2; ks++) {
            uint32_t kb2 = (uint32_t)ks * 32;
            uint32_t bh[2][4];
#pragma unroll
            for (int pp = 0; pp < 2; pp++)
                ldsm_x4(bh[pp], sb + TILE_PAD + bOff[pp] + kb2);
#pragma unroll
            for (int mi = 0; mi < 4; mi++) {
                uint32_t ah[4];
                ldsm_x4(ah, sb + aOff[mi] + kb2);
#pragma unroll
                for (int ni = 0; ni < 4; ni++)
                    mma16816(acc[mi][ni], ah, &bh[ni >> 1][(ni & 1) * 2]);
            }
        }
        __syncthreads();
    }

#pragma unroll
    for (int mi = 0; mi < 4; mi++) {
        int r0 = m0 + wm * 64 + mi * 16 + gID;
        int r1 = r0 + 8;
#pragma unroll
        for (int ni = 0; ni < 4; ni++) {
            int cbase = n0 + wn * 32 + ni * 8 + tg * 2;
            if (cbase >= Nmat) continue;
            bool two = (cbase + 1 < Nmat);
            float bx = bias ? bias[cbase] : 0.f;
            float by = (bias && two) ? bias[cbase + 1] : 0.f;
            if (r0 < M) {
                float* p = C + (size_t)r0 * Nmat + cbase;
                if (two) { p[0] = acc[mi][ni][0] + bx; p[1] = acc[mi][ni][1] + by; }
                else p[0] = acc[mi][ni][0] + bx;
            }
            if (r1 < M) {
                float* p = C + (size_t)r1 * Nmat + cbase;
                if (two) { p[0] = acc[mi][ni][2] + bx; p[1] = acc[mi][ni][3] + by; }
                else p[0] = acc[mi][ni][2] + bx;
            }
        }
    }
}

// ---------------- zero scratch ----------------
__global__ void k_zero() {
    size_t i = (size_t)blockIdx.x * blockDim.x + threadIdx.x;
    if (i < (size_t)Nn * HIDF) g_h1[i] = 0.f;
    if (i < Nn * NH) {
        g_mkey1[i] = 0u; g_den1[i] = 0.f;
        g_mkey2[i] = 0u; g_den2[i] = 0.f;
    }
    if (i < INF_) { g_bnsum[i] = 0.f; g_bnsum2[i] = 0.f; }
    if (i < NDOMc * INF_) { g_dsum[i] = 0.f; g_dsum2[i] = 0.f; }
    if (i < NDOMc) g_cnt[i] = 0.f;
}

__global__ void k_zerof(float* __restrict__ p, size_t n) {
    size_t i = (size_t)blockIdx.x * blockDim.x + threadIdx.x;
    if (i < n) p[i] = 0.f;
}

// ---------------- tiled SGEMM (GAT2 small GEMM), optional ELU on A loads ----------------
#define BM 128
#define BN 128
#define BK 8
#define TM 8
#define TN 8
__global__ __launch_bounds__(256) void sgemm_k(
    const float* __restrict__ A, const float* __restrict__ B,
    const float* __restrict__ bias, float* __restrict__ C,
    int M, int Nc, int K, int eluA)
{
    __shared__ float As[BK][BM];
    __shared__ float Bs[BK][BN];
    int tid = threadIdx.x;
    int m0 = blockIdx.y * BM;
    int n0 = blockIdx.x * BN;
    int tx = tid & 15, ty = tid >> 4;

    float acc[TM][TN];
    #pragma unroll
    for (int i = 0; i < TM; i++)
        #pragma unroll
        for (int j = 0; j < TN; j++) acc[i][j] = 0.f;

    int aRow = tid >> 1;
    int aCol = (tid & 1) * 4;
    int bRow = tid >> 5;
    int bCol = (tid & 31) * 4;

    int nK = K / BK;
    for (int kt = 0; kt < nK; kt++) {
        int kb = kt * BK;
        float4 av = make_float4(0.f, 0.f, 0.f, 0.f);
        if (m0 + aRow < M)
            av = *reinterpret_cast<const float4*>(A + (size_t)(m0 + aRow) * K + kb + aCol);
        if (eluA) { av.x = eluf(av.x); av.y = eluf(av.y); av.z = eluf(av.z); av.w = eluf(av.w); }
        As[aCol + 0][aRow] = av.x; As[aCol + 1][aRow] = av.y;
        As[aCol + 2][aRow] = av.z; As[aCol + 3][aRow] = av.w;

        const float* Bp = B + (size_t)(kb + bRow) * Nc + n0 + bCol;
        float4 bv;
        if (n0 + bCol + 3 < Nc && ((((size_t)Bp) & 15) == 0)) {
            bv = *reinterpret_cast<const float4*>(Bp);
        } else {
            bv.x = (n0 + bCol + 0 < Nc) ? Bp[0] : 0.f;
            bv.y = (n0 + bCol + 1 < Nc) ? Bp[1] : 0.f;
            bv.z = (n0 + bCol + 2 < Nc) ? Bp[2] : 0.f;
            bv.w = (n0 + bCol + 3 < Nc) ? Bp[3] : 0.f;
        }
        Bs[bRow][bCol + 0] = bv.x; Bs[bRow][bCol + 1] = bv.y;
        Bs[bRow][bCol + 2] = bv.z; Bs[bRow][bCol + 3] = bv.w;
        __syncthreads();

        #pragma unroll
        for (int k = 0; k < BK; k++) {
            float ar[TM], br[TN];
            #pragma unroll
            for (int i = 0; i < TM; i++) ar[i] = As[k][ty * TM + i];
            #pragma unroll
            for (int j = 0; j < TN; j++) br[j] = Bs[k][tx * TN + j];
            #pragma unroll
            for (int i = 0; i < TM; i++)
                #pragma unroll
                for (int j = 0; j < TN; j++) acc[i][j] += ar[i] * br[j];
        }
        __syncthreads();
    }

    #pragma unroll
    for (int i = 0; i < TM; i++) {
        int m = m0 + ty * TM + i;
        if (m >= M) continue;
        #pragma unroll
        for (int j = 0; j < TN; j++) {
            int n = n0 + tx * TN + j;
            if (n >= Nc) continue;
            float v = acc[i][j];
            if (bias) v += bias[n];
            C[(size_t)m * Nc + n] = v;
        }
    }
}

// ---------------- batch-norm column sums ----------------
__global__ void k_colsum(const float* __restrict__ X) {
    int j = blockIdx.x * blockDim.x + threadIdx.x;
    if (j >= INF_) return;
    int chunk = (Nn + gridDim.y - 1) / gridDim.y;
    int n0 = blockIdx.y * chunk;
    int n1 = min(n0 + chunk, Nn);
    float a = 0.f, b = 0.f;
    for (int n = n0; n < n1; n++) {
        float v = X[(size_t)n * INF_ + j];
        a += v; b += v * v;
    }
    atomicAdd(&g_bnsum[j], a);
    atomicAdd(&g_bnsum2[j], b);
}

// ---------------- attention logits: warp per (n, h) ----------------
__global__ void k_attn_logits(const float* __restrict__ Hh, const float* __restrict__ asrc,
                              const float* __restrict__ adst, float* als, float* ald, int F) {
    int w = (int)(((size_t)blockIdx.x * blockDim.x + threadIdx.x) >> 5);
    int lane = threadIdx.x & 31;
    if (w >= Nn * NH) return;
    int h = w % NH;
    const float* hp = Hh + (size_t)w * F;
    float s = 0.f, d = 0.f;
    for (int t = lane; t < F; t += 32) {
        float hv = hp[t];
        s += hv * asrc[h * F + t];
        d += hv * adst[h * F + t];
    }
    #pragma unroll
    for (int o = 16; o; o >>= 1) {
        s += __shfl_down_sync(0xffffffffu, s, o);
        d += __shfl_down_sync(0xffffffffu, d, o);
    }
    if (lane == 0) { als[w] = s; ald[w] = d; }
}

// ---------------- edge softmax ----------------
__global__ void k_edge_max(const int* __restrict__ src, const int* __restrict__ dst,
                           const float* __restrict__ als, const float* __restrict__ ald,
                           float* e, unsigned* mkey) {
    int i = blockIdx.x * blockDim.x + threadIdx.x;
    if (i >= Ee * NH) return;
    int ed = i / NH, h = i % NH;
    float v = als[src[ed] * NH + h] + ald[dst[ed] * NH + h];
    v = v > 0.f ? v : 0.2f * v;
    e[i] = v;
    atomicMax(&mkey[dst[ed] * NH + h], f2o(v));
}

__global__ void k_edge_exp(const int* __restrict__ dst, float* e,
                           const unsigned* __restrict__ mkey, float* den) {
    int i = blockIdx.x * blockDim.x + threadIdx.x;
    if (i >= Ee * NH) return;
    int ed = i / NH, h = i % NH;
    float m = o2f(mkey[dst[ed] * NH + h]);
    float ex = expf(e[i] - m);
    e[i] = ex;
    atomicAdd(&den[dst[ed] * NH + h], ex);
}

// ---------------- scatter, heads fused: warp per edge, 1 atomic per element ----------
// accumulates sum_h (alpha_h/NH) * H[s,h,:] into out[d, :]  (out = [N, HIDF])
__global__ void k_scatter_e(const int* __restrict__ src, const int* __restrict__ dst,
                            const float* __restrict__ Hh, const float* __restrict__ e,
                            const float* __restrict__ den, float* __restrict__ out) {
    int w = (int)(((size_t)blockIdx.x * blockDim.x + threadIdx.x) >> 5);
    int lane = threadIdx.x & 31;
    if (w >= Ee) return;
    int s = src[w], d = dst[w];
    float a0 = e[w * NH + 0] / (den[d * NH + 0] + 1e-16f) * (1.f / NH);
    float a1 = e[w * NH + 1] / (den[d * NH + 1] + 1e-16f) * (1.f / NH);
    float a2 = e[w * NH + 2] / (den[d * NH + 2] + 1e-16f) * (1.f / NH);
    const float4* H0 = reinterpret_cast<const float4*>(Hh + ((size_t)s * NH + 0) * HIDF);
    const float4* H1 = reinterpret_cast<const float4*>(Hh + ((size_t)s * NH + 1) * HIDF);
    const float4* H2 = reinterpret_cast<const float4*>(Hh + ((size_t)s * NH + 2) * HIDF);
    float* od = out + (size_t)d * HIDF;
    const int f4 = HIDF / 4;   // 128
#pragma unroll
    for (int i = lane; i < f4; i += 32) {
        float4 v0 = H0[i], v1 = H1[i], v2 = H2[i];
        int base = i * 4;
        atomicAdd(&od[base + 0], v0.x * a0 + v1.x * a1 + v2.x * a2);
        atomicAdd(&od[base + 1], v0.y * a0 + v1.y * a1 + v2.y * a2);
        atomicAdd(&od[base + 2], v0.z * a0 + v1.z * a1 + v2.z * a2);
        atomicAdd(&od[base + 3], v0.w * a0 + v1.w * a1 + v2.w * a2);
    }
}

// same, F=30, out = [N, OUTF] (written straight to z_out)
__global__ void k_scatter_e30(const int* __restrict__ src, const int* __restrict__ dst,
                              const float* __restrict__ Hh, const float* __restrict__ e,
                              const float* __restrict__ den, float* __restrict__ out) {
    int w = (int)(((size_t)blockIdx.x * blockDim.x + threadIdx.x) >> 5);
    int lane = threadIdx.x & 31;
    if (w >= Ee) return;
    int s = src[w], d = dst[w];
    float a0 = e[w * NH + 0] / (den[d * NH + 0] + 1e-16f) * (1.f / NH);
    float a1 = e[w * NH + 1] / (den[d * NH + 1] + 1e-16f) * (1.f / NH);
    float a2 = e[w * NH + 2] / (den[d * NH + 2] + 1e-16f) * (1.f / NH);
    const float* H0 = Hh + ((size_t)s * NH + 0) * OUTF;
    const float* H1 = Hh + ((size_t)s * NH + 1) * OUTF;
    const float* H2 = Hh + ((size_t)s * NH + 2) * OUTF;
    float* od = out + (size_t)d * OUTF;
    if (lane < OUTF)
        atomicAdd(&od[lane], H0[lane] * a0 + H1[lane] * a1 + H2[lane] * a2);
}

// ---------------- MLP head ----------------
__global__ void k_mlp(const float* __restrict__ z, const float* __restrict__ w1,
                      const float* __restrict__ b1, const float* __restrict__ w2,
                      const float* __restrict__ b2, const int* __restrict__ flag,
                      float* yp) {
    int n = blockIdx.x;
    int t = threadIdx.x;
    __shared__ float zs[OUTF];
    __shared__ float hid[MHc];
    if (t < OUTF) zs[t] = z[(size_t)n * OUTF + t];
    __syncthreads();
    if (*flag == 0) {
        if (t < NLABc) yp[(size_t)n * NLABc + t] = 0.f;
        return;
    }
    float a = b1[t];
    #pragma unroll
    for (int k = 0; k < OUTF; k++) a += zs[k] * w1[k * MHc + t];
    hid[t] = fmaxf(a, 0.f);
    __syncthreads();
    if (t < NLABc) {
        float o = b2[t];
        #pragma unroll
        for (int k2 = 0; k2 < MHc; k2++) o += hid[k2] * w2[k2 * NLABc + t];
        yp[(size_t)n * NLABc + t] = o;
    }
}

// ---------------- fc2 (K=30, write-bound) — float4 over j ----------------
__global__ void k_fc2v(const float* __restrict__ z, const float* __restrict__ W,
                       const float* __restrict__ b, float* __restrict__ out) {
    size_t i4 = (size_t)blockIdx.x * blockDim.x + threadIdx.x;
    const int jq = INF_ / 4;   // 750
    if (i4 >= (size_t)Nn * jq) return;
    int n = (int)(i4 / jq), j4 = (int)(i4 % jq) * 4;
    float4 acc = *reinterpret_cast<const float4*>(b + j4);
    const float* zr = z + (size_t)n * OUTF;
    #pragma unroll
    for (int k = 0; k < OUTF; k++) {
        float zk = zr[k];
        float4 w = *reinterpret_cast<const float4*>(W + (size_t)k * INF_ + j4);
        acc.x += zk * w.x; acc.y += zk * w.y; acc.z += zk * w.z; acc.w += zk * w.w;
    }
    *reinterpret_cast<float4*>(out + (size_t)n * INF_ + j4) = acc;
}

// ---------------- DSBN ----------------
__global__ void k_cnt(const int* __restrict__ y) {
    int n = blockIdx.x * blockDim.x + threadIdx.x;
    if (n < Nn) atomicAdd(&g_cnt[y[n]], 1.f);
}

__global__ void k_dsbn_sum(const float* __restrict__ X, const int* __restrict__ y) {
    int j = blockIdx.x * blockDim.x + threadIdx.x;
    if (j >= INF_) return;
    int chunk = (Nn + gridDim.y - 1) / gridDim.y;
    int n0 = blockIdx.y * chunk;
    int n1 = min(n0 + chunk, Nn);
    float a[NDOMc], b[NDOMc];
    #pragma unroll
    for (int k = 0; k < NDOMc; k++) { a[k] = 0.f; b[k] = 0.f; }
    for (int n = n0; n < n1; n++) {
        int d = y[n];
        float v = X[(size_t)n * INF_ + j];
        #pragma unroll
        for (int k = 0; k < NDOMc; k++) {
            float m = (d == k) ? 1.f : 0.f;
            a[k] += m * v;
            b[k] += m * v * v;
        }
    }
    #pragma unroll
    for (int k = 0; k < NDOMc; k++) {
        atomicAdd(&g_dsum[k * INF_ + j], a[k]);
        atomicAdd(&g_dsum2[k * INF_ + j], b[k]);
    }
}

// ======================================================================
extern "C" void kernel_launch(void* const* d_in, const int* in_sizes, int n_in,
                              void* d_out, int out_size) {
    const float* features = (const float*)d_in[0];
    const int*   ei       = (const int*)d_in[1];
    const int*   y        = (const int*)d_in[2];
    const int*   flag     = (const int*)d_in[3];
    const float* fc1_w    = (const float*)d_in[4];
    const float* fc1_b    = (const float*)d_in[5];
    const float* bn_g     = (const float*)d_in[6];
    const float* bn_b     = (const float*)d_in[7];
    const float* W1       = (const float*)d_in[8];
    const float* a1_src   = (const float*)d_in[9];
    const float* a1_dst   = (const float*)d_in[10];
    const float* W2       = (const float*)d_in[11];
    const float* a2_src   = (const float*)d_in[12];
    const float* a2_dst   = (const float*)d_in[13];
    const float* mlp_w1   = (const float*)d_in[14];
    const float* mlp_b1   = (const float*)d_in[15];
    const float* mlp_w2   = (const float*)d_in[16];
    const float* mlp_b2   = (const float*)d_in[17];
    const float* fc2_w    = (const float*)d_in[18];
    const float* fc2_b    = (const float*)d_in[19];
    const float* dsbn_g   = (const float*)d_in[20];
    const float* dsbn_b   = (const float*)d_in[21];
    const float* fc3_w    = (const float*)d_in[22];
    const float* fc3_b    = (const float*)d_in[23];

    float* out    = (float*)d_out;
    float* z_out  = out;
    float* h3_out = out + (size_t)Nn * OUTF;
    float* yp_out = h3_out + (size_t)Nn * INF_;
    const int* srcp = ei;
    const int* dstp = ei + Ee;

    void* p;
    cudaGetSymbolAddress(&p, g_x);     float* px    = (float*)p;
    cudaGetSymbolAddress(&p, g_H);     float* pH    = (float*)p;
    cudaGetSymbolAddress(&p, g_h1);    float* ph1   = (float*)p;
    cudaGetSymbolAddress(&p, g_H2);    float* pH2   = (float*)p;
    cudaGetSymbolAddress(&p, g_als1);  float* pals1 = (float*)p;
    cudaGetSymbolAddress(&p, g_ald1);  float* pald1 = (float*)p;
    cudaGetSymbolAddress(&p, g_als2);  float* pals2 = (float*)p;
    cudaGetSymbolAddress(&p, g_ald2);  float* pald2 = (float*)p;
    cudaGetSymbolAddress(&p, g_e1);    float* pe1   = (float*)p;
    cudaGetSymbolAddress(&p, g_e2);    float* pe2   = (float*)p;
    cudaGetSymbolAddress(&p, g_mkey1); unsigned* pmk1 = (unsigned*)p;
    cudaGetSymbolAddress(&p, g_mkey2); unsigned* pmk2 = (unsigned*)p;
    cudaGetSymbolAddress(&p, g_den1);  float* pden1 = (float*)p;
    cudaGetSymbolAddress(&p, g_den2);  float* pden2 = (float*)p;
    cudaGetSymbolAddress(&p, g_Aq);    __half* pAq = (__half*)p;
    cudaGetSymbolAddress(&p, g_Wq);    __half* pWq = (__half*)p;

    static int smem_set = 0;
    if (!smem_set) {
        cudaFuncSetAttribute(gemm_mma3, cudaFuncAttributeMaxDynamicSharedMemorySize, GSMEM);
        smem_set = 1;
    }

    const int nMt = (Nn + 127) / 128;
    const size_t cvtGrid4 = ((size_t)Nn * (KPAD / 4) + 255) / 256;
    const int scE = (Ee * 32 + 255) / 256;   // warp-per-edge grid

    // 0) zero scratch + z_out region
    {
        size_t tot = (size_t)Nn * HIDF;
        k_zero<<<(unsigned)((tot + 255) / 256), 256>>>();
        k_zerof<<<(Nn * OUTF + 255) / 256, 256>>>(z_out, (size_t)Nn * OUTF);
    }

    // 1) fc1
    {
        dim3 tg((KPAD + 31) / 32, (INF_ + 31) / 32);
        k_splitWT<<<tg, dim3(32, 32)>>>(fc1_w, pWq, INF_, INF_);
        k_cvtA4<<<(unsigned)cvtGrid4, 256>>>(features, pAq, Nn, INF_);
        int nNt = (INF_ + 127) / 128;
        gemm_mma3<<<nMt * nNt, 256, GSMEM>>>(pAq, pWq, fc1_b, px, Nn, INF_, nNt);
    }

    // 2) batchnorm stats + fused apply/ELU/convert
    {
        dim3 grid((INF_ + 255) / 256, 128);
        k_colsum<<<grid, 256>>>(px);
        k_bn_elu_cvt<<<(unsigned)cvtGrid4, 256>>>(px, bn_g, bn_b, pAq);
    }

    // 3) GAT layer 1
    {
        dim3 tg((KPAD + 31) / 32, (NH * HIDF + 31) / 32);
        k_splitWT<<<tg, dim3(32, 32)>>>(W1, pWq, INF_, NH * HIDF);
        int nNt = (NH * HIDF + 127) / 128;
        gemm_mma3<<<nMt * nNt, 256, GSMEM>>>(pAq, pWq, nullptr, pH, Nn, NH * HIDF, nNt);

        int warps = Nn * NH;
        k_attn_logits<<<(warps * 32 + 127) / 128, 128>>>(pH, a1_src, a1_dst, pals1, pald1, HIDF);

        int et = Ee * NH;
        k_edge_max<<<(et + 255) / 256, 256>>>(srcp, dstp, pals1, pald1, pe1, pmk1);
        k_edge_exp<<<(et + 255) / 256, 256>>>(dstp, pe1, pmk1, pden1);
        k_scatter_e<<<scE, 256>>>(srcp, dstp, pH, pe1, pden1, ph1);
        // h1 holds pre-ELU mean; ELU applied inside sgemm_k A-load (eluA=1)
    }

    // 4) GAT layer 2 -> z (scatter writes straight to z_out with fused mean)
    {
        dim3 grid((NH * OUTF + BN - 1) / BN, (Nn + BM - 1) / BM);
        sgemm_k<<<grid, 256>>>(ph1, W2, nullptr, pH2, Nn, NH * OUTF, HIDF, 1);

        int warps = Nn * NH;
        k_attn_logits<<<(warps * 32 + 127) / 128, 128>>>(pH2, a2_src, a2_dst, pals2, pald2, OUTF);

        int et = Ee * NH;
        k_edge_max<<<(et + 255) / 256, 256>>>(srcp, dstp, pals2, pald2, pe2, pmk2);
        k_edge_exp<<<(et + 255) / 256, 256>>>(dstp, pe2, pmk2, pden2);
        k_scatter_e30<<<scE, 256>>>(srcp, dstp, pH2, pe2, pden2, z_out);
    }

    // 5) MLP head
    k_mlp<<<Nn, MHc>>>(z_out, mlp_w1, mlp_b1, mlp_w2, mlp_b2, flag, yp_out);

    // 6) fc2 -> DSBN stats -> fused apply/ELU/convert
    {
        size_t tot4 = (size_t)Nn * (INF_ / 4);
        k_fc2v<<<(unsigned)((tot4 + 255) / 256), 256>>>(z_out, fc2_w, fc2_b, px);
        k_cnt<<<(Nn + 255) / 256, 256>>>(y);
        dim3 grid((INF_ + 255) / 256, 128);
        k_dsbn_sum<<<grid, 256>>>(px, y);
        k_dsbn_elu_cvt<<<(unsigned)cvtGrid4, 256>>>(px, y, dsbn_g, dsbn_b, pAq);
    }

    // 7) fc3 -> h3
    {
        dim3 tg((KPAD + 31) / 32, (INF_ + 31) / 32);
        k_splitWT<<<tg, dim3(32, 32)>>>(fc3_w, pWq, INF_, INF_);
        int nNt = (INF_ + 127) / 128;
        gemm_mma3<<<nMt * nNt, 256, GSMEM>>>(pAq, pWq, fc3_b, h3_out, Nn, INF_, nNt);
    }
}

// round 15
// speedup vs baseline: 1.5844x; 1.0053x over previous
#include <cuda_runtime.h>
#include <cuda_bf16.h>
#include <cuda_fp16.h>
#include <math.h>
#include <stdint.h>

#define Nn    20000
#define Ee    120000
#define INF_  3000
#define HIDF  512
#define OUTF  30
#define NH    3
#define NDOMc 4
#define MHc   64
#define NLABc 20
#define EPSBN 1e-5f
#define KPAD  3008                 // 3000 padded to multiple of 32

// ---------------- scratch (static device memory; no allocations) ----------------
__device__ float    g_x[(size_t)Nn * INF_];
__device__ float    g_H[(size_t)Nn * NH * HIDF];
__device__ float    g_h1[(size_t)Nn * HIDF];
__device__ float    g_H2[(size_t)Nn * NH * OUTF];
__device__ float    g_als1[Nn * NH], g_ald1[Nn * NH];
__device__ float    g_als2[Nn * NH], g_ald2[Nn * NH];
__device__ float    g_e1[(size_t)Ee * NH];
__device__ float    g_e2[(size_t)Ee * NH];
__device__ unsigned g_mkey1[Nn * NH], g_mkey2[Nn * NH];
__device__ float    g_den1[Nn * NH], g_den2[Nn * NH];
__device__ float    g_bnsum[INF_], g_bnsum2[INF_];
__device__ float    g_dsum[NDOMc * INF_], g_dsum2[NDOMc * INF_];
__device__ float    g_cnt[NDOMc];
__device__ int      g_roff[Nn + 1];
__device__ int      g_cur[Nn];
__device__ int      g_eidx[Ee];
__device__ __align__(256) __half g_Aq[(size_t)Nn * KPAD];
__device__ __align__(256) __half g_Wq[(size_t)INF_ * KPAD];

// ---------------- helpers ----------------
__device__ __forceinline__ unsigned f2o(float f) {
    unsigned u = __float_as_uint(f);
    return (u & 0x80000000u) ? ~u : (u | 0x80000000u);
}
__device__ __forceinline__ float o2f(unsigned k) {
    return (k & 0x80000000u) ? __uint_as_float(k ^ 0x80000000u) : __uint_as_float(~k);
}
__device__ __forceinline__ float eluf(float v) { return v > 0.f ? v : (expf(v) - 1.f); }

__device__ __forceinline__ uint32_t smem_u32(const void* p) {
    uint32_t a;
    asm("{ .reg .u64 t; cvta.to.shared.u64 t, %1; cvt.u32.u64 %0, t; }" : "=r"(a) : "l"(p));
    return a;
}

__device__ __forceinline__ void cp16(uint32_t dst, const void* src, int ok) {
    asm volatile("cp.async.cg.shared.global [%0], [%1], 16, %2;"
                 :: "r"(dst), "l"(src), "r"(ok ? 16 : 0) : "memory");
}
#define CP_COMMIT() asm volatile("cp.async.commit_group;" ::: "memory")
#define CP_WAIT1()  asm volatile("cp.async.wait_group 1;" ::: "memory")

__device__ __forceinline__ void mma16816(float* c, const uint32_t* a, const uint32_t* b) {
    asm volatile(
        "mma.sync.aligned.m16n8k16.row.col.f32.f16.f16.f32 "
        "{%0,%1,%2,%3},{%4,%5,%6,%7},{%8,%9},{%0,%1,%2,%3};"
        : "+f"(c[0]), "+f"(c[1]), "+f"(c[2]), "+f"(c[3])
        : "r"(a[0]), "r"(a[1]), "r"(a[2]), "r"(a[3]), "r"(b[0]), "r"(b[1]));
}
__device__ __forceinline__ void ldsm_x4(uint32_t* r, uint32_t addr) {
    asm volatile("ldmatrix.sync.aligned.m8n8.x4.shared.b16 {%0,%1,%2,%3}, [%4];"
                 : "=r"(r[0]), "=r"(r[1]), "=r"(r[2]), "=r"(r[3]) : "r"(addr));
}

// ---------------- fp16 convert helpers ----------------
__device__ __forceinline__ void cvt_store4(__half* dst, size_t o,
                                           float v0, float v1, float v2, float v3) {
    __half2 p0 = __halves2half2(__float2half_rn(v0), __float2half_rn(v1));
    __half2 p1 = __halves2half2(__float2half_rn(v2), __float2half_rn(v3));
    uint2 hv;
    hv.x = *(uint32_t*)&p0; hv.y = *(uint32_t*)&p1;
    *reinterpret_cast<uint2*>(dst + o) = hv;
}

__global__ void k_cvtA4(const float* __restrict__ X, __half* __restrict__ q, int M, int K) {
    size_t i4 = (size_t)blockIdx.x * blockDim.x + threadIdx.x;
    const int kq = KPAD / 4;
    if (i4 >= (size_t)M * kq) return;
    int m = (int)(i4 / kq), k4 = (int)(i4 % kq) * 4;
    const float* row = X + (size_t)m * K;
    float v0, v1, v2, v3;
    if (k4 + 3 < K) {
        float4 f = *reinterpret_cast<const float4*>(row + k4);
        v0 = f.x; v1 = f.y; v2 = f.z; v3 = f.w;
    } else {
        v0 = (k4 + 0 < K) ? row[k4 + 0] : 0.f;
        v1 = (k4 + 1 < K) ? row[k4 + 1] : 0.f;
        v2 = (k4 + 2 < K) ? row[k4 + 2] : 0.f;
        v3 = (k4 + 3 < K) ? row[k4 + 3] : 0.f;
    }
    cvt_store4(q, (size_t)m * KPAD + k4, v0, v1, v2, v3);
}

// Fused: BN apply + ELU + fp16 convert
__global__ void k_bn_elu_cvt(const float* __restrict__ X,
                             const float* __restrict__ g, const float* __restrict__ b,
                             __half* __restrict__ q) {
    size_t i4 = (size_t)blockIdx.x * blockDim.x + threadIdx.x;
    const int kq = KPAD / 4;
    if (i4 >= (size_t)Nn * kq) return;
    int m = (int)(i4 / kq), k4 = (int)(i4 % kq) * 4;
    float v[4];
    if (k4 + 3 < INF_) {
        float4 f = *reinterpret_cast<const float4*>(X + (size_t)m * INF_ + k4);
        v[0] = f.x; v[1] = f.y; v[2] = f.z; v[3] = f.w;
#pragma unroll
        for (int qq = 0; qq < 4; qq++) {
            int j = k4 + qq;
            float mu  = g_bnsum[j] * (1.f / Nn);
            float var = fmaxf(g_bnsum2[j] * (1.f / Nn) - mu * mu, 0.f);
            v[qq] = eluf((v[qq] - mu) * rsqrtf(var + EPSBN) * g[j] + b[j]);
        }
    } else {
#pragma unroll
        for (int qq = 0; qq < 4; qq++) {
            int j = k4 + qq;
            if (j < INF_) {
                float x = X[(size_t)m * INF_ + j];
                float mu  = g_bnsum[j] * (1.f / Nn);
                float var = fmaxf(g_bnsum2[j] * (1.f / Nn) - mu * mu, 0.f);
                v[qq] = eluf((x - mu) * rsqrtf(var + EPSBN) * g[j] + b[j]);
            } else v[qq] = 0.f;
        }
    }
    cvt_store4(q, (size_t)m * KPAD + k4, v[0], v[1], v[2], v[3]);
}

// Fused: DSBN apply + ELU + fp16 convert
__global__ void k_dsbn_elu_cvt(const float* __restrict__ X, const int* __restrict__ y,
                               const float* __restrict__ gmm, const float* __restrict__ bta,
                               __half* __restrict__ q) {
    size_t i4 = (size_t)blockIdx.x * blockDim.x + threadIdx.x;
    const int kq = KPAD / 4;
    if (i4 >= (size_t)Nn * kq) return;
    int m = (int)(i4 / kq), k4 = (int)(i4 % kq) * 4;
    int d = y[m];
    float c = g_cnt[d];
    bool norm = (c > 1.f);
    float inv = norm ? (1.f / c) : 0.f;
    float v[4];
#pragma unroll
    for (int qq = 0; qq < 4; qq++) {
        int j = k4 + qq;
        if (j < INF_) {
            float x = X[(size_t)m * INF_ + j];
            float o = x;
            if (norm) {
                float mu  = g_dsum[d * INF_ + j] * inv;
                float var = fmaxf(g_dsum2[d * INF_ + j] * inv - mu * mu, 0.f);
                o = (x - mu) * rsqrtf(var + EPSBN) * gmm[d * INF_ + j] + bta[d * INF_ + j];
            }
            v[qq] = eluf(o);
        } else v[qq] = 0.f;
    }
    cvt_store4(q, (size_t)m * KPAD + k4, v[0], v[1], v[2], v[3]);
}

// W[K, N] f32 -> WT fp16 [N, KPAD] (zero pad beyond K)
__global__ void k_splitWT(const float* __restrict__ W, __half* __restrict__ hi,
                          int K, int Nmat) {
    __shared__ float t[32][33];
    int kb = blockIdx.x * 32, nb = blockIdx.y * 32;
    int rk = kb + threadIdx.y, rn = nb + threadIdx.x;
    t[threadIdx.y][threadIdx.x] = (rk < K && rn < Nmat) ? W[(size_t)rk * Nmat + rn] : 0.f;
    __syncthreads();
    int wn = nb + threadIdx.y, wk = kb + threadIdx.x;
    if (wn < Nmat && wk < KPAD)
        hi[(size_t)wn * KPAD + wk] = __float2half_rn(t[threadIdx.x][threadIdx.y]);
}

// ------ mma.sync fp16 single-term GEMM: 256 thr, ldmatrix, 2-stage, 2 CTAs/SM ------
#define ROWB      80
#define TILE_PAD  (128 * ROWB)           // 10240 B
#define STAGE_B   (2 * TILE_PAD)         // 20480 B
#define GSMEM     (2 * STAGE_B)          // 40960 B

__device__ __forceinline__ void ld_stage(
    uint32_t sb,
    const __half* __restrict__ Aq, const __half* __restrict__ Bq,
    int m0, int n0, int M, int Nmat, int kb, int tid)
{
    int row = tid >> 1;
    int cb = (tid & 1) * 32;
    int ce = cb >> 1;

    int gA = m0 + row;
    int okA = gA < M;
    const __half* a = Aq + (size_t)(okA ? gA : 0) * KPAD + kb + ce;
    uint32_t soA = sb + (uint32_t)row * ROWB + (uint32_t)cb;
    cp16(soA,      a,     okA);
    cp16(soA + 16, a + 8, okA);

    int gB = n0 + row;
    int okB = gB < Nmat;
    const __half* b = Bq + (size_t)(okB ? gB : 0) * KPAD + kb + ce;
    uint32_t soB = sb + TILE_PAD + (uint32_t)row * ROWB + (uint32_t)cb;
    cp16(soB,      b,     okB);
    cp16(soB + 16, b + 8, okB);
}

__global__ void __launch_bounds__(256, 2) gemm_mma3(
    const __half* __restrict__ Aq, const __half* __restrict__ Bq,
    const float* __restrict__ bias, float* __restrict__ C,
    int M, int Nmat, int nNt)
{
    extern __shared__ char smem[];
    uint32_t sbase = smem_u32(smem);
    int tid = threadIdx.x, lane = tid & 31, wid = tid >> 5;
    int wm = wid >> 2, wn = wid & 3;
    int gID = lane >> 2, tg = lane & 3;
    int bid = blockIdx.x;
    int nt = bid % nNt, mt = bid / nNt;
    int m0 = mt * 128, n0 = nt * 128;
    const int nK = KPAD / 32;

    float acc[4][4][4];
#pragma unroll
    for (int i = 0; i < 4; i++)
#pragma unroll
        for (int j = 0; j < 4; j++)
#pragma unroll
            for (int q = 0; q < 4; q++) acc[i][j][q] = 0.f;

    ld_stage(sbase, Aq, Bq, m0, n0, M, Nmat, 0, tid);
    CP_COMMIT();

    uint32_t aOff[4], bOff[2];
#pragma unroll
    for (int mi = 0; mi < 4; mi++)
        aOff[mi] = (uint32_t)(wm * 64 + mi * 16 + (lane & 15)) * ROWB + (uint32_t)(lane >> 4) * 16;
#pragma unroll
    for (int pp = 0; pp < 2; pp++)
        bOff[pp] = (uint32_t)(wn * 32 + pp * 16 + ((lane >> 4) << 3) + (lane & 7)) * ROWB
                 + (uint32_t)(((lane >> 3) & 1) << 4);

    for (int kt = 0; kt < nK; kt++) {
        if (kt + 1 < nK)
            ld_stage(sbase + (uint32_t)((kt + 1) & 1) * STAGE_B,
                     Aq, Bq, m0, n0, M, Nmat, (kt + 1) * 32, tid);
        CP_COMMIT();
        CP_WAIT1();
        __syncthreads();

        uint32_t sb = sbase + (uint32_t)(kt & 1) * STAGE_B;
#pragma unroll
        for (int ks = 0; ks < 2; ks++) {
            uint32_t kb2 = (uint32_t)ks * 32;
            uint32_t bh[2][4];
#pragma unroll
            for (int pp = 0; pp < 2; pp++)
                ldsm_x4(bh[pp], sb + TILE_PAD + bOff[pp] + kb2);
#pragma unroll
            for (int mi = 0; mi < 4; mi++) {
                uint32_t ah[4];
                ldsm_x4(ah, sb + aOff[mi] + kb2);
#pragma unroll
                for (int ni = 0; ni < 4; ni++)
                    mma16816(acc[mi][ni], ah, &bh[ni >> 1][(ni & 1) * 2]);
            }
        }
        __syncthreads();
    }

#pragma unroll
    for (int mi = 0; mi < 4; mi++) {
        int r0 = m0 + wm * 64 + mi * 16 + gID;
        int r1 = r0 + 8;
#pragma unroll
        for (int ni = 0; ni < 4; ni++) {
            int cbase = n0 + wn * 32 + ni * 8 + tg * 2;
            if (cbase >= Nmat) continue;
            bool two = (cbase + 1 < Nmat);
            float bx = bias ? bias[cbase] : 0.f;
            float by = (bias && two) ? bias[cbase + 1] : 0.f;
            if (r0 < M) {
                float* p = C + (size_t)r0 * Nmat + cbase;
                if (two) { p[0] = acc[mi][ni][0] + bx; p[1] = acc[mi][ni][1] + by; }
                else p[0] = acc[mi][ni][0] + bx;
            }
            if (r1 < M) {
                float* p = C + (size_t)r1 * Nmat + cbase;
                if (two) { p[0] = acc[mi][ni][2] + bx; p[1] = acc[mi][ni][3] + by; }
                else p[0] = acc[mi][ni][2] + bx;
            }
        }
    }
}

// ---------------- zero scratch ----------------
__global__ void k_zero() {
    size_t i = (size_t)blockIdx.x * blockDim.x + threadIdx.x;
    if (i < Nn * NH) {
        g_mkey1[i] = 0u; g_den1[i] = 0.f;
        g_mkey2[i] = 0u; g_den2[i] = 0.f;
    }
    if (i < Nn) g_cur[i] = 0;          // reused as degree counter
    if (i < INF_) { g_bnsum[i] = 0.f; g_bnsum2[i] = 0.f; }
    if (i < NDOMc * INF_) { g_dsum[i] = 0.f; g_dsum2[i] = 0.f; }
    if (i < NDOMc) g_cnt[i] = 0.f;
}

// ---------------- CSR build ----------------
__global__ void k_deg(const int* __restrict__ dst) {
    int e = blockIdx.x * blockDim.x + threadIdx.x;
    if (e < Ee) atomicAdd(&g_cur[dst[e]], 1);
}

__global__ void k_scan() {   // single block, 1024 threads
    __shared__ int sh[1024];
    __shared__ int carryS;
    int tid = threadIdx.x;
    if (tid == 0) { carryS = 0; g_roff[0] = 0; }
    __syncthreads();
    for (int base = 0; base < Nn; base += 1024) {
        int v = (base + tid < Nn) ? g_cur[base + tid] : 0;
        sh[tid] = v;
        __syncthreads();
        for (int o = 1; o < 1024; o <<= 1) {
            int t = (tid >= o) ? sh[tid - o] : 0;
            __syncthreads();
            sh[tid] += t;
            __syncthreads();
        }
        if (base + tid < Nn) g_roff[base + tid + 1] = carryS + sh[tid];
        __syncthreads();
        if (tid == 0) carryS += sh[1023];
        __syncthreads();
    }
    // reset cursors to row starts
    for (int i = tid; i < Nn; i += 1024) g_cur[i] = g_roff[i];
}

__global__ void k_fill(const int* __restrict__ dst) {
    int e = blockIdx.x * blockDim.x + threadIdx.x;
    if (e < Ee) {
        int pos = atomicAdd(&g_cur[dst[e]], 1);
        g_eidx[pos] = e;
    }
}

// ---------------- tiled SGEMM (GAT2 small GEMM), optional ELU on A loads ----------------
#define BM 128
#define BN 128
#define BK 8
#define TM 8
#define TN 8
__global__ __launch_bounds__(256) void sgemm_k(
    const float* __restrict__ A, const float* __restrict__ B,
    const float* __restrict__ bias, float* __restrict__ C,
    int M, int Nc, int K, int eluA)
{
    __shared__ float As[BK][BM];
    __shared__ float Bs[BK][BN];
    int tid = threadIdx.x;
    int m0 = blockIdx.y * BM;
    int n0 = blockIdx.x * BN;
    int tx = tid & 15, ty = tid >> 4;

    float acc[TM][TN];
    #pragma unroll
    for (int i = 0; i < TM; i++)
        #pragma unroll
        for (int j = 0; j < TN; j++) acc[i][j] = 0.f;

    int aRow = tid >> 1;
    int aCol = (tid & 1) * 4;
    int bRow = tid >> 5;
    int bCol = (tid & 31) * 4;

    int nK = K / BK;
    for (int kt = 0; kt < nK; kt++) {
        int kb = kt * BK;
        float4 av = make_float4(0.f, 0.f, 0.f, 0.f);
        if (m0 + aRow < M)
            av = *reinterpret_cast<const float4*>(A + (size_t)(m0 + aRow) * K + kb + aCol);
        if (eluA) { av.x = eluf(av.x); av.y = eluf(av.y); av.z = eluf(av.z); av.w = eluf(av.w); }
        As[aCol + 0][aRow] = av.x; As[aCol + 1][aRow] = av.y;
        As[aCol + 2][aRow] = av.z; As[aCol + 3][aRow] = av.w;

        const float* Bp = B + (size_t)(kb + bRow) * Nc + n0 + bCol;
        float4 bv;
        if (n0 + bCol + 3 < Nc && ((((size_t)Bp) & 15) == 0)) {
            bv = *reinterpret_cast<const float4*>(Bp);
        } else {
            bv.x = (n0 + bCol + 0 < Nc) ? Bp[0] : 0.f;
            bv.y = (n0 + bCol + 1 < Nc) ? Bp[1] : 0.f;
            bv.z = (n0 + bCol + 2 < Nc) ? Bp[2] : 0.f;
            bv.w = (n0 + bCol + 3 < Nc) ? Bp[3] : 0.f;
        }
        Bs[bRow][bCol + 0] = bv.x; Bs[bRow][bCol + 1] = bv.y;
        Bs[bRow][bCol + 2] = bv.z; Bs[bRow][bCol + 3] = bv.w;
        __syncthreads();

        #pragma unroll
        for (int k = 0; k < BK; k++) {
            float ar[TM], br[TN];
            #pragma unroll
            for (int i = 0; i < TM; i++) ar[i] = As[k][ty * TM + i];
            #pragma unroll
            for (int j = 0; j < TN; j++) br[j] = Bs[k][tx * TN + j];
            #pragma unroll
            for (int i = 0; i < TM; i++)
                #pragma unroll
                for (int j = 0; j < TN; j++) acc[i][j] += ar[i] * br[j];
        }
        __syncthreads();
    }

    #pragma unroll
    for (int i = 0; i < TM; i++) {
        int m = m0 + ty * TM + i;
        if (m >= M) continue;
        #pragma unroll
        for (int j = 0; j < TN; j++) {
            int n = n0 + tx * TN + j;
            if (n >= Nc) continue;
            float v = acc[i][j];
            if (bias) v += bias[n];
            C[(size_t)m * Nc + n] = v;
        }
    }
}

// ---------------- batch-norm column sums ----------------
__global__ void k_colsum(const float* __restrict__ X) {
    int j = blockIdx.x * blockDim.x + threadIdx.x;
    if (j >= INF_) return;
    int chunk = (Nn + gridDim.y - 1) / gridDim.y;
    int n0 = blockIdx.y * chunk;
    int n1 = min(n0 + chunk, Nn);
    float a = 0.f, b = 0.f;
    for (int n = n0; n < n1; n++) {
        float v = X[(size_t)n * INF_ + j];
        a += v; b += v * v;
    }
    atomicAdd(&g_bnsum[j], a);
    atomicAdd(&g_bnsum2[j], b);
}

// ---------------- attention logits: warp per (n, h) ----------------
__global__ void k_attn_logits(const float* __restrict__ Hh, const float* __restrict__ asrc,
                              const float* __restrict__ adst, float* als, float* ald, int F) {
    int w = (int)(((size_t)blockIdx.x * blockDim.x + threadIdx.x) >> 5);
    int lane = threadIdx.x & 31;
    if (w >= Nn * NH) return;
    int h = w % NH;
    const float* hp = Hh + (size_t)w * F;
    float s = 0.f, d = 0.f;
    for (int t = lane; t < F; t += 32) {
        float hv = hp[t];
        s += hv * asrc[h * F + t];
        d += hv * adst[h * F + t];
    }
    #pragma unroll
    for (int o = 16; o; o >>= 1) {
        s += __shfl_down_sync(0xffffffffu, s, o);
        d += __shfl_down_sync(0xffffffffu, d, o);
    }
    if (lane == 0) { als[w] = s; ald[w] = d; }
}

// ---------------- edge softmax ----------------
__global__ void k_edge_max(const int* __restrict__ src, const int* __restrict__ dst,
                           const float* __restrict__ als, const float* __restrict__ ald,
                           float* e, unsigned* mkey) {
    int i = blockIdx.x * blockDim.x + threadIdx.x;
    if (i >= Ee * NH) return;
    int ed = i / NH, h = i % NH;
    float v = als[src[ed] * NH + h] + ald[dst[ed] * NH + h];
    v = v > 0.f ? v : 0.2f * v;
    e[i] = v;
    atomicMax(&mkey[dst[ed] * NH + h], f2o(v));
}

__global__ void k_edge_exp(const int* __restrict__ dst, float* e,
                           const unsigned* __restrict__ mkey, float* den) {
    int i = blockIdx.x * blockDim.x + threadIdx.x;
    if (i >= Ee * NH) return;
    int ed = i / NH, h = i % NH;
    float m = o2f(mkey[dst[ed] * NH + h]);
    float ex = expf(e[i] - m);
    e[i] = ex;
    atomicAdd(&den[dst[ed] * NH + h], ex);
}

// ---------------- CSR gather aggregation: warp per destination node -----------
// h1[d, f] = sum_{e in in(d)} sum_h (alpha_eh/NH) * H[src(e), h, f]   (no atomics)
__global__ void k_gather512(const int* __restrict__ src,
                            const float* __restrict__ e1, const float* __restrict__ den,
                            const float* __restrict__ Hh, float* __restrict__ out) {
    int d = (int)(((size_t)blockIdx.x * blockDim.x + threadIdx.x) >> 5);
    int lane = threadIdx.x & 31;
    if (d >= Nn) return;
    int beg = g_roff[d], end = g_roff[d + 1];
    float i0 = (1.f / NH) / (den[d * NH + 0] + 1e-16f);
    float i1 = (1.f / NH) / (den[d * NH + 1] + 1e-16f);
    float i2 = (1.f / NH) / (den[d * NH + 2] + 1e-16f);
    float acc[16];
#pragma unroll
    for (int i = 0; i < 16; i++) acc[i] = 0.f;
    for (int p = beg; p < end; p++) {
        int e = g_eidx[p];
        int s = src[e];
        float a0 = e1[e * NH + 0] * i0;
        float a1 = e1[e * NH + 1] * i1;
        float a2 = e1[e * NH + 2] * i2;
        const float* H0 = Hh + ((size_t)s * NH + 0) * HIDF + lane;
        const float* H1 = Hh + ((size_t)s * NH + 1) * HIDF + lane;
        const float* H2 = Hh + ((size_t)s * NH + 2) * HIDF + lane;
#pragma unroll
        for (int i = 0; i < 16; i++) {
            int f = i * 32;
            acc[i] += H0[f] * a0 + H1[f] * a1 + H2[f] * a2;
        }
    }
    float* od = out + (size_t)d * HIDF + lane;
#pragma unroll
    for (int i = 0; i < 16; i++) od[i * 32] = acc[i];
}

// same, F=30, writes straight to z_out (covers all nodes incl. degree-0)
__global__ void k_gather30(const int* __restrict__ src,
                           const float* __restrict__ e2, const float* __restrict__ den,
                           const float* __restrict__ Hh, float* __restrict__ out) {
    int d = (int)(((size_t)blockIdx.x * blockDim.x + threadIdx.x) >> 5);
    int lane = threadIdx.x & 31;
    if (d >= Nn) return;
    int beg = g_roff[d], end = g_roff[d + 1];
    float i0 = (1.f / NH) / (den[d * NH + 0] + 1e-16f);
    float i1 = (1.f / NH) / (den[d * NH + 1] + 1e-16f);
    float i2 = (1.f / NH) / (den[d * NH + 2] + 1e-16f);
    float acc = 0.f;
    for (int p = beg; p < end; p++) {
        int e = g_eidx[p];
        int s = src[e];
        float a0 = e2[e * NH + 0] * i0;
        float a1 = e2[e * NH + 1] * i1;
        float a2 = e2[e * NH + 2] * i2;
        if (lane < OUTF) {
            acc += Hh[((size_t)s * NH + 0) * OUTF + lane] * a0
                 + Hh[((size_t)s * NH + 1) * OUTF + lane] * a1
                 + Hh[((size_t)s * NH + 2) * OUTF + lane] * a2;
        }
    }
    if (lane < OUTF) out[(size_t)d * OUTF + lane] = acc;
}

// ---------------- MLP head ----------------
__global__ void k_mlp(const float* __restrict__ z, const float* __restrict__ w1,
                      const float* __restrict__ b1, const float* __restrict__ w2,
                      const float* __restrict__ b2, const int* __restrict__ flag,
                      float* yp) {
    int n = blockIdx.x;
    int t = threadIdx.x;
    __shared__ float zs[OUTF];
    __shared__ float hid[MHc];
    if (t < OUTF) zs[t] = z[(size_t)n * OUTF + t];
    __syncthreads();
    if (*flag == 0) {
        if (t < NLABc) yp[(size_t)n * NLABc + t] = 0.f;
        return;
    }
    float a = b1[t];
    #pragma unroll
    for (int k = 0; k < OUTF; k++) a += zs[k] * w1[k * MHc + t];
    hid[t] = fmaxf(a, 0.f);
    __syncthreads();
    if (t < NLABc) {
        float o = b2[t];
        #pragma unroll
        for (int k2 = 0; k2 < MHc; k2++) o += hid[k2] * w2[k2 * NLABc + t];
        yp[(size_t)n * NLABc + t] = o;
    }
}

// ---------------- fc2 (K=30, write-bound) — float4 over j ----------------
__global__ void k_fc2v(const float* __restrict__ z, const float* __restrict__ W,
                       const float* __restrict__ b, float* __restrict__ out) {
    size_t i4 = (size_t)blockIdx.x * blockDim.x + threadIdx.x;
    const int jq = INF_ / 4;
    if (i4 >= (size_t)Nn * jq) return;
    int n = (int)(i4 / jq), j4 = (int)(i4 % jq) * 4;
    float4 acc = *reinterpret_cast<const float4*>(b + j4);
    const float* zr = z + (size_t)n * OUTF;
    #pragma unroll
    for (int k = 0; k < OUTF; k++) {
        float zk = zr[k];
        float4 w = *reinterpret_cast<const float4*>(W + (size_t)k * INF_ + j4);
        acc.x += zk * w.x; acc.y += zk * w.y; acc.z += zk * w.z; acc.w += zk * w.w;
    }
    *reinterpret_cast<float4*>(out + (size_t)n * INF_ + j4) = acc;
}

// ---------------- DSBN ----------------
__global__ void k_cnt(const int* __restrict__ y) {
    int n = blockIdx.x * blockDim.x + threadIdx.x;
    if (n < Nn) atomicAdd(&g_cnt[y[n]], 1.f);
}

__global__ void k_dsbn_sum(const float* __restrict__ X, const int* __restrict__ y) {
    int j = blockIdx.x * blockDim.x + threadIdx.x;
    if (j >= INF_) return;
    int chunk = (Nn + gridDim.y - 1) / gridDim.y;
    int n0 = blockIdx.y * chunk;
    int n1 = min(n0 + chunk, Nn);
    float a[NDOMc], b[NDOMc];
    #pragma unroll
    for (int k = 0; k < NDOMc; k++) { a[k] = 0.f; b[k] = 0.f; }
    for (int n = n0; n < n1; n++) {
        int d = y[n];
        float v = X[(size_t)n * INF_ + j];
        #pragma unroll
        for (int k = 0; k < NDOMc; k++) {
            float m = (d == k) ? 1.f : 0.f;
            a[k] += m * v;
            b[k] += m * v * v;
        }
    }
    #pragma unroll
    for (int k = 0; k < NDOMc; k++) {
        atomicAdd(&g_dsum[k * INF_ + j], a[k]);
        atomicAdd(&g_dsum2[k * INF_ + j], b[k]);
    }
}

// ======================================================================
extern "C" void kernel_launch(void* const* d_in, const int* in_sizes, int n_in,
                              void* d_out, int out_size) {
    const float* features = (const float*)d_in[0];
    const int*   ei       = (const int*)d_in[1];
    const int*   y        = (const int*)d_in[2];
    const int*   flag     = (const int*)d_in[3];
    const float* fc1_w    = (const float*)d_in[4];
    const float* fc1_b    = (const float*)d_in[5];
    const float* bn_g     = (const float*)d_in[6];
    const float* bn_b     = (const float*)d_in[7];
    const float* W1       = (const float*)d_in[8];
    const float* a1_src   = (const float*)d_in[9];
    const float* a1_dst   = (const float*)d_in[10];
    const float* W2       = (const float*)d_in[11];
    const float* a2_src   = (const float*)d_in[12];
    const float* a2_dst   = (const float*)d_in[13];
    const float* mlp_w1   = (const float*)d_in[14];
    const float* mlp_b1   = (const float*)d_in[15];
    const float* mlp_w2   = (const float*)d_in[16];
    const float* mlp_b2   = (const float*)d_in[17];
    const float* fc2_w    = (const float*)d_in[18];
    const float* fc2_b    = (const float*)d_in[19];
    const float* dsbn_g   = (const float*)d_in[20];
    const float* dsbn_b   = (const float*)d_in[21];
    const float* fc3_w    = (const float*)d_in[22];
    const float* fc3_b    = (const float*)d_in[23];

    float* out    = (float*)d_out;
    float* z_out  = out;
    float* h3_out = out + (size_t)Nn * OUTF;
    float* yp_out = h3_out + (size_t)Nn * INF_;
    const int* srcp = ei;
    const int* dstp = ei + Ee;

    void* p;
    cudaGetSymbolAddress(&p, g_x);     float* px    = (float*)p;
    cudaGetSymbolAddress(&p, g_H);     float* pH    = (float*)p;
    cudaGetSymbolAddress(&p, g_h1);    float* ph1   = (float*)p;
    cudaGetSymbolAddress(&p, g_H2);    float* pH2   = (float*)p;
    cudaGetSymbolAddress(&p, g_als1);  float* pals1 = (float*)p;
    cudaGetSymbolAddress(&p, g_ald1);  float* pald1 = (float*)p;
    cudaGetSymbolAddress(&p, g_als2);  float* pals2 = (float*)p;
    cudaGetSymbolAddress(&p, g_ald2);  float* pald2 = (float*)p;
    cudaGetSymbolAddress(&p, g_e1);    float* pe1   = (float*)p;
    cudaGetSymbolAddress(&p, g_e2);    float* pe2   = (float*)p;
    cudaGetSymbolAddress(&p, g_mkey1); unsigned* pmk1 = (unsigned*)p;
    cudaGetSymbolAddress(&p, g_mkey2); unsigned* pmk2 = (unsigned*)p;
    cudaGetSymbolAddress(&p, g_den1);  float* pden1 = (float*)p;
    cudaGetSymbolAddress(&p, g_den2);  float* pden2 = (float*)p;
    cudaGetSymbolAddress(&p, g_Aq);    __half* pAq = (__half*)p;
    cudaGetSymbolAddress(&p, g_Wq);    __half* pWq = (__half*)p;

    static int smem_set = 0;
    if (!smem_set) {
        cudaFuncSetAttribute(gemm_mma3, cudaFuncAttributeMaxDynamicSharedMemorySize, GSMEM);
        smem_set = 1;
    }

    const int nMt = (Nn + 127) / 128;
    const size_t cvtGrid4 = ((size_t)Nn * (KPAD / 4) + 255) / 256;
    const int gaW = (Nn * 32 + 255) / 256;   // warp-per-node grid

    // 0) zero scratch + CSR build (depends only on edge_index)
    {
        size_t tot = (size_t)NDOMc * INF_;
        size_t mx = tot > (size_t)Nn * NH ? tot : (size_t)Nn * NH;
        if ((size_t)Nn > mx) mx = Nn;
        k_zero<<<(unsigned)((mx + 255) / 256), 256>>>();
        k_deg<<<(Ee + 255) / 256, 256>>>(dstp);
        k_scan<<<1, 1024>>>();
        k_fill<<<(Ee + 255) / 256, 256>>>(dstp);
    }

    // 1) fc1
    {
        dim3 tg((KPAD + 31) / 32, (INF_ + 31) / 32);
        k_splitWT<<<tg, dim3(32, 32)>>>(fc1_w, pWq, INF_, INF_);
        k_cvtA4<<<(unsigned)cvtGrid4, 256>>>(features, pAq, Nn, INF_);
        int nNt = (INF_ + 127) / 128;
        gemm_mma3<<<nMt * nNt, 256, GSMEM>>>(pAq, pWq, fc1_b, px, Nn, INF_, nNt);
    }

    // 2) batchnorm stats + fused apply/ELU/convert
    {
        dim3 grid((INF_ + 255) / 256, 128);
        k_colsum<<<grid, 256>>>(px);
        k_bn_elu_cvt<<<(unsigned)cvtGrid4, 256>>>(px, bn_g, bn_b, pAq);
    }

    // 3) GAT layer 1
    {
        dim3 tg((KPAD + 31) / 32, (NH * HIDF + 31) / 32);
        k_splitWT<<<tg, dim3(32, 32)>>>(W1, pWq, INF_, NH * HIDF);
        int nNt = (NH * HIDF + 127) / 128;
        gemm_mma3<<<nMt * nNt, 256, GSMEM>>>(pAq, pWq, nullptr, pH, Nn, NH * HIDF, nNt);

        int warps = Nn * NH;
        k_attn_logits<<<(warps * 32 + 127) / 128, 128>>>(pH, a1_src, a1_dst, pals1, pald1, HIDF);

        int et = Ee * NH;
        k_edge_max<<<(et + 255) / 256, 256>>>(srcp, dstp, pals1, pald1, pe1, pmk1);
        k_edge_exp<<<(et + 255) / 256, 256>>>(dstp, pe1, pmk1, pden1);
        k_gather512<<<gaW, 256>>>(srcp, pe1, pden1, pH, ph1);
        // h1 holds pre-ELU mean; ELU fused into sgemm_k A-load
    }

    // 4) GAT layer 2 -> z (gather writes straight to z_out with fused mean)
    {
        dim3 grid((NH * OUTF + BN - 1) / BN, (Nn + BM - 1) / BM);
        sgemm_k<<<grid, 256>>>(ph1, W2, nullptr, pH2, Nn, NH * OUTF, HIDF, 1);

        int warps = Nn * NH;
        k_attn_logits<<<(warps * 32 + 127) / 128, 128>>>(pH2, a2_src, a2_dst, pals2, pald2, OUTF);

        int et = Ee * NH;
        k_edge_max<<<(et + 255) / 256, 256>>>(srcp, dstp, pals2, pald2, pe2, pmk2);
        k_edge_exp<<<(et + 255) / 256, 256>>>(dstp, pe2, pmk2, pden2);
        k_gather30<<<gaW, 256>>>(srcp, pe2, pden2, pH2, z_out);
    }

    // 5) MLP head
    k_mlp<<<Nn, MHc>>>(z_out, mlp_w1, mlp_b1, mlp_w2, mlp_b2, flag, yp_out);

    // 6) fc2 -> DSBN stats -> fused apply/ELU/convert
    {
        size_t tot4 = (size_t)Nn * (INF_ / 4);
        k_fc2v<<<(unsigned)((tot4 + 255) / 256), 256>>>(z_out, fc2_w, fc2_b, px);
        k_cnt<<<(Nn + 255) / 256, 256>>>(y);
        dim3 grid((INF_ + 255) / 256, 128);
        k_dsbn_sum<<<grid, 256>>>(px, y);
        k_dsbn_elu_cvt<<<(unsigned)cvtGrid4, 256>>>(px, y, dsbn_g, dsbn_b, pAq);
    }

    // 7) fc3 -> h3
    {
        dim3 tg((KPAD + 31) / 32, (INF_ + 31) / 32);
        k_splitWT<<<tg, dim3(32, 32)>>>(fc3_w, pWq, INF_, INF_);
        int nNt = (INF_ + 127) / 128;
        gemm_mma3<<<nMt * nNt, 256, GSMEM>>>(pAq, pWq, fc3_b, h3_out, Nn, INF_, nNt);
    }
}

// round 16
// speedup vs baseline: 1.6205x; 1.0228x over previous
#include <cuda_runtime.h>
#include <cuda_bf16.h>
#include <cuda_fp16.h>
#include <math.h>
#include <stdint.h>

#define Nn    20000
#define Ee    120000
#define INF_  3000
#define HIDF  512
#define OUTF  30
#define NH    3
#define NDOMc 4
#define MHc   64
#define NLABc 20
#define EPSBN 1e-5f
#define KPAD  3008                 // 3000 padded to multiple of 32

// ---------------- scratch (static device memory; no allocations) ----------------
__device__ float    g_x[(size_t)Nn * INF_];
__device__ __align__(256) __half g_Hh[(size_t)Nn * NH * HIDF];   // GAT1 features, fp16
__device__ float    g_h1[(size_t)Nn * HIDF];
__device__ float    g_H2[(size_t)Nn * NH * OUTF];
__device__ float    g_als1[Nn * NH], g_ald1[Nn * NH];
__device__ float    g_als2[Nn * NH], g_ald2[Nn * NH];
__device__ float    g_e1[(size_t)Ee * NH];
__device__ float    g_e2[(size_t)Ee * NH];
__device__ unsigned g_mkey1[Nn * NH], g_mkey2[Nn * NH];
__device__ float    g_den1[Nn * NH], g_den2[Nn * NH];
__device__ float    g_bnsum[INF_], g_bnsum2[INF_];
__device__ float    g_dsum[NDOMc * INF_], g_dsum2[NDOMc * INF_];
__device__ float    g_cnt[NDOMc];
__device__ int      g_roff[Nn + 1];
__device__ int      g_cur[Nn];
__device__ int      g_eidx[Ee];
__device__ __align__(256) __half g_Aq[(size_t)Nn * KPAD];
__device__ __align__(256) __half g_Wq[(size_t)INF_ * KPAD];

// ---------------- helpers ----------------
__device__ __forceinline__ unsigned f2o(float f) {
    unsigned u = __float_as_uint(f);
    return (u & 0x80000000u) ? ~u : (u | 0x80000000u);
}
__device__ __forceinline__ float o2f(unsigned k) {
    return (k & 0x80000000u) ? __uint_as_float(k ^ 0x80000000u) : __uint_as_float(~k);
}
__device__ __forceinline__ float eluf(float v) { return v > 0.f ? v : (expf(v) - 1.f); }

__device__ __forceinline__ uint32_t smem_u32(const void* p) {
    uint32_t a;
    asm("{ .reg .u64 t; cvta.to.shared.u64 t, %1; cvt.u32.u64 %0, t; }" : "=r"(a) : "l"(p));
    return a;
}

__device__ __forceinline__ void cp16(uint32_t dst, const void* src, int ok) {
    asm volatile("cp.async.cg.shared.global [%0], [%1], 16, %2;"
                 :: "r"(dst), "l"(src), "r"(ok ? 16 : 0) : "memory");
}
#define CP_COMMIT() asm volatile("cp.async.commit_group;" ::: "memory")
#define CP_WAIT1()  asm volatile("cp.async.wait_group 1;" ::: "memory")

__device__ __forceinline__ void mma16816(float* c, const uint32_t* a, const uint32_t* b) {
    asm volatile(
        "mma.sync.aligned.m16n8k16.row.col.f32.f16.f16.f32 "
        "{%0,%1,%2,%3},{%4,%5,%6,%7},{%8,%9},{%0,%1,%2,%3};"
        : "+f"(c[0]), "+f"(c[1]), "+f"(c[2]), "+f"(c[3])
        : "r"(a[0]), "r"(a[1]), "r"(a[2]), "r"(a[3]), "r"(b[0]), "r"(b[1]));
}
__device__ __forceinline__ void ldsm_x4(uint32_t* r, uint32_t addr) {
    asm volatile("ldmatrix.sync.aligned.m8n8.x4.shared.b16 {%0,%1,%2,%3}, [%4];"
                 : "=r"(r[0]), "=r"(r[1]), "=r"(r[2]), "=r"(r[3]) : "r"(addr));
}

// ---------------- fp16 convert helpers ----------------
__device__ __forceinline__ void cvt_store4(__half* dst, size_t o,
                                           float v0, float v1, float v2, float v3) {
    __half2 p0 = __halves2half2(__float2half_rn(v0), __float2half_rn(v1));
    __half2 p1 = __halves2half2(__float2half_rn(v2), __float2half_rn(v3));
    uint2 hv;
    hv.x = *(uint32_t*)&p0; hv.y = *(uint32_t*)&p1;
    *reinterpret_cast<uint2*>(dst + o) = hv;
}

__global__ void k_cvtA4(const float* __restrict__ X, __half* __restrict__ q, int M, int K) {
    size_t i4 = (size_t)blockIdx.x * blockDim.x + threadIdx.x;
    const int kq = KPAD / 4;
    if (i4 >= (size_t)M * kq) return;
    int m = (int)(i4 / kq), k4 = (int)(i4 % kq) * 4;
    const float* row = X + (size_t)m * K;
    float v0, v1, v2, v3;
    if (k4 + 3 < K) {
        float4 f = *reinterpret_cast<const float4*>(row + k4);
        v0 = f.x; v1 = f.y; v2 = f.z; v3 = f.w;
    } else {
        v0 = (k4 + 0 < K) ? row[k4 + 0] : 0.f;
        v1 = (k4 + 1 < K) ? row[k4 + 1] : 0.f;
        v2 = (k4 + 2 < K) ? row[k4 + 2] : 0.f;
        v3 = (k4 + 3 < K) ? row[k4 + 3] : 0.f;
    }
    cvt_store4(q, (size_t)m * KPAD + k4, v0, v1, v2, v3);
}

// Fused: BN apply + ELU + fp16 convert
__global__ void k_bn_elu_cvt(const float* __restrict__ X,
                             const float* __restrict__ g, const float* __restrict__ b,
                             __half* __restrict__ q) {
    size_t i4 = (size_t)blockIdx.x * blockDim.x + threadIdx.x;
    const int kq = KPAD / 4;
    if (i4 >= (size_t)Nn * kq) return;
    int m = (int)(i4 / kq), k4 = (int)(i4 % kq) * 4;
    float v[4];
    if (k4 + 3 < INF_) {
        float4 f = *reinterpret_cast<const float4*>(X + (size_t)m * INF_ + k4);
        v[0] = f.x; v[1] = f.y; v[2] = f.z; v[3] = f.w;
#pragma unroll
        for (int qq = 0; qq < 4; qq++) {
            int j = k4 + qq;
            float mu  = g_bnsum[j] * (1.f / Nn);
            float var = fmaxf(g_bnsum2[j] * (1.f / Nn) - mu * mu, 0.f);
            v[qq] = eluf((v[qq] - mu) * rsqrtf(var + EPSBN) * g[j] + b[j]);
        }
    } else {
#pragma unroll
        for (int qq = 0; qq < 4; qq++) {
            int j = k4 + qq;
            if (j < INF_) {
                float x = X[(size_t)m * INF_ + j];
                float mu  = g_bnsum[j] * (1.f / Nn);
                float var = fmaxf(g_bnsum2[j] * (1.f / Nn) - mu * mu, 0.f);
                v[qq] = eluf((x - mu) * rsqrtf(var + EPSBN) * g[j] + b[j]);
            } else v[qq] = 0.f;
        }
    }
    cvt_store4(q, (size_t)m * KPAD + k4, v[0], v[1], v[2], v[3]);
}

// Fused: DSBN apply + ELU + fp16 convert
__global__ void k_dsbn_elu_cvt(const float* __restrict__ X, const int* __restrict__ y,
                               const float* __restrict__ gmm, const float* __restrict__ bta,
                               __half* __restrict__ q) {
    size_t i4 = (size_t)blockIdx.x * blockDim.x + threadIdx.x;
    const int kq = KPAD / 4;
    if (i4 >= (size_t)Nn * kq) return;
    int m = (int)(i4 / kq), k4 = (int)(i4 % kq) * 4;
    int d = y[m];
    float c = g_cnt[d];
    bool norm = (c > 1.f);
    float inv = norm ? (1.f / c) : 0.f;
    float v[4];
#pragma unroll
    for (int qq = 0; qq < 4; qq++) {
        int j = k4 + qq;
        if (j < INF_) {
            float x = X[(size_t)m * INF_ + j];
            float o = x;
            if (norm) {
                float mu  = g_dsum[d * INF_ + j] * inv;
                float var = fmaxf(g_dsum2[d * INF_ + j] * inv - mu * mu, 0.f);
                o = (x - mu) * rsqrtf(var + EPSBN) * gmm[d * INF_ + j] + bta[d * INF_ + j];
            }
            v[qq] = eluf(o);
        } else v[qq] = 0.f;
    }
    cvt_store4(q, (size_t)m * KPAD + k4, v[0], v[1], v[2], v[3]);
}

// W[K, N] f32 -> WT fp16 [N, KPAD] (zero pad beyond K)
__global__ void k_splitWT(const float* __restrict__ W, __half* __restrict__ hi,
                          int K, int Nmat) {
    __shared__ float t[32][33];
    int kb = blockIdx.x * 32, nb = blockIdx.y * 32;
    int rk = kb + threadIdx.y, rn = nb + threadIdx.x;
    t[threadIdx.y][threadIdx.x] = (rk < K && rn < Nmat) ? W[(size_t)rk * Nmat + rn] : 0.f;
    __syncthreads();
    int wn = nb + threadIdx.y, wk = kb + threadIdx.x;
    if (wn < Nmat && wk < KPAD)
        hi[(size_t)wn * KPAD + wk] = __float2half_rn(t[threadIdx.x][threadIdx.y]);
}

// ------ mma.sync fp16 single-term GEMM: 256 thr, ldmatrix, 2-stage, 2 CTAs/SM ------
// Output: either fp32 C (+bias) or fp16 Ch (no bias).
#define ROWB      80
#define TILE_PAD  (128 * ROWB)
#define STAGE_B   (2 * TILE_PAD)
#define GSMEM     (2 * STAGE_B)

__device__ __forceinline__ void ld_stage(
    uint32_t sb,
    const __half* __restrict__ Aq, const __half* __restrict__ Bq,
    int m0, int n0, int M, int Nmat, int kb, int tid)
{
    int row = tid >> 1;
    int cb = (tid & 1) * 32;
    int ce = cb >> 1;

    int gA = m0 + row;
    int okA = gA < M;
    const __half* a = Aq + (size_t)(okA ? gA : 0) * KPAD + kb + ce;
    uint32_t soA = sb + (uint32_t)row * ROWB + (uint32_t)cb;
    cp16(soA,      a,     okA);
    cp16(soA + 16, a + 8, okA);

    int gB = n0 + row;
    int okB = gB < Nmat;
    const __half* b = Bq + (size_t)(okB ? gB : 0) * KPAD + kb + ce;
    uint32_t soB = sb + TILE_PAD + (uint32_t)row * ROWB + (uint32_t)cb;
    cp16(soB,      b,     okB);
    cp16(soB + 16, b + 8, okB);
}

__global__ void __launch_bounds__(256, 2) gemm_mma3(
    const __half* __restrict__ Aq, const __half* __restrict__ Bq,
    const float* __restrict__ bias, float* __restrict__ C,
    __half* __restrict__ Ch,
    int M, int Nmat, int nNt)
{
    extern __shared__ char smem[];
    uint32_t sbase = smem_u32(smem);
    int tid = threadIdx.x, lane = tid & 31, wid = tid >> 5;
    int wm = wid >> 2, wn = wid & 3;
    int gID = lane >> 2, tg = lane & 3;
    int bid = blockIdx.x;
    int nt = bid % nNt, mt = bid / nNt;
    int m0 = mt * 128, n0 = nt * 128;
    const int nK = KPAD / 32;

    float acc[4][4][4];
#pragma unroll
    for (int i = 0; i < 4; i++)
#pragma unroll
        for (int j = 0; j < 4; j++)
#pragma unroll
            for (int q = 0; q < 4; q++) acc[i][j][q] = 0.f;

    ld_stage(sbase, Aq, Bq, m0, n0, M, Nmat, 0, tid);
    CP_COMMIT();

    uint32_t aOff[4], bOff[2];
#pragma unroll
    for (int mi = 0; mi < 4; mi++)
        aOff[mi] = (uint32_t)(wm * 64 + mi * 16 + (lane & 15)) * ROWB + (uint32_t)(lane >> 4) * 16;
#pragma unroll
    for (int pp = 0; pp < 2; pp++)
        bOff[pp] = (uint32_t)(wn * 32 + pp * 16 + ((lane >> 4) << 3) + (lane & 7)) * ROWB
                 + (uint32_t)(((lane >> 3) & 1) << 4);

    for (int kt = 0; kt < nK; kt++) {
        if (kt + 1 < nK)
            ld_stage(sbase + (uint32_t)((kt + 1) & 1) * STAGE_B,
                     Aq, Bq, m0, n0, M, Nmat, (kt + 1) * 32, tid);
        CP_COMMIT();
        CP_WAIT1();
        __syncthreads();

        uint32_t sb = sbase + (uint32_t)(kt & 1) * STAGE_B;
#pragma unroll
        for (int ks = 0; ks < 2; ks++) {
            uint32_t kb2 = (uint32_t)ks * 32;
            uint32_t bh[2][4];
#pragma unroll
            for (int pp = 0; pp < 2; pp++)
                ldsm_x4(bh[pp], sb + TILE_PAD + bOff[pp] + kb2);
#pragma unroll
            for (int mi = 0; mi < 4; mi++) {
                uint32_t ah[4];
                ldsm_x4(ah, sb + aOff[mi] + kb2);
#pragma unroll
                for (int ni = 0; ni < 4; ni++)
                    mma16816(acc[mi][ni], ah, &bh[ni >> 1][(ni & 1) * 2]);
            }
        }
        __syncthreads();
    }

#pragma unroll
    for (int mi = 0; mi < 4; mi++) {
        int r0 = m0 + wm * 64 + mi * 16 + gID;
        int r1 = r0 + 8;
#pragma unroll
        for (int ni = 0; ni < 4; ni++) {
            int cbase = n0 + wn * 32 + ni * 8 + tg * 2;
            if (cbase >= Nmat) continue;
            bool two = (cbase + 1 < Nmat);
            if (Ch) {
                if (r0 < M) {
                    __half2 h = __halves2half2(__float2half_rn(acc[mi][ni][0]),
                                               __float2half_rn(acc[mi][ni][1]));
                    if (two) *reinterpret_cast<__half2*>(Ch + (size_t)r0 * Nmat + cbase) = h;
                    else Ch[(size_t)r0 * Nmat + cbase] = __low2half(h);
                }
                if (r1 < M) {
                    __half2 h = __halves2half2(__float2half_rn(acc[mi][ni][2]),
                                               __float2half_rn(acc[mi][ni][3]));
                    if (two) *reinterpret_cast<__half2*>(Ch + (size_t)r1 * Nmat + cbase) = h;
                    else Ch[(size_t)r1 * Nmat + cbase] = __low2half(h);
                }
            } else {
                float bx = bias ? bias[cbase] : 0.f;
                float by = (bias && two) ? bias[cbase + 1] : 0.f;
                if (r0 < M) {
                    float* p = C + (size_t)r0 * Nmat + cbase;
                    if (two) { p[0] = acc[mi][ni][0] + bx; p[1] = acc[mi][ni][1] + by; }
                    else p[0] = acc[mi][ni][0] + bx;
                }
                if (r1 < M) {
                    float* p = C + (size_t)r1 * Nmat + cbase;
                    if (two) { p[0] = acc[mi][ni][2] + bx; p[1] = acc[mi][ni][3] + by; }
                    else p[0] = acc[mi][ni][2] + bx;
                }
            }
        }
    }
}

// ---------------- zero scratch ----------------
__global__ void k_zero() {
    size_t i = (size_t)blockIdx.x * blockDim.x + threadIdx.x;
    if (i < Nn * NH) {
        g_mkey1[i] = 0u; g_den1[i] = 0.f;
        g_mkey2[i] = 0u; g_den2[i] = 0.f;
    }
    if (i < Nn) g_cur[i] = 0;
    if (i < INF_) { g_bnsum[i] = 0.f; g_bnsum2[i] = 0.f; }
    if (i < NDOMc * INF_) { g_dsum[i] = 0.f; g_dsum2[i] = 0.f; }
    if (i < NDOMc) g_cnt[i] = 0.f;
}

// ---------------- CSR build ----------------
__global__ void k_deg(const int* __restrict__ dst) {
    int e = blockIdx.x * blockDim.x + threadIdx.x;
    if (e < Ee) atomicAdd(&g_cur[dst[e]], 1);
}

__global__ void k_scan() {
    __shared__ int sh[1024];
    __shared__ int carryS;
    int tid = threadIdx.x;
    if (tid == 0) { carryS = 0; g_roff[0] = 0; }
    __syncthreads();
    for (int base = 0; base < Nn; base += 1024) {
        int v = (base + tid < Nn) ? g_cur[base + tid] : 0;
        sh[tid] = v;
        __syncthreads();
        for (int o = 1; o < 1024; o <<= 1) {
            int t = (tid >= o) ? sh[tid - o] : 0;
            __syncthreads();
            sh[tid] += t;
            __syncthreads();
        }
        if (base + tid < Nn) g_roff[base + tid + 1] = carryS + sh[tid];
        __syncthreads();
        if (tid == 0) carryS += sh[1023];
        __syncthreads();
    }
    for (int i = tid; i < Nn; i += 1024) g_cur[i] = g_roff[i];
}

__global__ void k_fill(const int* __restrict__ dst) {
    int e = blockIdx.x * blockDim.x + threadIdx.x;
    if (e < Ee) {
        int pos = atomicAdd(&g_cur[dst[e]], 1);
        g_eidx[pos] = e;
    }
}

// ---------------- tiled SGEMM (GAT2 small GEMM), optional ELU on A loads ----------------
#define BM 128
#define BN 128
#define BK 8
#define TM 8
#define TN 8
__global__ __launch_bounds__(256) void sgemm_k(
    const float* __restrict__ A, const float* __restrict__ B,
    const float* __restrict__ bias, float* __restrict__ C,
    int M, int Nc, int K, int eluA)
{
    __shared__ float As[BK][BM];
    __shared__ float Bs[BK][BN];
    int tid = threadIdx.x;
    int m0 = blockIdx.y * BM;
    int n0 = blockIdx.x * BN;
    int tx = tid & 15, ty = tid >> 4;

    float acc[TM][TN];
    #pragma unroll
    for (int i = 0; i < TM; i++)
        #pragma unroll
        for (int j = 0; j < TN; j++) acc[i][j] = 0.f;

    int aRow = tid >> 1;
    int aCol = (tid & 1) * 4;
    int bRow = tid >> 5;
    int bCol = (tid & 31) * 4;

    int nK = K / BK;
    for (int kt = 0; kt < nK; kt++) {
        int kb = kt * BK;
        float4 av = make_float4(0.f, 0.f, 0.f, 0.f);
        if (m0 + aRow < M)
            av = *reinterpret_cast<const float4*>(A + (size_t)(m0 + aRow) * K + kb + aCol);
        if (eluA) { av.x = eluf(av.x); av.y = eluf(av.y); av.z = eluf(av.z); av.w = eluf(av.w); }
        As[aCol + 0][aRow] = av.x; As[aCol + 1][aRow] = av.y;
        As[aCol + 2][aRow] = av.z; As[aCol + 3][aRow] = av.w;

        const float* Bp = B + (size_t)(kb + bRow) * Nc + n0 + bCol;
        float4 bv;
        if (n0 + bCol + 3 < Nc && ((((size_t)Bp) & 15) == 0)) {
            bv = *reinterpret_cast<const float4*>(Bp);
        } else {
            bv.x = (n0 + bCol + 0 < Nc) ? Bp[0] : 0.f;
            bv.y = (n0 + bCol + 1 < Nc) ? Bp[1] : 0.f;
            bv.z = (n0 + bCol + 2 < Nc) ? Bp[2] : 0.f;
            bv.w = (n0 + bCol + 3 < Nc) ? Bp[3] : 0.f;
        }
        Bs[bRow][bCol + 0] = bv.x; Bs[bRow][bCol + 1] = bv.y;
        Bs[bRow][bCol + 2] = bv.z; Bs[bRow][bCol + 3] = bv.w;
        __syncthreads();

        #pragma unroll
        for (int k = 0; k < BK; k++) {
            float ar[TM], br[TN];
            #pragma unroll
            for (int i = 0; i < TM; i++) ar[i] = As[k][ty * TM + i];
            #pragma unroll
            for (int j = 0; j < TN; j++) br[j] = Bs[k][tx * TN + j];
            #pragma unroll
            for (int i = 0; i < TM; i++)
                #pragma unroll
                for (int j = 0; j < TN; j++) acc[i][j] += ar[i] * br[j];
        }
        __syncthreads();
    }

    #pragma unroll
    for (int i = 0; i < TM; i++) {
        int m = m0 + ty * TM + i;
        if (m >= M) continue;
        #pragma unroll
        for (int j = 0; j < TN; j++) {
            int n = n0 + tx * TN + j;
            if (n >= Nc) continue;
            float v = acc[i][j];
            if (bias) v += bias[n];
            C[(size_t)m * Nc + n] = v;
        }
    }
}

// ---------------- batch-norm column sums ----------------
__global__ void k_colsum(const float* __restrict__ X) {
    int j = blockIdx.x * blockDim.x + threadIdx.x;
    if (j >= INF_) return;
    int chunk = (Nn + gridDim.y - 1) / gridDim.y;
    int n0 = blockIdx.y * chunk;
    int n1 = min(n0 + chunk, Nn);
    float a = 0.f, b = 0.f;
    for (int n = n0; n < n1; n++) {
        float v = X[(size_t)n * INF_ + j];
        a += v; b += v * v;
    }
    atomicAdd(&g_bnsum[j], a);
    atomicAdd(&g_bnsum2[j], b);
}

// ---------------- attention logits (fp16 H): warp per (n, h) ----------------
__global__ void k_attn_logits_h(const __half* __restrict__ Hh, const float* __restrict__ asrc,
                                const float* __restrict__ adst, float* als, float* ald) {
    int w = (int)(((size_t)blockIdx.x * blockDim.x + threadIdx.x) >> 5);
    int lane = threadIdx.x & 31;
    if (w >= Nn * NH) return;
    int h = w % NH;
    const __half2* hp = reinterpret_cast<const __half2*>(Hh + (size_t)w * HIDF);
    float s = 0.f, d = 0.f;
    for (int t2 = lane; t2 < HIDF / 2; t2 += 32) {
        float2 hv = __half22float2(hp[t2]);
        int t = t2 * 2;
        s += hv.x * asrc[h * HIDF + t]     + hv.y * asrc[h * HIDF + t + 1];
        d += hv.x * adst[h * HIDF + t]     + hv.y * adst[h * HIDF + t + 1];
    }
    #pragma unroll
    for (int o = 16; o; o >>= 1) {
        s += __shfl_down_sync(0xffffffffu, s, o);
        d += __shfl_down_sync(0xffffffffu, d, o);
    }
    if (lane == 0) { als[w] = s; ald[w] = d; }
}

// fp32 variant for GAT2 (H2 small, fp32)
__global__ void k_attn_logits(const float* __restrict__ Hh, const float* __restrict__ asrc,
                              const float* __restrict__ adst, float* als, float* ald, int F) {
    int w = (int)(((size_t)blockIdx.x * blockDim.x + threadIdx.x) >> 5);
    int lane = threadIdx.x & 31;
    if (w >= Nn * NH) return;
    int h = w % NH;
    const float* hp = Hh + (size_t)w * F;
    float s = 0.f, d = 0.f;
    for (int t = lane; t < F; t += 32) {
        float hv = hp[t];
        s += hv * asrc[h * F + t];
        d += hv * adst[h * F + t];
    }
    #pragma unroll
    for (int o = 16; o; o >>= 1) {
        s += __shfl_down_sync(0xffffffffu, s, o);
        d += __shfl_down_sync(0xffffffffu, d, o);
    }
    if (lane == 0) { als[w] = s; ald[w] = d; }
}

// ---------------- edge softmax ----------------
__global__ void k_edge_max(const int* __restrict__ src, const int* __restrict__ dst,
                           const float* __restrict__ als, const float* __restrict__ ald,
                           float* e, unsigned* mkey) {
    int i = blockIdx.x * blockDim.x + threadIdx.x;
    if (i >= Ee * NH) return;
    int ed = i / NH, h = i % NH;
    float v = als[src[ed] * NH + h] + ald[dst[ed] * NH + h];
    v = v > 0.f ? v : 0.2f * v;
    e[i] = v;
    atomicMax(&mkey[dst[ed] * NH + h], f2o(v));
}

__global__ void k_edge_exp(const int* __restrict__ dst, float* e,
                           const unsigned* __restrict__ mkey, float* den) {
    int i = blockIdx.x * blockDim.x + threadIdx.x;
    if (i >= Ee * NH) return;
    int ed = i / NH, h = i % NH;
    float m = o2f(mkey[dst[ed] * NH + h]);
    float ex = expf(e[i] - m);
    e[i] = ex;
    atomicAdd(&den[dst[ed] * NH + h], ex);
}

// ---------------- CSR gather aggregation (fp16 H): warp per destination -------
__global__ void k_gather512h(const int* __restrict__ src,
                             const float* __restrict__ e1, const float* __restrict__ den,
                             const __half* __restrict__ Hh, float* __restrict__ out) {
    int d = (int)(((size_t)blockIdx.x * blockDim.x + threadIdx.x) >> 5);
    int lane = threadIdx.x & 31;
    if (d >= Nn) return;
    int beg = g_roff[d], end = g_roff[d + 1];
    float i0 = (1.f / NH) / (den[d * NH + 0] + 1e-16f);
    float i1 = (1.f / NH) / (den[d * NH + 1] + 1e-16f);
    float i2 = (1.f / NH) / (den[d * NH + 2] + 1e-16f);
    float acc[16];
#pragma unroll
    for (int i = 0; i < 16; i++) acc[i] = 0.f;
    for (int p = beg; p < end; p++) {
        int e = g_eidx[p];
        int s = src[e];
        float a0 = e1[e * NH + 0] * i0;
        float a1 = e1[e * NH + 1] * i1;
        float a2 = e1[e * NH + 2] * i2;
        const __half2* H0 = reinterpret_cast<const __half2*>(Hh + ((size_t)s * NH + 0) * HIDF) + lane;
        const __half2* H1 = reinterpret_cast<const __half2*>(Hh + ((size_t)s * NH + 1) * HIDF) + lane;
        const __half2* H2 = reinterpret_cast<const __half2*>(Hh + ((size_t)s * NH + 2) * HIDF) + lane;
#pragma unroll
        for (int it = 0; it < 8; it++) {
            float2 v0 = __half22float2(H0[it * 32]);
            float2 v1 = __half22float2(H1[it * 32]);
            float2 v2 = __half22float2(H2[it * 32]);
            acc[2 * it + 0] += v0.x * a0 + v1.x * a1 + v2.x * a2;
            acc[2 * it + 1] += v0.y * a0 + v1.y * a1 + v2.y * a2;
        }
    }
    float2* od = reinterpret_cast<float2*>(out + (size_t)d * HIDF) + lane;
#pragma unroll
    for (int it = 0; it < 8; it++)
        od[it * 32] = make_float2(acc[2 * it + 0], acc[2 * it + 1]);
}

// F=30, fp32 H2, writes straight to z_out
__global__ void k_gather30(const int* __restrict__ src,
                           const float* __restrict__ e2, const float* __restrict__ den,
                           const float* __restrict__ Hh, float* __restrict__ out) {
    int d = (int)(((size_t)blockIdx.x * blockDim.x + threadIdx.x) >> 5);
    int lane = threadIdx.x & 31;
    if (d >= Nn) return;
    int beg = g_roff[d], end = g_roff[d + 1];
    float i0 = (1.f / NH) / (den[d * NH + 0] + 1e-16f);
    float i1 = (1.f / NH) / (den[d * NH + 1] + 1e-16f);
    float i2 = (1.f / NH) / (den[d * NH + 2] + 1e-16f);
    float acc = 0.f;
    for (int p = beg; p < end; p++) {
        int e = g_eidx[p];
        int s = src[e];
        float a0 = e2[e * NH + 0] * i0;
        float a1 = e2[e * NH + 1] * i1;
        float a2 = e2[e * NH + 2] * i2;
        if (lane < OUTF) {
            acc += Hh[((size_t)s * NH + 0) * OUTF + lane] * a0
                 + Hh[((size_t)s * NH + 1) * OUTF + lane] * a1
                 + Hh[((size_t)s * NH + 2) * OUTF + lane] * a2;
        }
    }
    if (lane < OUTF) out[(size_t)d * OUTF + lane] = acc;
}

// ---------------- MLP head ----------------
__global__ void k_mlp(const float* __restrict__ z, const float* __restrict__ w1,
                      const float* __restrict__ b1, const float* __restrict__ w2,
                      const float* __restrict__ b2, const int* __restrict__ flag,
                      float* yp) {
    int n = blockIdx.x;
    int t = threadIdx.x;
    __shared__ float zs[OUTF];
    __shared__ float hid[MHc];
    if (t < OUTF) zs[t] = z[(size_t)n * OUTF + t];
    __syncthreads();
    if (*flag == 0) {
        if (t < NLABc) yp[(size_t)n * NLABc + t] = 0.f;
        return;
    }
    float a = b1[t];
    #pragma unroll
    for (int k = 0; k < OUTF; k++) a += zs[k] * w1[k * MHc + t];
    hid[t] = fmaxf(a, 0.f);
    __syncthreads();
    if (t < NLABc) {
        float o = b2[t];
        #pragma unroll
        for (int k2 = 0; k2 < MHc; k2++) o += hid[k2] * w2[k2 * NLABc + t];
        yp[(size_t)n * NLABc + t] = o;
    }
}

// ---------------- fc2 (K=30, write-bound) — float4 over j ----------------
__global__ void k_fc2v(const float* __restrict__ z, const float* __restrict__ W,
                       const float* __restrict__ b, float* __restrict__ out) {
    size_t i4 = (size_t)blockIdx.x * blockDim.x + threadIdx.x;
    const int jq = INF_ / 4;
    if (i4 >= (size_t)Nn * jq) return;
    int n = (int)(i4 / jq), j4 = (int)(i4 % jq) * 4;
    float4 acc = *reinterpret_cast<const float4*>(b + j4);
    const float* zr = z + (size_t)n * OUTF;
    #pragma unroll
    for (int k = 0; k < OUTF; k++) {
        float zk = zr[k];
        float4 w = *reinterpret_cast<const float4*>(W + (size_t)k * INF_ + j4);
        acc.x += zk * w.x; acc.y += zk * w.y; acc.z += zk * w.z; acc.w += zk * w.w;
    }
    *reinterpret_cast<float4*>(out + (size_t)n * INF_ + j4) = acc;
}

// ---------------- DSBN ----------------
__global__ void k_cnt(const int* __restrict__ y) {
    int n = blockIdx.x * blockDim.x + threadIdx.x;
    if (n < Nn) atomicAdd(&g_cnt[y[n]], 1.f);
}

__global__ void k_dsbn_sum(const float* __restrict__ X, const int* __restrict__ y) {
    int j = blockIdx.x * blockDim.x + threadIdx.x;
    if (j >= INF_) return;
    int chunk = (Nn + gridDim.y - 1) / gridDim.y;
    int n0 = blockIdx.y * chunk;
    int n1 = min(n0 + chunk, Nn);
    float a[NDOMc], b[NDOMc];
    #pragma unroll
    for (int k = 0; k < NDOMc; k++) { a[k] = 0.f; b[k] = 0.f; }
    for (int n = n0; n < n1; n++) {
        int d = y[n];
        float v = X[(size_t)n * INF_ + j];
        #pragma unroll
        for (int k = 0; k < NDOMc; k++) {
            float m = (d == k) ? 1.f : 0.f;
            a[k] += m * v;
            b[k] += m * v * v;
        }
    }
    #pragma unroll
    for (int k = 0; k < NDOMc; k++) {
        atomicAdd(&g_dsum[k * INF_ + j], a[k]);
        atomicAdd(&g_dsum2[k * INF_ + j], b[k]);
    }
}

// ======================================================================
extern "C" void kernel_launch(void* const* d_in, const int* in_sizes, int n_in,
                              void* d_out, int out_size) {
    const float* features = (const float*)d_in[0];
    const int*   ei       = (const int*)d_in[1];
    const int*   y        = (const int*)d_in[2];
    const int*   flag     = (const int*)d_in[3];
    const float* fc1_w    = (const float*)d_in[4];
    const float* fc1_b    = (const float*)d_in[5];
    const float* bn_g     = (const float*)d_in[6];
    const float* bn_b     = (const float*)d_in[7];
    const float* W1       = (const float*)d_in[8];
    const float* a1_src   = (const float*)d_in[9];
    const float* a1_dst   = (const float*)d_in[10];
    const float* W2       = (const float*)d_in[11];
    const float* a2_src   = (const float*)d_in[12];
    const float* a2_dst   = (const float*)d_in[13];
    const float* mlp_w1   = (const float*)d_in[14];
    const float* mlp_b1   = (const float*)d_in[15];
    const float* mlp_w2   = (const float*)d_in[16];
    const float* mlp_b2   = (const float*)d_in[17];
    const float* fc2_w    = (const float*)d_in[18];
    const float* fc2_b    = (const float*)d_in[19];
    const float* dsbn_g   = (const float*)d_in[20];
    const float* dsbn_b   = (const float*)d_in[21];
    const float* fc3_w    = (const float*)d_in[22];
    const float* fc3_b    = (const float*)d_in[23];

    float* out    = (float*)d_out;
    float* z_out  = out;
    float* h3_out = out + (size_t)Nn * OUTF;
    float* yp_out = h3_out + (size_t)Nn * INF_;
    const int* srcp = ei;
    const int* dstp = ei + Ee;

    void* p;
    cudaGetSymbolAddress(&p, g_x);     float* px    = (float*)p;
    cudaGetSymbolAddress(&p, g_Hh);    __half* pHh  = (__half*)p;
    cudaGetSymbolAddress(&p, g_h1);    float* ph1   = (float*)p;
    cudaGetSymbolAddress(&p, g_H2);    float* pH2   = (float*)p;
    cudaGetSymbolAddress(&p, g_als1);  float* pals1 = (float*)p;
    cudaGetSymbolAddress(&p, g_ald1);  float* pald1 = (float*)p;
    cudaGetSymbolAddress(&p, g_als2);  float* pals2 = (float*)p;
    cudaGetSymbolAddress(&p, g_ald2);  float* pald2 = (float*)p;
    cudaGetSymbolAddress(&p, g_e1);    float* pe1   = (float*)p;
    cudaGetSymbolAddress(&p, g_e2);    float* pe2   = (float*)p;
    cudaGetSymbolAddress(&p, g_mkey1); unsigned* pmk1 = (unsigned*)p;
    cudaGetSymbolAddress(&p, g_mkey2); unsigned* pmk2 = (unsigned*)p;
    cudaGetSymbolAddress(&p, g_den1);  float* pden1 = (float*)p;
    cudaGetSymbolAddress(&p, g_den2);  float* pden2 = (float*)p;
    cudaGetSymbolAddress(&p, g_Aq);    __half* pAq = (__half*)p;
    cudaGetSymbolAddress(&p, g_Wq);    __half* pWq = (__half*)p;

    static int smem_set = 0;
    if (!smem_set) {
        cudaFuncSetAttribute(gemm_mma3, cudaFuncAttributeMaxDynamicSharedMemorySize, GSMEM);
        smem_set = 1;
    }

    const int nMt = (Nn + 127) / 128;
    const size_t cvtGrid4 = ((size_t)Nn * (KPAD / 4) + 255) / 256;
    const int gaW = (Nn * 32 + 255) / 256;

    // 0) zero scratch + CSR build
    {
        size_t tot = (size_t)NDOMc * INF_;
        size_t mx = tot > (size_t)Nn * NH ? tot : (size_t)Nn * NH;
        if ((size_t)Nn > mx) mx = Nn;
        k_zero<<<(unsigned)((mx + 255) / 256), 256>>>();
        k_deg<<<(Ee + 255) / 256, 256>>>(dstp);
        k_scan<<<1, 1024>>>();
        k_fill<<<(Ee + 255) / 256, 256>>>(dstp);
    }

    // 1) fc1
    {
        dim3 tg((KPAD + 31) / 32, (INF_ + 31) / 32);
        k_splitWT<<<tg, dim3(32, 32)>>>(fc1_w, pWq, INF_, INF_);
        k_cvtA4<<<(unsigned)cvtGrid4, 256>>>(features, pAq, Nn, INF_);
        int nNt = (INF_ + 127) / 128;
        gemm_mma3<<<nMt * nNt, 256, GSMEM>>>(pAq, pWq, fc1_b, px, nullptr, Nn, INF_, nNt);
    }

    // 2) batchnorm stats + fused apply/ELU/convert
    {
        dim3 grid((INF_ + 255) / 256, 128);
        k_colsum<<<grid, 256>>>(px);
        k_bn_elu_cvt<<<(unsigned)cvtGrid4, 256>>>(px, bn_g, bn_b, pAq);
    }

    // 3) GAT layer 1 (H written as fp16)
    {
        dim3 tg((KPAD + 31) / 32, (NH * HIDF + 31) / 32);
        k_splitWT<<<tg, dim3(32, 32)>>>(W1, pWq, INF_, NH * HIDF);
        int nNt = (NH * HIDF + 127) / 128;
        gemm_mma3<<<nMt * nNt, 256, GSMEM>>>(pAq, pWq, nullptr, nullptr, pHh, Nn, NH * HIDF, nNt);

        int warps = Nn * NH;
        k_attn_logits_h<<<(warps * 32 + 127) / 128, 128>>>(pHh, a1_src, a1_dst, pals1, pald1);

        int et = Ee * NH;
        k_edge_max<<<(et + 255) / 256, 256>>>(srcp, dstp, pals1, pald1, pe1, pmk1);
        k_edge_exp<<<(et + 255) / 256, 256>>>(dstp, pe1, pmk1, pden1);
        k_gather512h<<<gaW, 256>>>(srcp, pe1, pden1, pHh, ph1);
        // h1 holds pre-ELU mean; ELU fused into sgemm_k A-load
    }

    // 4) GAT layer 2 -> z
    {
        dim3 grid((NH * OUTF + BN - 1) / BN, (Nn + BM - 1) / BM);
        sgemm_k<<<grid, 256>>>(ph1, W2, nullptr, pH2, Nn, NH * OUTF, HIDF, 1);

        int warps = Nn * NH;
        k_attn_logits<<<(warps * 32 + 127) / 128, 128>>>(pH2, a2_src, a2_dst, pals2, pald2, OUTF);

        int et = Ee * NH;
        k_edge_max<<<(et + 255) / 256, 256>>>(srcp, dstp, pals2, pald2, pe2, pmk2);
        k_edge_exp<<<(et + 255) / 256, 256>>>(dstp, pe2, pmk2, pden2);
        k_gather30<<<gaW, 256>>>(srcp, pe2, pden2, pH2, z_out);
    }

    // 5) MLP head
    k_mlp<<<Nn, MHc>>>(z_out, mlp_w1, mlp_b1, mlp_w2, mlp_b2, flag, yp_out);

    // 6) fc2 -> DSBN stats -> fused apply/ELU/convert
    {
        size_t tot4 = (size_t)Nn * (INF_ / 4);
        k_fc2v<<<(unsigned)((tot4 + 255) / 256), 256>>>(z_out, fc2_w, fc2_b, px);
        k_cnt<<<(Nn + 255) / 256, 256>>>(y);
        dim3 grid((INF_ + 255) / 256, 128);
        k_dsbn_sum<<<grid, 256>>>(px, y);
        k_dsbn_elu_cvt<<<(unsigned)cvtGrid4, 256>>>(px, y, dsbn_g, dsbn_b, pAq);
    }

    // 7) fc3 -> h3
    {
        dim3 tg((KPAD + 31) / 32, (INF_ + 31) / 32);
        k_splitWT<<<tg, dim3(32, 32)>>>(fc3_w, pWq, INF_, INF_);
        int nNt = (INF_ + 127) / 128;
        gemm_mma3<<<nMt * nNt, 256, GSMEM>>>(pAq, pWq, fc3_b, h3_out, nullptr, Nn, INF_, nNt);
    }
}

// round 17
// speedup vs baseline: 1.6583x; 1.0233x over previous
#include <cuda_runtime.h>
#include <cuda_bf16.h>
#include <cuda_fp16.h>
#include <math.h>
#include <stdint.h>

#define Nn    20000
#define Ee    120000
#define INF_  3000
#define HIDF  512
#define OUTF  30
#define NH    3
#define NDOMc 4
#define MHc   64
#define NLABc 20
#define EPSBN 1e-5f
#define KPAD  3008                 // 3000 padded to multiple of 32

// ---------------- scratch (static device memory; no allocations) ----------------
__device__ float    g_x[(size_t)Nn * INF_];
__device__ __align__(256) __half g_Hh[(size_t)Nn * NH * HIDF];   // GAT1 features, fp16
__device__ float    g_h1[(size_t)Nn * HIDF];
__device__ float    g_H2[(size_t)Nn * NH * OUTF];
__device__ float    g_als1[Nn * NH], g_ald1[Nn * NH];
__device__ float    g_als2[Nn * NH], g_ald2[Nn * NH];
__device__ float    g_e1[(size_t)Ee * NH];
__device__ float    g_e2[(size_t)Ee * NH];
__device__ unsigned g_mkey1[Nn * NH], g_mkey2[Nn * NH];
__device__ float    g_den1[Nn * NH], g_den2[Nn * NH];
__device__ float    g_bnsum[INF_], g_bnsum2[INF_];
__device__ float    g_dsum[NDOMc * INF_], g_dsum2[NDOMc * INF_];
__device__ float    g_cnt[NDOMc];
__device__ int      g_roff[Nn + 1];
__device__ int      g_cur[Nn];
__device__ int      g_eidx[Ee];
__device__ __align__(256) __half g_Aq[(size_t)Nn * KPAD];
__device__ __align__(256) __half g_Wq[(size_t)INF_ * KPAD];

// ---------------- helpers ----------------
__device__ __forceinline__ unsigned f2o(float f) {
    unsigned u = __float_as_uint(f);
    return (u & 0x80000000u) ? ~u : (u | 0x80000000u);
}
__device__ __forceinline__ float o2f(unsigned k) {
    return (k & 0x80000000u) ? __uint_as_float(k ^ 0x80000000u) : __uint_as_float(~k);
}
__device__ __forceinline__ float eluf(float v) { return v > 0.f ? v : (expf(v) - 1.f); }

__device__ __forceinline__ uint32_t smem_u32(const void* p) {
    uint32_t a;
    asm("{ .reg .u64 t; cvta.to.shared.u64 t, %1; cvt.u32.u64 %0, t; }" : "=r"(a) : "l"(p));
    return a;
}

__device__ __forceinline__ void cp16(uint32_t dst, const void* src, int ok) {
    asm volatile("cp.async.cg.shared.global [%0], [%1], 16, %2;"
                 :: "r"(dst), "l"(src), "r"(ok ? 16 : 0) : "memory");
}
#define CP_COMMIT() asm volatile("cp.async.commit_group;" ::: "memory")
#define CP_WAIT1()  asm volatile("cp.async.wait_group 1;" ::: "memory")

__device__ __forceinline__ void mma16816(float* c, const uint32_t* a, const uint32_t* b) {
    asm volatile(
        "mma.sync.aligned.m16n8k16.row.col.f32.f16.f16.f32 "
        "{%0,%1,%2,%3},{%4,%5,%6,%7},{%8,%9},{%0,%1,%2,%3};"
        : "+f"(c[0]), "+f"(c[1]), "+f"(c[2]), "+f"(c[3])
        : "r"(a[0]), "r"(a[1]), "r"(a[2]), "r"(a[3]), "r"(b[0]), "r"(b[1]));
}
__device__ __forceinline__ void ldsm_x4(uint32_t* r, uint32_t addr) {
    asm volatile("ldmatrix.sync.aligned.m8n8.x4.shared.b16 {%0,%1,%2,%3}, [%4];"
                 : "=r"(r[0]), "=r"(r[1]), "=r"(r[2]), "=r"(r[3]) : "r"(addr));
}

// ---------------- fp16 convert helpers ----------------
__device__ __forceinline__ void cvt_store4(__half* dst, size_t o,
                                           float v0, float v1, float v2, float v3) {
    __half2 p0 = __halves2half2(__float2half_rn(v0), __float2half_rn(v1));
    __half2 p1 = __halves2half2(__float2half_rn(v2), __float2half_rn(v3));
    uint2 hv;
    hv.x = *(uint32_t*)&p0; hv.y = *(uint32_t*)&p1;
    *reinterpret_cast<uint2*>(dst + o) = hv;
}

__global__ void k_cvtA4(const float* __restrict__ X, __half* __restrict__ q, int M, int K) {
    size_t i4 = (size_t)blockIdx.x * blockDim.x + threadIdx.x;
    const int kq = KPAD / 4;
    if (i4 >= (size_t)M * kq) return;
    int m = (int)(i4 / kq), k4 = (int)(i4 % kq) * 4;
    const float* row = X + (size_t)m * K;
    float v0, v1, v2, v3;
    if (k4 + 3 < K) {
        float4 f = *reinterpret_cast<const float4*>(row + k4);
        v0 = f.x; v1 = f.y; v2 = f.z; v3 = f.w;
    } else {
        v0 = (k4 + 0 < K) ? row[k4 + 0] : 0.f;
        v1 = (k4 + 1 < K) ? row[k4 + 1] : 0.f;
        v2 = (k4 + 2 < K) ? row[k4 + 2] : 0.f;
        v3 = (k4 + 3 < K) ? row[k4 + 3] : 0.f;
    }
    cvt_store4(q, (size_t)m * KPAD + k4, v0, v1, v2, v3);
}

// Fused: BN apply + ELU + fp16 convert
__global__ void k_bn_elu_cvt(const float* __restrict__ X,
                             const float* __restrict__ g, const float* __restrict__ b,
                             __half* __restrict__ q) {
    size_t i4 = (size_t)blockIdx.x * blockDim.x + threadIdx.x;
    const int kq = KPAD / 4;
    if (i4 >= (size_t)Nn * kq) return;
    int m = (int)(i4 / kq), k4 = (int)(i4 % kq) * 4;
    float v[4];
    if (k4 + 3 < INF_) {
        float4 f = *reinterpret_cast<const float4*>(X + (size_t)m * INF_ + k4);
        v[0] = f.x; v[1] = f.y; v[2] = f.z; v[3] = f.w;
#pragma unroll
        for (int qq = 0; qq < 4; qq++) {
            int j = k4 + qq;
            float mu  = g_bnsum[j] * (1.f / Nn);
            float var = fmaxf(g_bnsum2[j] * (1.f / Nn) - mu * mu, 0.f);
            v[qq] = eluf((v[qq] - mu) * rsqrtf(var + EPSBN) * g[j] + b[j]);
        }
    } else {
#pragma unroll
        for (int qq = 0; qq < 4; qq++) {
            int j = k4 + qq;
            if (j < INF_) {
                float x = X[(size_t)m * INF_ + j];
                float mu  = g_bnsum[j] * (1.f / Nn);
                float var = fmaxf(g_bnsum2[j] * (1.f / Nn) - mu * mu, 0.f);
                v[qq] = eluf((x - mu) * rsqrtf(var + EPSBN) * g[j] + b[j]);
            } else v[qq] = 0.f;
        }
    }
    cvt_store4(q, (size_t)m * KPAD + k4, v[0], v[1], v[2], v[3]);
}

// Fused: DSBN apply + ELU + fp16 convert
__global__ void k_dsbn_elu_cvt(const float* __restrict__ X, const int* __restrict__ y,
                               const float* __restrict__ gmm, const float* __restrict__ bta,
                               __half* __restrict__ q) {
    size_t i4 = (size_t)blockIdx.x * blockDim.x + threadIdx.x;
    const int kq = KPAD / 4;
    if (i4 >= (size_t)Nn * kq) return;
    int m = (int)(i4 / kq), k4 = (int)(i4 % kq) * 4;
    int d = y[m];
    float c = g_cnt[d];
    bool norm = (c > 1.f);
    float inv = norm ? (1.f / c) : 0.f;
    float v[4];
#pragma unroll
    for (int qq = 0; qq < 4; qq++) {
        int j = k4 + qq;
        if (j < INF_) {
            float x = X[(size_t)m * INF_ + j];
            float o = x;
            if (norm) {
                float mu  = g_dsum[d * INF_ + j] * inv;
                float var = fmaxf(g_dsum2[d * INF_ + j] * inv - mu * mu, 0.f);
                o = (x - mu) * rsqrtf(var + EPSBN) * gmm[d * INF_ + j] + bta[d * INF_ + j];
            }
            v[qq] = eluf(o);
        } else v[qq] = 0.f;
    }
    cvt_store4(q, (size_t)m * KPAD + k4, v[0], v[1], v[2], v[3]);
}

// ELU + fp16 convert of h1 (K = 512 exactly)
__global__ void k_elu_cvt512(const float* __restrict__ X, __half* __restrict__ q) {
    size_t i4 = (size_t)blockIdx.x * blockDim.x + threadIdx.x;
    const int kq = HIDF / 4;   // 128
    if (i4 >= (size_t)Nn * kq) return;
    int m = (int)(i4 / kq), k4 = (int)(i4 % kq) * 4;
    float4 f = *reinterpret_cast<const float4*>(X + (size_t)m * HIDF + k4);
    cvt_store4(q, (size_t)m * HIDF + k4, eluf(f.x), eluf(f.y), eluf(f.z), eluf(f.w));
}

// W[K, N] f32 -> WT fp16 [N, kpad] (zero pad beyond K)
__global__ void k_splitWT(const float* __restrict__ W, __half* __restrict__ hi,
                          int K, int Nmat, int kpad) {
    __shared__ float t[32][33];
    int kb = blockIdx.x * 32, nb = blockIdx.y * 32;
    int rk = kb + threadIdx.y, rn = nb + threadIdx.x;
    t[threadIdx.y][threadIdx.x] = (rk < K && rn < Nmat) ? W[(size_t)rk * Nmat + rn] : 0.f;
    __syncthreads();
    int wn = nb + threadIdx.y, wk = kb + threadIdx.x;
    if (wn < Nmat && wk < kpad)
        hi[(size_t)wn * kpad + wk] = __float2half_rn(t[threadIdx.x][threadIdx.y]);
}

// ------ mma.sync fp16 GEMM: 256 thr, ldmatrix, 2-stage, 2 CTAs/SM ------
// Output: fp32 C (+bias, optional column stats) or fp16 Ch. Runtime K (kTot % 32 == 0).
#define ROWB      80
#define TILE_PAD  (128 * ROWB)
#define STAGE_B   (2 * TILE_PAD)
#define GSMEM     (2 * STAGE_B)

__device__ __forceinline__ void ld_stage(
    uint32_t sb,
    const __half* __restrict__ Aq, const __half* __restrict__ Bq,
    int m0, int n0, int M, int Nmat, int kb, int tid, int kTot)
{
    int row = tid >> 1;
    int cb = (tid & 1) * 32;
    int ce = cb >> 1;

    int gA = m0 + row;
    int okA = gA < M;
    const __half* a = Aq + (size_t)(okA ? gA : 0) * kTot + kb + ce;
    uint32_t soA = sb + (uint32_t)row * ROWB + (uint32_t)cb;
    cp16(soA,      a,     okA);
    cp16(soA + 16, a + 8, okA);

    int gB = n0 + row;
    int okB = gB < Nmat;
    const __half* b = Bq + (size_t)(okB ? gB : 0) * kTot + kb + ce;
    uint32_t soB = sb + TILE_PAD + (uint32_t)row * ROWB + (uint32_t)cb;
    cp16(soB,      b,     okB);
    cp16(soB + 16, b + 8, okB);
}

__global__ void __launch_bounds__(256, 2) gemm_mma3(
    const __half* __restrict__ Aq, const __half* __restrict__ Bq,
    const float* __restrict__ bias, float* __restrict__ C,
    __half* __restrict__ Ch,
    float* __restrict__ sS, float* __restrict__ sQ,
    int M, int Nmat, int nNt, int kTot)
{
    extern __shared__ char smem[];
    __shared__ float sstat[256];
    uint32_t sbase = smem_u32(smem);
    int tid = threadIdx.x, lane = tid & 31, wid = tid >> 5;
    int wm = wid >> 2, wn = wid & 3;
    int gID = lane >> 2, tg = lane & 3;
    int bid = blockIdx.x;
    int nt = bid % nNt, mt = bid / nNt;
    int m0 = mt * 128, n0 = nt * 128;
    const int nK = kTot / 32;

    if (sS) sstat[tid] = 0.f;

    float acc[4][4][4];
#pragma unroll
    for (int i = 0; i < 4; i++)
#pragma unroll
        for (int j = 0; j < 4; j++)
#pragma unroll
            for (int q = 0; q < 4; q++) acc[i][j][q] = 0.f;

    ld_stage(sbase, Aq, Bq, m0, n0, M, Nmat, 0, tid, kTot);
    CP_COMMIT();

    uint32_t aOff[4], bOff[2];
#pragma unroll
    for (int mi = 0; mi < 4; mi++)
        aOff[mi] = (uint32_t)(wm * 64 + mi * 16 + (lane & 15)) * ROWB + (uint32_t)(lane >> 4) * 16;
#pragma unroll
    for (int pp = 0; pp < 2; pp++)
        bOff[pp] = (uint32_t)(wn * 32 + pp * 16 + ((lane >> 4) << 3) + (lane & 7)) * ROWB
                 + (uint32_t)(((lane >> 3) & 1) << 4);

    for (int kt = 0; kt < nK; kt++) {
        if (kt + 1 < nK)
            ld_stage(sbase + (uint32_t)((kt + 1) & 1) * STAGE_B,
                     Aq, Bq, m0, n0, M, Nmat, (kt + 1) * 32, tid, kTot);
        CP_COMMIT();
        CP_WAIT1();
        __syncthreads();

        uint32_t sb = sbase + (uint32_t)(kt & 1) * STAGE_B;
#pragma unroll
        for (int ks = 0; ks < 2; ks++) {
            uint32_t kb2 = (uint32_t)ks * 32;
            uint32_t bh[2][4];
#pragma unroll
            for (int pp = 0; pp < 2; pp++)
                ldsm_x4(bh[pp], sb + TILE_PAD + bOff[pp] + kb2);
#pragma unroll
            for (int mi = 0; mi < 4; mi++) {
                uint32_t ah[4];
                ldsm_x4(ah, sb + aOff[mi] + kb2);
#pragma unroll
                for (int ni = 0; ni < 4; ni++)
                    mma16816(acc[mi][ni], ah, &bh[ni >> 1][(ni & 1) * 2]);
            }
        }
        __syncthreads();
    }

    float st[4][4];   // per-ni: sum_c0, sq_c0, sum_c1, sq_c1
#pragma unroll
    for (int ni = 0; ni < 4; ni++) { st[ni][0] = st[ni][1] = st[ni][2] = st[ni][3] = 0.f; }

#pragma unroll
    for (int mi = 0; mi < 4; mi++) {
        int r0 = m0 + wm * 64 + mi * 16 + gID;
        int r1 = r0 + 8;
#pragma unroll
        for (int ni = 0; ni < 4; ni++) {
            int cbase = n0 + wn * 32 + ni * 8 + tg * 2;
            if (cbase >= Nmat) continue;
            bool two = (cbase + 1 < Nmat);
            if (Ch) {
                if (r0 < M) {
                    __half2 h = __halves2half2(__float2half_rn(acc[mi][ni][0]),
                                               __float2half_rn(acc[mi][ni][1]));
                    if (two) *reinterpret_cast<__half2*>(Ch + (size_t)r0 * Nmat + cbase) = h;
                    else Ch[(size_t)r0 * Nmat + cbase] = __low2half(h);
                }
                if (r1 < M) {
                    __half2 h = __halves2half2(__float2half_rn(acc[mi][ni][2]),
                                               __float2half_rn(acc[mi][ni][3]));
                    if (two) *reinterpret_cast<__half2*>(Ch + (size_t)r1 * Nmat + cbase) = h;
                    else Ch[(size_t)r1 * Nmat + cbase] = __low2half(h);
                }
            } else {
                float bx = bias ? bias[cbase] : 0.f;
                float by = (bias && two) ? bias[cbase + 1] : 0.f;
                if (r0 < M) {
                    float v0 = acc[mi][ni][0] + bx;
                    float v1 = acc[mi][ni][1] + by;
                    float* p = C + (size_t)r0 * Nmat + cbase;
                    if (two) { p[0] = v0; p[1] = v1;
                               st[ni][0] += v0; st[ni][1] += v0 * v0;
                               st[ni][2] += v1; st[ni][3] += v1 * v1; }
                    else { p[0] = v0; st[ni][0] += v0; st[ni][1] += v0 * v0; }
                }
                if (r1 < M) {
                    float v0 = acc[mi][ni][2] + bx;
                    float v1 = acc[mi][ni][3] + by;
                    float* p = C + (size_t)r1 * Nmat + cbase;
                    if (two) { p[0] = v0; p[1] = v1;
                               st[ni][0] += v0; st[ni][1] += v0 * v0;
                               st[ni][2] += v1; st[ni][3] += v1 * v1; }
                    else { p[0] = v0; st[ni][0] += v0; st[ni][1] += v0 * v0; }
                }
            }
        }
    }

    if (sS) {
#pragma unroll
        for (int ni = 0; ni < 4; ni++) {
            int cl = wn * 32 + ni * 8 + tg * 2;
            atomicAdd(&sstat[cl], st[ni][0]);
            atomicAdd(&sstat[128 + cl], st[ni][1]);
            if (cl + 1 < 128) {
                atomicAdd(&sstat[cl + 1], st[ni][2]);
                atomicAdd(&sstat[128 + cl + 1], st[ni][3]);
            }
        }
        __syncthreads();
        if (tid < 128) {
            int c = n0 + tid;
            if (c < Nmat) {
                atomicAdd(&sS[c], sstat[tid]);
                atomicAdd(&sQ[c], sstat[128 + tid]);
            }
        }
    }
}

// ---------------- zero scratch ----------------
__global__ void k_zero() {
    size_t i = (size_t)blockIdx.x * blockDim.x + threadIdx.x;
    if (i < Nn * NH) {
        g_mkey1[i] = 0u; g_den1[i] = 0.f;
        g_mkey2[i] = 0u; g_den2[i] = 0.f;
    }
    if (i < Nn) g_cur[i] = 0;
    if (i < INF_) { g_bnsum[i] = 0.f; g_bnsum2[i] = 0.f; }
    if (i < NDOMc * INF_) { g_dsum[i] = 0.f; g_dsum2[i] = 0.f; }
    if (i < NDOMc) g_cnt[i] = 0.f;
}

// ---------------- CSR build ----------------
__global__ void k_deg(const int* __restrict__ dst) {
    int e = blockIdx.x * blockDim.x + threadIdx.x;
    if (e < Ee) atomicAdd(&g_cur[dst[e]], 1);
}

__global__ void k_scan() {
    __shared__ int sh[1024];
    __shared__ int carryS;
    int tid = threadIdx.x;
    if (tid == 0) { carryS = 0; g_roff[0] = 0; }
    __syncthreads();
    for (int base = 0; base < Nn; base += 1024) {
        int v = (base + tid < Nn) ? g_cur[base + tid] : 0;
        sh[tid] = v;
        __syncthreads();
        for (int o = 1; o < 1024; o <<= 1) {
            int t = (tid >= o) ? sh[tid - o] : 0;
            __syncthreads();
            sh[tid] += t;
            __syncthreads();
        }
        if (base + tid < Nn) g_roff[base + tid + 1] = carryS + sh[tid];
        __syncthreads();
        if (tid == 0) carryS += sh[1023];
        __syncthreads();
    }
    for (int i = tid; i < Nn; i += 1024) g_cur[i] = g_roff[i];
}

__global__ void k_fill(const int* __restrict__ dst) {
    int e = blockIdx.x * blockDim.x + threadIdx.x;
    if (e < Ee) {
        int pos = atomicAdd(&g_cur[dst[e]], 1);
        g_eidx[pos] = e;
    }
}

// ---------------- attention logits (fp16 H): warp per (n, h) ----------------
__global__ void k_attn_logits_h(const __half* __restrict__ Hh, const float* __restrict__ asrc,
                                const float* __restrict__ adst, float* als, float* ald) {
    int w = (int)(((size_t)blockIdx.x * blockDim.x + threadIdx.x) >> 5);
    int lane = threadIdx.x & 31;
    if (w >= Nn * NH) return;
    int h = w % NH;
    const __half2* hp = reinterpret_cast<const __half2*>(Hh + (size_t)w * HIDF);
    float s = 0.f, d = 0.f;
    for (int t2 = lane; t2 < HIDF / 2; t2 += 32) {
        float2 hv = __half22float2(hp[t2]);
        int t = t2 * 2;
        s += hv.x * asrc[h * HIDF + t]     + hv.y * asrc[h * HIDF + t + 1];
        d += hv.x * adst[h * HIDF + t]     + hv.y * adst[h * HIDF + t + 1];
    }
    #pragma unroll
    for (int o = 16; o; o >>= 1) {
        s += __shfl_down_sync(0xffffffffu, s, o);
        d += __shfl_down_sync(0xffffffffu, d, o);
    }
    if (lane == 0) { als[w] = s; ald[w] = d; }
}

// fp32 variant for GAT2 (H2 small, fp32)
__global__ void k_attn_logits(const float* __restrict__ Hh, const float* __restrict__ asrc,
                              const float* __restrict__ adst, float* als, float* ald, int F) {
    int w = (int)(((size_t)blockIdx.x * blockDim.x + threadIdx.x) >> 5);
    int lane = threadIdx.x & 31;
    if (w >= Nn * NH) return;
    int h = w % NH;
    const float* hp = Hh + (size_t)w * F;
    float s = 0.f, d = 0.f;
    for (int t = lane; t < F; t += 32) {
        float hv = hp[t];
        s += hv * asrc[h * F + t];
        d += hv * adst[h * F + t];
    }
    #pragma unroll
    for (int o = 16; o; o >>= 1) {
        s += __shfl_down_sync(0xffffffffu, s, o);
        d += __shfl_down_sync(0xffffffffu, d, o);
    }
    if (lane == 0) { als[w] = s; ald[w] = d; }
}

// ---------------- edge softmax ----------------
__global__ void k_edge_max(const int* __restrict__ src, const int* __restrict__ dst,
                           const float* __restrict__ als, const float* __restrict__ ald,
                           float* e, unsigned* mkey) {
    int i = blockIdx.x * blockDim.x + threadIdx.x;
    if (i >= Ee * NH) return;
    int ed = i / NH, h = i % NH;
    float v = als[src[ed] * NH + h] + ald[dst[ed] * NH + h];
    v = v > 0.f ? v : 0.2f * v;
    e[i] = v;
    atomicMax(&mkey[dst[ed] * NH + h], f2o(v));
}

__global__ void k_edge_exp(const int* __restrict__ dst, float* e,
                           const unsigned* __restrict__ mkey, float* den) {
    int i = blockIdx.x * blockDim.x + threadIdx.x;
    if (i >= Ee * NH) return;
    int ed = i / NH, h = i % NH;
    float m = o2f(mkey[dst[ed] * NH + h]);
    float ex = expf(e[i] - m);
    e[i] = ex;
    atomicAdd(&den[dst[ed] * NH + h], ex);
}

// ---------------- CSR gather aggregation (fp16 H): warp per destination -------
__global__ void k_gather512h(const int* __restrict__ src,
                             const float* __restrict__ e1, const float* __restrict__ den,
                             const __half* __restrict__ Hh, float* __restrict__ out) {
    int d = (int)(((size_t)blockIdx.x * blockDim.x + threadIdx.x) >> 5);
    int lane = threadIdx.x & 31;
    if (d >= Nn) return;
    int beg = g_roff[d], end = g_roff[d + 1];
    float i0 = (1.f / NH) / (den[d * NH + 0] + 1e-16f);
    float i1 = (1.f / NH) / (den[d * NH + 1] + 1e-16f);
    float i2 = (1.f / NH) / (den[d * NH + 2] + 1e-16f);
    float acc[16];
#pragma unroll
    for (int i = 0; i < 16; i++) acc[i] = 0.f;
    for (int p = beg; p < end; p++) {
        int e = g_eidx[p];
        int s = src[e];
        float a0 = e1[e * NH + 0] * i0;
        float a1 = e1[e * NH + 1] * i1;
        float a2 = e1[e * NH + 2] * i2;
        const __half2* H0 = reinterpret_cast<const __half2*>(Hh + ((size_t)s * NH + 0) * HIDF) + lane;
        const __half2* H1 = reinterpret_cast<const __half2*>(Hh + ((size_t)s * NH + 1) * HIDF) + lane;
        const __half2* H2 = reinterpret_cast<const __half2*>(Hh + ((size_t)s * NH + 2) * HIDF) + lane;
#pragma unroll
        for (int it = 0; it < 8; it++) {
            float2 v0 = __half22float2(H0[it * 32]);
            float2 v1 = __half22float2(H1[it * 32]);
            float2 v2 = __half22float2(H2[it * 32]);
            acc[2 * it + 0] += v0.x * a0 + v1.x * a1 + v2.x * a2;
            acc[2 * it + 1] += v0.y * a0 + v1.y * a1 + v2.y * a2;
        }
    }
    float2* od = reinterpret_cast<float2*>(out + (size_t)d * HIDF) + lane;
#pragma unroll
    for (int it = 0; it < 8; it++)
        od[it * 32] = make_float2(acc[2 * it + 0], acc[2 * it + 1]);
}

// F=30, fp32 H2, writes straight to z_out
__global__ void k_gather30(const int* __restrict__ src,
                           const float* __restrict__ e2, const float* __restrict__ den,
                           const float* __restrict__ Hh, float* __restrict__ out) {
    int d = (int)(((size_t)blockIdx.x * blockDim.x + threadIdx.x) >> 5);
    int lane = threadIdx.x & 31;
    if (d >= Nn) return;
    int beg = g_roff[d], end = g_roff[d + 1];
    float i0 = (1.f / NH) / (den[d * NH + 0] + 1e-16f);
    float i1 = (1.f / NH) / (den[d * NH + 1] + 1e-16f);
    float i2 = (1.f / NH) / (den[d * NH + 2] + 1e-16f);
    float acc = 0.f;
    for (int p = beg; p < end; p++) {
        int e = g_eidx[p];
        int s = src[e];
        float a0 = e2[e * NH + 0] * i0;
        float a1 = e2[e * NH + 1] * i1;
        float a2 = e2[e * NH + 2] * i2;
        if (lane < OUTF) {
            acc += Hh[((size_t)s * NH + 0) * OUTF + lane] * a0
                 + Hh[((size_t)s * NH + 1) * OUTF + lane] * a1
                 + Hh[((size_t)s * NH + 2) * OUTF + lane] * a2;
        }
    }
    if (lane < OUTF) out[(size_t)d * OUTF + lane] = acc;
}

// ---------------- MLP head ----------------
__global__ void k_mlp(const float* __restrict__ z, const float* __restrict__ w1,
                      const float* __restrict__ b1, const float* __restrict__ w2,
                      const float* __restrict__ b2, const int* __restrict__ flag,
                      float* yp) {
    int n = blockIdx.x;
    int t = threadIdx.x;
    __shared__ float zs[OUTF];
    __shared__ float hid[MHc];
    if (t < OUTF) zs[t] = z[(size_t)n * OUTF + t];
    __syncthreads();
    if (*flag == 0) {
        if (t < NLABc) yp[(size_t)n * NLABc + t] = 0.f;
        return;
    }
    float a = b1[t];
    #pragma unroll
    for (int k = 0; k < OUTF; k++) a += zs[k] * w1[k * MHc + t];
    hid[t] = fmaxf(a, 0.f);
    __syncthreads();
    if (t < NLABc) {
        float o = b2[t];
        #pragma unroll
        for (int k2 = 0; k2 < MHc; k2++) o += hid[k2] * w2[k2 * NLABc + t];
        yp[(size_t)n * NLABc + t] = o;
    }
}

// ---------------- fc2 (K=30, write-bound) — float4 over j ----------------
__global__ void k_fc2v(const float* __restrict__ z, const float* __restrict__ W,
                       const float* __restrict__ b, float* __restrict__ out) {
    size_t i4 = (size_t)blockIdx.x * blockDim.x + threadIdx.x;
    const int jq = INF_ / 4;
    if (i4 >= (size_t)Nn * jq) return;
    int n = (int)(i4 / jq), j4 = (int)(i4 % jq) * 4;
    float4 acc = *reinterpret_cast<const float4*>(b + j4);
    const float* zr = z + (size_t)n * OUTF;
    #pragma unroll
    for (int k = 0; k < OUTF; k++) {
        float zk = zr[k];
        float4 w = *reinterpret_cast<const float4*>(W + (size_t)k * INF_ + j4);
        acc.x += zk * w.x; acc.y += zk * w.y; acc.z += zk * w.z; acc.w += zk * w.w;
    }
    *reinterpret_cast<float4*>(out + (size_t)n * INF_ + j4) = acc;
}

// ---------------- DSBN ----------------
__global__ void k_cnt(const int* __restrict__ y) {
    int n = blockIdx.x * blockDim.x + threadIdx.x;
    if (n < Nn) atomicAdd(&g_cnt[y[n]], 1.f);
}

__global__ void k_dsbn_sum(const float* __restrict__ X, const int* __restrict__ y) {
    int j = blockIdx.x * blockDim.x + threadIdx.x;
    if (j >= INF_) return;
    int chunk = (Nn + gridDim.y - 1) / gridDim.y;
    int n0 = blockIdx.y * chunk;
    int n1 = min(n0 + chunk, Nn);
    float a[NDOMc], b[NDOMc];
    #pragma unroll
    for (int k = 0; k < NDOMc; k++) { a[k] = 0.f; b[k] = 0.f; }
    for (int n = n0; n < n1; n++) {
        int d = y[n];
        float v = X[(size_t)n * INF_ + j];
        #pragma unroll
        for (int k = 0; k < NDOMc; k++) {
            float m = (d == k) ? 1.f : 0.f;
            a[k] += m * v;
            b[k] += m * v * v;
        }
    }
    #pragma unroll
    for (int k = 0; k < NDOMc; k++) {
        atomicAdd(&g_dsum[k * INF_ + j], a[k]);
        atomicAdd(&g_dsum2[k * INF_ + j], b[k]);
    }
}

// ======================================================================
extern "C" void kernel_launch(void* const* d_in, const int* in_sizes, int n_in,
                              void* d_out, int out_size) {
    const float* features = (const float*)d_in[0];
    const int*   ei       = (const int*)d_in[1];
    const int*   y        = (const int*)d_in[2];
    const int*   flag     = (const int*)d_in[3];
    const float* fc1_w    = (const float*)d_in[4];
    const float* fc1_b    = (const float*)d_in[5];
    const float* bn_g     = (const float*)d_in[6];
    const float* bn_b     = (const float*)d_in[7];
    const float* W1       = (const float*)d_in[8];
    const float* a1_src   = (const float*)d_in[9];
    const float* a1_dst   = (const float*)d_in[10];
    const float* W2       = (const float*)d_in[11];
    const float* a2_src   = (const float*)d_in[12];
    const float* a2_dst   = (const float*)d_in[13];
    const float* mlp_w1   = (const float*)d_in[14];
    const float* mlp_b1   = (const float*)d_in[15];
    const float* mlp_w2   = (const float*)d_in[16];
    const float* mlp_b2   = (const float*)d_in[17];
    const float* fc2_w    = (const float*)d_in[18];
    const float* fc2_b    = (const float*)d_in[19];
    const float* dsbn_g   = (const float*)d_in[20];
    const float* dsbn_b   = (const float*)d_in[21];
    const float* fc3_w    = (const float*)d_in[22];
    const float* fc3_b    = (const float*)d_in[23];

    float* out    = (float*)d_out;
    float* z_out  = out;
    float* h3_out = out + (size_t)Nn * OUTF;
    float* yp_out = h3_out + (size_t)Nn * INF_;
    const int* srcp = ei;
    const int* dstp = ei + Ee;

    void* p;
    cudaGetSymbolAddress(&p, g_x);      float* px    = (float*)p;
    cudaGetSymbolAddress(&p, g_Hh);     __half* pHh  = (__half*)p;
    cudaGetSymbolAddress(&p, g_h1);     float* ph1   = (float*)p;
    cudaGetSymbolAddress(&p, g_H2);     float* pH2   = (float*)p;
    cudaGetSymbolAddress(&p, g_als1);   float* pals1 = (float*)p;
    cudaGetSymbolAddress(&p, g_ald1);   float* pald1 = (float*)p;
    cudaGetSymbolAddress(&p, g_als2);   float* pals2 = (float*)p;
    cudaGetSymbolAddress(&p, g_ald2);   float* pald2 = (float*)p;
    cudaGetSymbolAddress(&p, g_e1);     float* pe1   = (float*)p;
    cudaGetSymbolAddress(&p, g_e2);     float* pe2   = (float*)p;
    cudaGetSymbolAddress(&p, g_mkey1);  unsigned* pmk1 = (unsigned*)p;
    cudaGetSymbolAddress(&p, g_mkey2);  unsigned* pmk2 = (unsigned*)p;
    cudaGetSymbolAddress(&p, g_den1);   float* pden1 = (float*)p;
    cudaGetSymbolAddress(&p, g_den2);   float* pden2 = (float*)p;
    cudaGetSymbolAddress(&p, g_bnsum);  float* pbns  = (float*)p;
    cudaGetSymbolAddress(&p, g_bnsum2); float* pbns2 = (float*)p;
    cudaGetSymbolAddress(&p, g_Aq);     __half* pAq  = (__half*)p;
    cudaGetSymbolAddress(&p, g_Wq);     __half* pWq  = (__half*)p;

    static int smem_set = 0;
    if (!smem_set) {
        cudaFuncSetAttribute(gemm_mma3, cudaFuncAttributeMaxDynamicSharedMemorySize, GSMEM);
        smem_set = 1;
    }

    const int nMt = (Nn + 127) / 128;
    const size_t cvtGrid4 = ((size_t)Nn * (KPAD / 4) + 255) / 256;
    const int gaW = (Nn * 32 + 255) / 256;

    // 0) zero scratch + CSR build
    {
        size_t tot = (size_t)NDOMc * INF_;
        size_t mx = tot > (size_t)Nn * NH ? tot : (size_t)Nn * NH;
        if ((size_t)Nn > mx) mx = Nn;
        k_zero<<<(unsigned)((mx + 255) / 256), 256>>>();
        k_deg<<<(Ee + 255) / 256, 256>>>(dstp);
        k_scan<<<1, 1024>>>();
        k_fill<<<(Ee + 255) / 256, 256>>>(dstp);
    }

    // 1) fc1 (BN column stats fused into epilogue)
    {
        dim3 tg((KPAD + 31) / 32, (INF_ + 31) / 32);
        k_splitWT<<<tg, dim3(32, 32)>>>(fc1_w, pWq, INF_, INF_, KPAD);
        k_cvtA4<<<(unsigned)cvtGrid4, 256>>>(features, pAq, Nn, INF_);
        int nNt = (INF_ + 127) / 128;
        gemm_mma3<<<nMt * nNt, 256, GSMEM>>>(pAq, pWq, fc1_b, px, nullptr,
                                             pbns, pbns2, Nn, INF_, nNt, KPAD);
    }

    // 2) fused BN apply/ELU/convert (stats already complete)
    k_bn_elu_cvt<<<(unsigned)cvtGrid4, 256>>>(px, bn_g, bn_b, pAq);

    // 3) GAT layer 1 (H written as fp16)
    {
        dim3 tg((KPAD + 31) / 32, (NH * HIDF + 31) / 32);
        k_splitWT<<<tg, dim3(32, 32)>>>(W1, pWq, INF_, NH * HIDF, KPAD);
        int nNt = (NH * HIDF + 127) / 128;
        gemm_mma3<<<nMt * nNt, 256, GSMEM>>>(pAq, pWq, nullptr, nullptr, pHh,
                                             nullptr, nullptr, Nn, NH * HIDF, nNt, KPAD);

        int warps = Nn * NH;
        k_attn_logits_h<<<(warps * 32 + 127) / 128, 128>>>(pHh, a1_src, a1_dst, pals1, pald1);

        int et = Ee * NH;
        k_edge_max<<<(et + 255) / 256, 256>>>(srcp, dstp, pals1, pald1, pe1, pmk1);
        k_edge_exp<<<(et + 255) / 256, 256>>>(dstp, pe1, pmk1, pden1);
        k_gather512h<<<gaW, 256>>>(srcp, pe1, pden1, pHh, ph1);
    }

    // 4) GAT layer 2 -> z (feature GEMM on the fp16 tensor path, K=512)
    {
        k_elu_cvt512<<<(Nn * (HIDF / 4) + 255) / 256, 256>>>(ph1, pAq);
        dim3 tg((HIDF + 31) / 32, (NH * OUTF + 31) / 32);
        k_splitWT<<<tg, dim3(32, 32)>>>(W2, pWq, HIDF, NH * OUTF, HIDF);
        gemm_mma3<<<nMt * 1, 256, GSMEM>>>(pAq, pWq, nullptr, pH2, nullptr,
                                           nullptr, nullptr, Nn, NH * OUTF, 1, HIDF);

        int warps = Nn * NH;
        k_attn_logits<<<(warps * 32 + 127) / 128, 128>>>(pH2, a2_src, a2_dst, pals2, pald2, OUTF);

        int et = Ee * NH;
        k_edge_max<<<(et + 255) / 256, 256>>>(srcp, dstp, pals2, pald2, pe2, pmk2);
        k_edge_exp<<<(et + 255) / 256, 256>>>(dstp, pe2, pmk2, pden2);
        k_gather30<<<gaW, 256>>>(srcp, pe2, pden2, pH2, z_out);
    }

    // 5) MLP head
    k_mlp<<<Nn, MHc>>>(z_out, mlp_w1, mlp_b1, mlp_w2, mlp_b2, flag, yp_out);

    // 6) fc2 -> DSBN stats -> fused apply/ELU/convert
    {
        size_t tot4 = (size_t)Nn * (INF_ / 4);
        k_fc2v<<<(unsigned)((tot4 + 255) / 256), 256>>>(z_out, fc2_w, fc2_b, px);
        k_cnt<<<(Nn + 255) / 256, 256>>>(y);
        dim3 grid((INF_ + 255) / 256, 128);
        k_dsbn_sum<<<grid, 256>>>(px, y);
        k_dsbn_elu_cvt<<<(unsigned)cvtGrid4, 256>>>(px, y, dsbn_g, dsbn_b, pAq);
    }

    // 7) fc3 -> h3
    {
        dim3 tg((KPAD + 31) / 32, (INF_ + 31) / 32);
        k_splitWT<<<tg, dim3(32, 32)>>>(fc3_w, pWq, INF_, INF_, KPAD);
        int nNt = (INF_ + 127) / 128;
        gemm_mma3<<<nMt * nNt, 256, GSMEM>>>(pAq, pWq, fc3_b, h3_out, nullptr,
                                             nullptr, nullptr, Nn, INF_, nNt, KPAD);
    }
}